// round 11
// baseline (speedup 1.0000x reference)
#include <cuda_runtime.h>
#include <cuda_bf16.h>
#include <math.h>
#include <stdint.h>

// Problem constants
#define BB 2
#define TT 2048
#define CC 1024
#define HH 16
#define DD 64
#define MM (BB*TT)          // 4096
#define N_QKV (3*CC)        // 3072
#define KK CC               // GEMM K = 1024
#define BH (BB*HH)          // 32
#define EPSY 1e-6f
#define NTASK (BH * (TT/128))   // 512 flash tasks

// ------------------------- scratch (device globals) -----------------------
__device__ float g_xsq[MM];
__device__ float g_xsq2[MM];
__device__ float g_ksqA[N_QKV];
__device__ float g_ksqP[CC];
__device__ float2 g_tbl[TT * 32];
__device__ int g_fctr;
__device__ __nv_bfloat16 g_Ah[(size_t)MM * KK];
__device__ __nv_bfloat16 g_Am[(size_t)MM * KK];
__device__ __nv_bfloat16 g_BhA[(size_t)N_QKV * KK];
__device__ __nv_bfloat16 g_BmA[(size_t)N_QKV * KK];
__device__ __nv_bfloat16 g_BhP[(size_t)CC * KK];
__device__ __nv_bfloat16 g_BmP[(size_t)CC * KK];
// flash operands: Qp/Kp hi-only [bh][t][64] bf16; Vp [bh][t][hi64|mid64]
__device__ __nv_bfloat16 g_Qp[(size_t)BH * TT * 64];
__device__ __nv_bfloat16 g_Kp[(size_t)BH * TT * 64];
__device__ __nv_bfloat16 g_Vp[(size_t)BH * TT * 128];

// ------------------------- PTX helpers ------------------------------------
__device__ __forceinline__ uint32_t smem_u32(const void* p) {
    uint32_t a;
    asm("{ .reg .u64 t; cvta.to.shared.u64 t, %1; cvt.u32.u64 %0, t; }"
        : "=r"(a) : "l"(p));
    return a;
}
__device__ __forceinline__ void cp16(uint32_t dst, const void* src) {
    asm volatile("cp.async.cg.shared.global [%0], [%1], 16;" :: "r"(dst), "l"(src) : "memory");
}
#define CP_COMMIT() asm volatile("cp.async.commit_group;" ::: "memory")
#define CP_WAIT(n)  asm volatile("cp.async.wait_group %0;" :: "n"(n) : "memory")

#define LDM4(r0, r1, r2, r3, addr) \
    asm volatile("ldmatrix.sync.aligned.m8n8.x4.shared.b16 {%0,%1,%2,%3}, [%4];" \
        : "=r"(r0), "=r"(r1), "=r"(r2), "=r"(r3) : "r"(addr))

#define LDM4T(r0, r1, r2, r3, addr) \
    asm volatile("ldmatrix.sync.aligned.m8n8.x4.trans.shared.b16 {%0,%1,%2,%3}, [%4];" \
        : "=r"(r0), "=r"(r1), "=r"(r2), "=r"(r3) : "r"(addr))

#define MMA16816(d, a, b) \
    asm volatile("mma.sync.aligned.m16n8k16.row.col.f32.bf16.bf16.f32 " \
        "{%0,%1,%2,%3}, {%4,%5,%6,%7}, {%8,%9}, {%0,%1,%2,%3};" \
        : "+f"((d)[0]), "+f"((d)[1]), "+f"((d)[2]), "+f"((d)[3]) \
        : "r"((a)[0]), "r"((a)[1]), "r"((a)[2]), "r"((a)[3]), \
          "r"((b)[0]), "r"((b)[1]))

// packs {hi, lo} fp32 -> bf16x2 (first source is upper half)
__device__ __forceinline__ uint32_t pack_bf16x2(float hi, float lo) {
    uint32_t r;
    asm("cvt.rn.bf16x2.f32 %0, %1, %2;" : "=r"(r) : "f"(hi), "f"(lo));
    return r;
}
// unpack bf16x2 -> sum of the two fp32 values
__device__ __forceinline__ float sum_bf16x2(uint32_t r) {
    __nv_bfloat162 b2 = *reinterpret_cast<__nv_bfloat162*>(&r);
    float2 f2 = __bfloat1622float2(b2);
    return f2.x + f2.y;
}
// split-store a pair of adjacent cols (d even) into hi/mid planes of one row
__device__ __forceinline__ void store_pair(__nv_bfloat16* P, size_t rowo, int d,
                                           float a, float b) {
    float ha = __bfloat162float(__float2bfloat16(a));
    float hb = __bfloat162float(__float2bfloat16(b));
    *(uint32_t*)((char*)P + (rowo + d) * 2)      = pack_bf16x2(b, a);
    *(uint32_t*)((char*)P + (rowo + 64 + d) * 2) = pack_bf16x2(b - hb, a - ha);
}

// ------------------------- merged prep: everything before GEMM1 ------------
// blocks [0,MM): x split + rowsq
// [MM, MM+96): w_attn transpose strip (32 n-cols, full K), colsq w/o atomics
// [MM+96, MM+128): w_proj same
// [MM+128, MM+384): rope table + xsq2 zero + fctr reset
__global__ void prep2_kernel(const float* __restrict__ x,
                             __nv_bfloat16* __restrict__ Ah,
                             __nv_bfloat16* __restrict__ Am,
                             float* __restrict__ xsq,
                             const float* __restrict__ wA,
                             __nv_bfloat16* __restrict__ BhA,
                             __nv_bfloat16* __restrict__ BmA,
                             float* __restrict__ ksqa,
                             const float* __restrict__ wP,
                             __nv_bfloat16* __restrict__ BhP,
                             __nv_bfloat16* __restrict__ BmP,
                             float* __restrict__ ksqp,
                             float* __restrict__ xsq2,
                             float2* __restrict__ tbl,
                             int* __restrict__ fctr) {
    __shared__ float red[8];
    __shared__ float tile[32][33];
    int blk = blockIdx.x, tid = threadIdx.x;
    if (blk < MM) {
        int row = blk;
        size_t i = (size_t)row * 256 + tid;
        float4 v = ((const float4*)x)[i];
        __nv_bfloat16 h0 = __float2bfloat16(v.x);
        __nv_bfloat16 h1 = __float2bfloat16(v.y);
        __nv_bfloat16 h2 = __float2bfloat16(v.z);
        __nv_bfloat16 h3 = __float2bfloat16(v.w);
        __nv_bfloat162* Hp = (__nv_bfloat162*)Ah;
        __nv_bfloat162* Mq = (__nv_bfloat162*)Am;
        Hp[2*i]   = __nv_bfloat162(h0, h1);
        Hp[2*i+1] = __nv_bfloat162(h2, h3);
        Mq[2*i]   = __nv_bfloat162(__float2bfloat16(v.x - __bfloat162float(h0)),
                                   __float2bfloat16(v.y - __bfloat162float(h1)));
        Mq[2*i+1] = __nv_bfloat162(__float2bfloat16(v.z - __bfloat162float(h2)),
                                   __float2bfloat16(v.w - __bfloat162float(h3)));
        float s = v.x*v.x + v.y*v.y + v.z*v.z + v.w*v.w;
        #pragma unroll
        for (int off = 16; off > 0; off >>= 1)
            s += __shfl_xor_sync(0xffffffffu, s, off);
        if ((tid & 31) == 0) red[tid >> 5] = s;
        __syncthreads();
        if (tid == 0) {
            float t = 0.f;
            #pragma unroll
            for (int w = 0; w < 8; ++w) t += red[w];
            xsq[row] = t;
        }
        return;
    }
    if (blk < MM + 128) {
        // weight transpose strip: one block owns 32 n-columns across full K
        const float* W; __nv_bfloat16 *Bh, *Bm; float* ksq; int N, n0;
        if (blk < MM + 96) {
            W = wA; Bh = BhA; Bm = BmA; ksq = ksqa; N = N_QKV;
            n0 = (blk - MM) * 32;
        } else {
            W = wP; Bh = BhP; Bm = BmP; ksq = ksqp; N = CC;
            n0 = (blk - MM - 96) * 32;
        }
        int tx = tid & 31, ty = tid >> 5;
        float csum[4] = {0.f, 0.f, 0.f, 0.f};
        for (int k0 = 0; k0 < KK; k0 += 32) {
            for (int j = ty; j < 32; j += 8)
                tile[j][tx] = W[(size_t)(k0 + j) * N + n0 + tx];
            __syncthreads();
            #pragma unroll
            for (int j4 = 0; j4 < 4; ++j4) {
                int j = ty + j4 * 8;
                float v = tile[tx][j];
                __nv_bfloat16 h = __float2bfloat16(v);
                __nv_bfloat16 m = __float2bfloat16(v - __bfloat162float(h));
                size_t o = (size_t)(n0 + j) * KK + k0 + tx;
                Bh[o] = h; Bm[o] = m;
                float sq = v * v;
                #pragma unroll
                for (int off = 16; off > 0; off >>= 1)
                    sq += __shfl_xor_sync(0xffffffffu, sq, off);
                csum[j4] += sq;
            }
            __syncthreads();
        }
        if (tx == 0) {
            #pragma unroll
            for (int j4 = 0; j4 < 4; ++j4)
                ksq[n0 + ty + j4 * 8] = csum[j4];
        }
        return;
    }
    // rope table + zero xsq2 + fctr
    int i = (blk - (MM + 128)) * 256 + tid;
    if (i == 0) *fctr = 0;
    if (i < MM) xsq2[i] = 0.f;
    int t = i >> 5, dd = i & 31;
    float freq = expf(-9.2103403719761836f * ((float)(2*dd) / 64.f));
    float sn, cs;
    sincosf((float)t * freq, &sn, &cs);
    tbl[i] = make_float2(sn, cs);
}

// ------------------------- mma.sync GEMM + YAT epilogue -------------------
// CTA 128(M)x256(N), 8 warps 2x4 -> warp tile 64x64. 3-stage cp.async.
// MODE 0 (GEMM2): 3 MMA combos, YAT -> fp32 out.
// MODE 1 (GEMM1): Q/K regions 1 combo (hh), V region 2 combos (hh+hm);
//                 YAT -> RoPE -> Qp/Kp (hi) + Vp split planes.
#define SROW 144
#define ATILE (128*SROW)                 // 18432
#define BTILE (256*SROW)                 // 36864
#define GSTAGE (ATILE + BTILE)           // 55296
#define GNKCH (KK/32)                    // 32

template<int MODE>
__global__ __launch_bounds__(256, 1)
void gemm_mma_kernel(const __nv_bfloat16* __restrict__ Ah, const __nv_bfloat16* __restrict__ Am,
                     const __nv_bfloat16* __restrict__ Bh, const __nv_bfloat16* __restrict__ Bm,
                     const float* __restrict__ bias, const float* __restrict__ xsq,
                     const float* __restrict__ ksq, const float* __restrict__ alphap,
                     float* __restrict__ out, int N, float outf,
                     __nv_bfloat16* __restrict__ Qp, __nv_bfloat16* __restrict__ Kp,
                     __nv_bfloat16* __restrict__ Vp, const float2* __restrict__ tbl) {
    extern __shared__ char dsm[];
    uint32_t sbase = smem_u32(dsm);

    const int tid = threadIdx.x;
    const int lane = tid & 31;
    const int wid = tid >> 5;
    const int wm = wid >> 2;
    const int wn = wid & 3;
    const int m0 = blockIdx.y * 128;
    const int n0 = blockIdx.x * 256;
    const int l8 = lane & 7;
    const int lm = lane >> 3;
    const int region = (MODE == 1) ? (n0 >> 10) : 2;
    const bool useBmid = (MODE == 0) || (region == 2);

    const char* pAh = (const char*)Ah + (size_t)m0 * (KK*2);
    const char* pAm = (const char*)Am + (size_t)m0 * (KK*2);
    const char* pBh = (const char*)Bh + (size_t)n0 * (KK*2);
    const char* pBm = (const char*)Bm + (size_t)n0 * (KK*2);

    const int lplane = (tid >> 2) & 1;
    const int lchunk = tid & 3;

    #define LOAD_CHUNK(kc, st) do {                                           \
        size_t kb = (size_t)(kc) * 64 + (size_t)lchunk * 16;                  \
        uint32_t sbs = sbase + (st) * GSTAGE;                                 \
        uint32_t doff0 = (tid >> 3) * SROW + lplane * 64 + lchunk * 16;       \
        if (MODE == 0 || lplane == 0) {                                       \
            _Pragma("unroll")                                                 \
            for (int i = 0; i < 4; ++i) {                                     \
                int row = (tid >> 3) + i * 32;                                \
                const char* sa = (lplane ? pAm : pAh) + (size_t)row * (KK*2) + kb;\
                cp16(sbs + doff0 + i * (32*SROW), sa);                        \
            }                                                                 \
        }                                                                     \
        if (useBmid || lplane == 0) {                                         \
            _Pragma("unroll")                                                 \
            for (int i = 0; i < 8; ++i) {                                     \
                int row = (tid >> 3) + i * 32;                                \
                const char* sbp = (lplane ? pBm : pBh) + (size_t)row * (KK*2) + kb;\
                cp16(sbs + ATILE + doff0 + i * (32*SROW), sbp);               \
            }                                                                 \
        }                                                                     \
        CP_COMMIT();                                                          \
    } while (0)

    float acc[4][8][4];
    #pragma unroll
    for (int i = 0; i < 4; ++i)
        #pragma unroll
        for (int j = 0; j < 8; ++j)
            #pragma unroll
            for (int r = 0; r < 4; ++r) acc[i][j][r] = 0.f;

    const int arow = lane & 15;
    const int akoff = (lane >> 4) * 16;
    constexpr int NPL = (MODE == 0) ? 2 : 1;

    LOAD_CHUNK(0, 0);
    LOAD_CHUNK(1, 1);

    for (int kc = 0; kc < GNKCH; ++kc) {
        int st = kc - (kc / 3) * 3;
        if (kc + 1 < GNKCH) { CP_WAIT(1); } else { CP_WAIT(0); }
        __syncthreads();
        if (kc + 2 < GNKCH) {
            int st2 = (kc + 2) - ((kc + 2) / 3) * 3;
            LOAD_CHUNK(kc + 2, st2);
        }

        uint32_t sA = sbase + st * GSTAGE;
        uint32_t sB = sA + ATILE;

        #pragma unroll
        for (int ks = 0; ks < 2; ++ks) {
            uint32_t a[NPL][4][4];
            #pragma unroll
            for (int pl = 0; pl < NPL; ++pl)
                #pragma unroll
                for (int fm = 0; fm < 4; ++fm) {
                    uint32_t ad = sA + (wm*64 + fm*16 + arow) * SROW
                                + pl*64 + ks*32 + akoff;
                    LDM4(a[pl][fm][0], a[pl][fm][1], a[pl][fm][2], a[pl][fm][3], ad);
                }
            uint32_t b[2][8][2];
            #pragma unroll
            for (int pr = 0; pr < 4; ++pr) {
                uint32_t bd = sB + (wn*64 + (pr*2 + (lm >> 1))*8 + l8) * SROW
                            + ks*32 + (lm & 1)*16;
                LDM4(b[0][pr*2][0], b[0][pr*2][1],
                     b[0][pr*2+1][0], b[0][pr*2+1][1], bd);
            }
            if (useBmid) {
                #pragma unroll
                for (int pr = 0; pr < 4; ++pr) {
                    uint32_t bd = sB + (wn*64 + (pr*2 + (lm >> 1))*8 + l8) * SROW
                                + 64 + ks*32 + (lm & 1)*16;
                    LDM4(b[1][pr*2][0], b[1][pr*2][1],
                         b[1][pr*2+1][0], b[1][pr*2+1][1], bd);
                }
            }
            #pragma unroll
            for (int fm = 0; fm < 4; ++fm)
                #pragma unroll
                for (int fn = 0; fn < 8; ++fn) {
                    MMA16816(acc[fm][fn], a[0][fm], b[0][fn]);
                    if (useBmid) MMA16816(acc[fm][fn], a[0][fm], b[1][fn]);
                    if (MODE == 0) MMA16816(acc[fm][fn], a[NPL-1][fm], b[0][fn]);
                }
        }
        __syncthreads();
    }

    float alpha = *alphap;
    float scl = powf(sqrtf(outf) / logf(1.f + outf), alpha);
    int g = lane >> 2;
    int t2 = (lane & 3) * 2;

    #pragma unroll
    for (int fm = 0; fm < 4; ++fm) {
        int mA = m0 + wm*64 + fm*16 + g;
        float xsA = xsq[mA];
        float xsB = xsq[mA + 8];
        #pragma unroll
        for (int fn = 0; fn < 8; ++fn) {
            int col = n0 + wn*64 + fn*8 + t2;
            float k0v = ksq[col], k1v = ksq[col+1];
            float b0v = bias[col], b1v = bias[col+1];
            float d0 = acc[fm][fn][0], d1 = acc[fm][fn][1];
            float d2 = acc[fm][fn][2], d3 = acc[fm][fn][3];
            acc[fm][fn][0] = d0*d0 / (xsA + k0v - 2.f*d0 + EPSY) * scl + b0v;
            acc[fm][fn][1] = d1*d1 / (xsA + k1v - 2.f*d1 + EPSY) * scl + b1v;
            acc[fm][fn][2] = d2*d2 / (xsB + k0v - 2.f*d2 + EPSY) * scl + b0v;
            acc[fm][fn][3] = d3*d3 / (xsB + k1v - 2.f*d3 + EPSY) * scl + b1v;
        }
        if (MODE == 0) {
            #pragma unroll
            for (int fn = 0; fn < 8; ++fn) {
                int col = n0 + wn*64 + fn*8 + t2;
                *(float2*)(out + (size_t)mA * N + col)
                    = make_float2(acc[fm][fn][0], acc[fm][fn][1]);
                *(float2*)(out + (size_t)(mA+8) * N + col)
                    = make_float2(acc[fm][fn][2], acc[fm][fn][3]);
            }
        } else {
            int hloc = ((n0 & 1023) + wn*64) >> 6;
            float qs = (region == 0) ? 0.125f : 1.f;
            #pragma unroll
            for (int half = 0; half < 2; ++half) {
                int mrow = mA + half*8;
                int t = mrow & (TT-1);
                int b = mrow >> 11;
                if (region < 2) {
                    __nv_bfloat16* P = (region == 0) ? Qp : Kp;
                    size_t rowo = ((size_t)(b*HH + hloc) * TT + t) * 64;
                    #pragma unroll
                    for (int fn = 0; fn < 4; ++fn) {
                        int dd = fn*8 + t2;
                        float4 sc = *(const float4*)(tbl + (t*32 + dd));
                        float x1a = acc[fm][fn][half*2]     * qs;
                        float x1b = acc[fm][fn][half*2+1]   * qs;
                        float x2a = acc[fm][fn+4][half*2]   * qs;
                        float x2b = acc[fm][fn+4][half*2+1] * qs;
                        float r0a = x1a*sc.y - x2a*sc.x, r0b = x1b*sc.w - x2b*sc.z;
                        float r1a = x2a*sc.y + x1a*sc.x, r1b = x2b*sc.w + x1b*sc.z;
                        *(uint32_t*)((char*)P + (rowo + dd) * 2)      = pack_bf16x2(r0b, r0a);
                        *(uint32_t*)((char*)P + (rowo + dd + 32) * 2) = pack_bf16x2(r1b, r1a);
                    }
                } else {
                    size_t rowo = ((size_t)(b*HH + hloc) * TT + t) * 128;
                    #pragma unroll
                    for (int fn = 0; fn < 8; ++fn)
                        store_pair(Vp, rowo, fn*8 + t2,
                                   acc[fm][fn][half*2], acc[fm][fn][half*2+1]);
                }
            }
        }
    }
    #undef LOAD_CHUNK
}

// ------------------------- flash attention (persistent, mma.sync) ----------
// BQ=128, BK=128. Q/K hi-only rows 128B (+16 pad = 144). V rows [hi|mid] 272B.
// QK: 1 MMA combo. PV: 2 combos (p_hi*v_hi + p_hi*v_mid); the softmax
// denominator l is computed from the SAME bf16-rounded p values the MMA sees,
// so the weighted mean is exact under slightly-perturbed weights.
// Fixed m=0 (logits provably bounded for this problem).
#define FQ 128
#define QROWK 144
#define VROW 272
#define SQ_SZ (128*QROWK)                // 18432
#define SK_OFF SQ_SZ
#define SK_SZ (128*QROWK)                // 18432
#define SV_OFF (SK_OFF + 2*SK_SZ)        // 55296
#define SV_SZ (128*VROW)                 // 34816
#define FSMEM (SV_OFF + 2*SV_SZ)         // 124928
#define NPERS 148

__global__ __launch_bounds__(256, 1)
void flash_mma_kernel(const __nv_bfloat16* __restrict__ Qp,
                      const __nv_bfloat16* __restrict__ Kp,
                      const __nv_bfloat16* __restrict__ Vp,
                      __nv_bfloat16* __restrict__ OH,
                      __nv_bfloat16* __restrict__ OM,
                      float* __restrict__ xsq2,
                      int* __restrict__ fctr) {
    extern __shared__ char smf[];
    __shared__ int s_task;
    uint32_t sb = smem_u32(smf);
    int tid = threadIdx.x;
    int lane = tid & 31, wq = tid >> 5;
    const int l8 = lane & 7, lm = lane >> 3;
    const int g = lane >> 2, cq = lane & 3;

    for (;;) {
        if (tid == 0) s_task = atomicAdd(fctr, 1);
        __syncthreads();
        int task = s_task;
        if (task >= NTASK) return;
        int qi = (TT/FQ) - 1 - (task >> 5);   // descending work (LPT)
        int bh = task & 31;
        int q0 = qi * FQ;
        const char* Qg = (const char*)(Qp + ((size_t)bh * TT + q0) * 64);
        const char* Kg = (const char*)(Kp + (size_t)bh * TT * 64);
        const char* Vg = (const char*)(Vp + (size_t)bh * TT * 128);

        // Q tile (hi only) + K0 + V0 -> stage 0
        #pragma unroll
        for (int i = 0; i < 4; ++i) {
            int idx = tid + i * 256; int r = idx >> 3, ch = idx & 7;
            cp16(sb + r * QROWK + ch * 16, Qg + (size_t)r * 128 + ch * 16);
        }
        #pragma unroll
        for (int i = 0; i < 4; ++i) {
            int idx = tid + i * 256; int r = idx >> 3, ch = idx & 7;
            cp16(sb + SK_OFF + r * QROWK + ch * 16, Kg + (size_t)r * 128 + ch * 16);
        }
        #pragma unroll
        for (int i = 0; i < 8; ++i) {
            int idx = tid + i * 256; int r = idx >> 4, ch = idx & 15;
            cp16(sb + SV_OFF + r * VROW + ch * 16, Vg + (size_t)r * 256 + ch * 16);
        }
        CP_COMMIT();

        float oacc[8][4];
        #pragma unroll
        for (int fo = 0; fo < 8; ++fo)
            #pragma unroll
            for (int r = 0; r < 4; ++r) oacc[fo][r] = 0.f;
        uint32_t qa[4][4];
        float l0 = 0.f, l1 = 0.f;
        const int nkt = qi + 1;

        for (int kt = 0; kt < nkt; ++kt) {
            int st = kt & 1;
            CP_WAIT(0);
            __syncthreads();
            if (kt + 1 < nkt) {
                int sn = st ^ 1, k0n = (kt + 1) * FQ;
                #pragma unroll
                for (int i = 0; i < 4; ++i) {
                    int idx = tid + i * 256; int r = idx >> 3, ch = idx & 7;
                    cp16(sb + SK_OFF + sn * SK_SZ + r * QROWK + ch * 16,
                         Kg + (size_t)(k0n + r) * 128 + ch * 16);
                }
                #pragma unroll
                for (int i = 0; i < 8; ++i) {
                    int idx = tid + i * 256; int r = idx >> 4, ch = idx & 15;
                    cp16(sb + SV_OFF + sn * SV_SZ + r * VROW + ch * 16,
                         Vg + (size_t)(k0n + r) * 256 + ch * 16);
                }
                CP_COMMIT();
            }

            if (kt == 0) {
                #pragma unroll
                for (int ks = 0; ks < 4; ++ks) {
                    uint32_t ad = sb + (wq * 16 + (lane & 15)) * QROWK
                                + ks * 32 + (lane >> 4) * 16;
                    LDM4(qa[ks][0], qa[ks][1], qa[ks][2], qa[ks][3], ad);
                }
            }

            uint32_t sKb = sb + SK_OFF + st * SK_SZ;
            uint32_t sVb = sb + SV_OFF + st * SV_SZ;
            bool diag = (kt == nkt - 1);
            const int fnmax = diag ? (2*wq + 2) : 16;
            const int k2max = diag ? (wq + 1) : 8;

            // ---- S = Q K^T, single combo ------------------------------------
            float sacc[16][4];
            #pragma unroll
            for (int fn = 0; fn < 16; ++fn)
                #pragma unroll
                for (int r = 0; r < 4; ++r) sacc[fn][r] = 0.f;

            #pragma unroll
            for (int ks = 0; ks < 4; ++ks) {
                #pragma unroll
                for (int half = 0; half < 2; ++half) {
                    if (half*8 >= fnmax) break;
                    uint32_t kh[8][2];
                    #pragma unroll
                    for (int pr = 0; pr < 4; ++pr) {
                        if (half*8 + pr*2 >= fnmax) break;
                        uint32_t base = sKb
                            + (half*64 + (pr*2 + (lm >> 1))*8 + l8) * QROWK
                            + ks*32 + (lm & 1)*16;
                        LDM4(kh[pr*2][0], kh[pr*2][1], kh[pr*2+1][0], kh[pr*2+1][1], base);
                    }
                    #pragma unroll
                    for (int f = 0; f < 8; ++f) {
                        if (half*8 + f >= fnmax) break;
                        MMA16816(sacc[half*8 + f], qa[ks], kh[f]);
                    }
                }
            }

            // ---- mask + softmax (fixed m=0) ----------------------------------
            int k0 = kt * FQ;
            int r0q = q0 + wq * 16 + g;
            if (diag) {
                #pragma unroll
                for (int fn = 0; fn < 16; ++fn) {
                    int col = k0 + fn * 8 + 2 * cq;
                    if (col     > r0q)     sacc[fn][0] = -1e30f;
                    if (col + 1 > r0q)     sacc[fn][1] = -1e30f;
                    if (col     > r0q + 8) sacc[fn][2] = -1e30f;
                    if (col + 1 > r0q + 8) sacc[fn][3] = -1e30f;
                }
            }

            // pack bf16 p; l sums the ROUNDED values -> exact weighted mean
            float rs0 = 0.f, rs1 = 0.f;
            uint32_t pah[8][4];
            #pragma unroll
            for (int k2 = 0; k2 < 8; ++k2) {
                #pragma unroll
                for (int half = 0; half < 2; ++half) {
                    int fn = k2 * 2 + half;
                    float p0 = __expf(sacc[fn][0]);
                    float p1 = __expf(sacc[fn][1]);
                    float p2 = __expf(sacc[fn][2]);
                    float p3 = __expf(sacc[fn][3]);
                    uint32_t r01 = pack_bf16x2(p1, p0);
                    uint32_t r23 = pack_bf16x2(p3, p2);
                    pah[k2][half*2+0] = r01;
                    pah[k2][half*2+1] = r23;
                    rs0 += sum_bf16x2(r01);
                    rs1 += sum_bf16x2(r23);
                }
            }
            rs0 += __shfl_xor_sync(0xffffffffu, rs0, 1);
            rs0 += __shfl_xor_sync(0xffffffffu, rs0, 2);
            rs1 += __shfl_xor_sync(0xffffffffu, rs1, 1);
            rs1 += __shfl_xor_sync(0xffffffffu, rs1, 2);
            l0 += rs0;
            l1 += rs1;

            // ---- O += P V (2 combos, ldmatrix.trans) -------------------------
            #pragma unroll
            for (int k2 = 0; k2 < 8; ++k2) {
                if (k2 >= k2max) break;
                uint32_t vh[8][2], vm[8][2];
                #pragma unroll
                for (int pr = 0; pr < 4; ++pr) {
                    uint32_t base = sVb + (k2*16 + (lm & 1)*8 + l8) * VROW
                                  + (pr*2 + (lm >> 1)) * 16;
                    LDM4T(vh[pr*2][0], vh[pr*2][1], vh[pr*2+1][0], vh[pr*2+1][1], base);
                    LDM4T(vm[pr*2][0], vm[pr*2][1], vm[pr*2+1][0], vm[pr*2+1][1],
                          base + 128);
                }
                #pragma unroll
                for (int fo = 0; fo < 8; ++fo) {
                    MMA16816(oacc[fo], pah[k2], vh[fo]);
                    MMA16816(oacc[fo], pah[k2], vm[fo]);
                }
            }
        }

        // ---- fused epilogue: bf16 split planes + atomic row-sumsq -----------
        float inv0 = 1.f / l0, inv1 = 1.f / l1;
        int b = bh >> 4, h = bh & 15;
        int r0q = q0 + wq * 16 + g;
        size_t row0 = (size_t)(b * TT + r0q);
        float s0 = 0.f, s1 = 0.f;
        #pragma unroll
        for (int fo = 0; fo < 8; ++fo) {
            int col = h * 64 + fo * 8 + 2 * cq;
            float w00 = oacc[fo][0] * inv0, w01 = oacc[fo][1] * inv0;
            float w10 = oacc[fo][2] * inv1, w11 = oacc[fo][3] * inv1;
            s0 += w00*w00 + w01*w01;
            s1 += w10*w10 + w11*w11;
            float h00 = __bfloat162float(__float2bfloat16(w00));
            float h01 = __bfloat162float(__float2bfloat16(w01));
            float h10 = __bfloat162float(__float2bfloat16(w10));
            float h11 = __bfloat162float(__float2bfloat16(w11));
            *(uint32_t*)((char*)OH + (row0 * KK + col) * 2) = pack_bf16x2(w01, w00);
            *(uint32_t*)((char*)OM + (row0 * KK + col) * 2) = pack_bf16x2(w01 - h01, w00 - h00);
            *(uint32_t*)((char*)OH + ((row0 + 8) * KK + col) * 2) = pack_bf16x2(w11, w10);
            *(uint32_t*)((char*)OM + ((row0 + 8) * KK + col) * 2) = pack_bf16x2(w11 - h11, w10 - h10);
        }
        s0 += __shfl_xor_sync(0xffffffffu, s0, 1);
        s0 += __shfl_xor_sync(0xffffffffu, s0, 2);
        s1 += __shfl_xor_sync(0xffffffffu, s1, 1);
        s1 += __shfl_xor_sync(0xffffffffu, s1, 2);
        if (cq == 0) {
            atomicAdd(&xsq2[row0], s0);
            atomicAdd(&xsq2[row0 + 8], s1);
        }
    }
}

// ------------------------- host launch --------------------------------------
extern "C" void kernel_launch(void* const* d_in, const int* in_sizes, int n_in,
                              void* d_out, int out_size) {
    const float* x      = (const float*)d_in[0];
    const float* w_attn = (const float*)d_in[2];
    const float* b_attn = (const float*)d_in[3];
    const float* a_attn = (const float*)d_in[4];
    const float* w_proj = (const float*)d_in[5];
    const float* b_proj = (const float*)d_in[6];
    const float* a_proj = (const float*)d_in[7];
    float* out = (float*)d_out;

    void *xsq_, *xsq2_, *ksqa_, *ksqp_, *tbl_, *fctr_;
    void *ah_, *am_, *bha_, *bma_, *bhp_, *bmp_, *qp_, *kp_, *vp_;
    cudaGetSymbolAddress(&xsq_,  g_xsq);
    cudaGetSymbolAddress(&xsq2_, g_xsq2);
    cudaGetSymbolAddress(&ksqa_, g_ksqA);
    cudaGetSymbolAddress(&ksqp_, g_ksqP);
    cudaGetSymbolAddress(&tbl_,  g_tbl);
    cudaGetSymbolAddress(&fctr_, g_fctr);
    cudaGetSymbolAddress(&ah_,   g_Ah);
    cudaGetSymbolAddress(&am_,   g_Am);
    cudaGetSymbolAddress(&bha_,  g_BhA);
    cudaGetSymbolAddress(&bma_,  g_BmA);
    cudaGetSymbolAddress(&bhp_,  g_BhP);
    cudaGetSymbolAddress(&bmp_,  g_BmP);
    cudaGetSymbolAddress(&qp_,   g_Qp);
    cudaGetSymbolAddress(&kp_,   g_Kp);
    cudaGetSymbolAddress(&vp_,   g_Vp);
    float* xsq  = (float*)xsq_;
    float* xsq2 = (float*)xsq2_;
    float* ksqa = (float*)ksqa_;
    float* ksqp = (float*)ksqp_;
    float2* tbl = (float2*)tbl_;
    int* fctr   = (int*)fctr_;
    __nv_bfloat16* Ah  = (__nv_bfloat16*)ah_;
    __nv_bfloat16* Am  = (__nv_bfloat16*)am_;
    __nv_bfloat16* BhA = (__nv_bfloat16*)bha_;
    __nv_bfloat16* BmA = (__nv_bfloat16*)bma_;
    __nv_bfloat16* BhP = (__nv_bfloat16*)bhp_;
    __nv_bfloat16* BmP = (__nv_bfloat16*)bmp_;
    __nv_bfloat16* Qp  = (__nv_bfloat16*)qp_;
    __nv_bfloat16* Kp  = (__nv_bfloat16*)kp_;
    __nv_bfloat16* Vp  = (__nv_bfloat16*)vp_;

    const int gemm_smem = 3 * GSTAGE;                        // 165888
    cudaFuncSetAttribute(gemm_mma_kernel<0>,
                         cudaFuncAttributeMaxDynamicSharedMemorySize, gemm_smem);
    cudaFuncSetAttribute(gemm_mma_kernel<1>,
                         cudaFuncAttributeMaxDynamicSharedMemorySize, gemm_smem);
    cudaFuncSetAttribute(flash_mma_kernel,
                         cudaFuncAttributeMaxDynamicSharedMemorySize, FSMEM);

    // single merged prep: x split+rowsq, weight strips (transpose+colsq,
    // no atomics), rope table, xsq2 zero, fctr reset
    prep2_kernel<<<MM + 128 + 256, 256>>>(x, Ah, Am, xsq,
                                          w_attn, BhA, BmA, ksqa,
                                          w_proj, BhP, BmP, ksqp,
                                          xsq2, tbl, fctr);

    // GEMM1 (Q/K 1 combo, V 2 combos) + YAT + RoPE + split -> Qp/Kp/Vp
    {
        dim3 grid(N_QKV / 256, MM / 128);
        gemm_mma_kernel<1><<<grid, 256, gemm_smem>>>(Ah, Am, BhA, BmA, b_attn, xsq,
                                                     ksqa, a_attn, nullptr, N_QKV,
                                                     (float)N_QKV, Qp, Kp, Vp, tbl);
    }

    // persistent flash attention (QK 1 combo, PV 2 combos, m=0) -> Ah/Am + xsq2
    flash_mma_kernel<<<NPERS, 256, FSMEM>>>(Qp, Kp, Vp, Ah, Am, xsq2, fctr);

    // GEMM2 (3 combos) + YAT -> out
    {
        dim3 grid(CC / 256, MM / 128);
        gemm_mma_kernel<0><<<grid, 256, gemm_smem>>>(Ah, Am, BhP, BmP, b_proj, xsq2,
                                                     ksqp, a_proj, out, CC,
                                                     (float)CC, nullptr, nullptr,
                                                     nullptr, nullptr);
    }
}

// round 12
// speedup vs baseline: 1.1318x; 1.1318x over previous
#include <cuda_runtime.h>
#include <cuda_bf16.h>
#include <math.h>
#include <stdint.h>

// Problem constants
#define BB 2
#define TT 2048
#define CC 1024
#define HH 16
#define DD 64
#define MM (BB*TT)          // 4096
#define N_QKV (3*CC)        // 3072
#define KK CC               // GEMM K = 1024
#define BH (BB*HH)          // 32
#define EPSY 1e-6f
#define NTASK (BH * (TT/128))   // 512 flash tasks

// ------------------------- scratch (device globals) -----------------------
__device__ float g_xsq[MM];
__device__ float g_xsq2[MM];
__device__ float g_ksqA[N_QKV];
__device__ float g_ksqP[CC];
__device__ float2 g_tbl[TT * 32];
__device__ int g_fctr;
__device__ __nv_bfloat16 g_Ah[(size_t)MM * KK];
__device__ __nv_bfloat16 g_Am[(size_t)MM * KK];
__device__ __nv_bfloat16 g_BhA[(size_t)N_QKV * KK];
__device__ __nv_bfloat16 g_BmA[(size_t)N_QKV * KK];
__device__ __nv_bfloat16 g_BhP[(size_t)CC * KK];
__device__ __nv_bfloat16 g_BmP[(size_t)CC * KK];
// flash operands: Qp/Kp hi-only [bh][t][64] bf16; Vp [bh][t][hi64|mid64]
__device__ __nv_bfloat16 g_Qp[(size_t)BH * TT * 64];
__device__ __nv_bfloat16 g_Kp[(size_t)BH * TT * 64];
__device__ __nv_bfloat16 g_Vp[(size_t)BH * TT * 128];

// ------------------------- PTX helpers ------------------------------------
__device__ __forceinline__ uint32_t smem_u32(const void* p) {
    uint32_t a;
    asm("{ .reg .u64 t; cvta.to.shared.u64 t, %1; cvt.u32.u64 %0, t; }"
        : "=r"(a) : "l"(p));
    return a;
}
__device__ __forceinline__ void cp16(uint32_t dst, const void* src) {
    asm volatile("cp.async.cg.shared.global [%0], [%1], 16;" :: "r"(dst), "l"(src) : "memory");
}
#define CP_COMMIT() asm volatile("cp.async.commit_group;" ::: "memory")
#define CP_WAIT(n)  asm volatile("cp.async.wait_group %0;" :: "n"(n) : "memory")

#define LDM4(r0, r1, r2, r3, addr) \
    asm volatile("ldmatrix.sync.aligned.m8n8.x4.shared.b16 {%0,%1,%2,%3}, [%4];" \
        : "=r"(r0), "=r"(r1), "=r"(r2), "=r"(r3) : "r"(addr))

#define LDM4T(r0, r1, r2, r3, addr) \
    asm volatile("ldmatrix.sync.aligned.m8n8.x4.trans.shared.b16 {%0,%1,%2,%3}, [%4];" \
        : "=r"(r0), "=r"(r1), "=r"(r2), "=r"(r3) : "r"(addr))

#define MMA16816(d, a, b) \
    asm volatile("mma.sync.aligned.m16n8k16.row.col.f32.bf16.bf16.f32 " \
        "{%0,%1,%2,%3}, {%4,%5,%6,%7}, {%8,%9}, {%0,%1,%2,%3};" \
        : "+f"((d)[0]), "+f"((d)[1]), "+f"((d)[2]), "+f"((d)[3]) \
        : "r"((a)[0]), "r"((a)[1]), "r"((a)[2]), "r"((a)[3]), \
          "r"((b)[0]), "r"((b)[1]))

// packs {hi, lo} fp32 -> bf16x2 (first source is upper half)
__device__ __forceinline__ uint32_t pack_bf16x2(float hi, float lo) {
    uint32_t r;
    asm("cvt.rn.bf16x2.f32 %0, %1, %2;" : "=r"(r) : "f"(hi), "f"(lo));
    return r;
}
// unpack bf16x2 -> sum of the two fp32 values
__device__ __forceinline__ float sum_bf16x2(uint32_t r) {
    __nv_bfloat162 b2 = *reinterpret_cast<__nv_bfloat162*>(&r);
    float2 f2 = __bfloat1622float2(b2);
    return f2.x + f2.y;
}
// split-store a pair of adjacent cols (d even) into hi/mid planes of one row
__device__ __forceinline__ void store_pair(__nv_bfloat16* P, size_t rowo, int d,
                                           float a, float b) {
    float ha = __bfloat162float(__float2bfloat16(a));
    float hb = __bfloat162float(__float2bfloat16(b));
    *(uint32_t*)((char*)P + (rowo + d) * 2)      = pack_bf16x2(b, a);
    *(uint32_t*)((char*)P + (rowo + 64 + d) * 2) = pack_bf16x2(b - hb, a - ha);
}

// ------------------------- prep: zero accumulators + rope table ------------
__global__ void prep_kernel(float* __restrict__ ksqa, float* __restrict__ ksqp,
                            float* __restrict__ xsq2, float2* __restrict__ tbl,
                            int* __restrict__ fctr) {
    int i = blockIdx.x * 256 + threadIdx.x;        // grid 256 -> 65536 threads
    if (i == 0) *fctr = 0;
    if (i < N_QKV) ksqa[i] = 0.f;
    if (i < CC)    ksqp[i] = 0.f;
    if (i < MM)    xsq2[i] = 0.f;
    int t = i >> 5, dd = i & 31;
    float freq = expf(-9.2103403719761836f * ((float)(2*dd) / 64.f));
    float sn, cs;
    sincosf((float)t * freq, &sn, &cs);
    tbl[i] = make_float2(sn, cs);
}

// ------------------------- merged prep2: x split + both W transposes -------
__global__ void prep2_kernel(const float* __restrict__ x,
                             __nv_bfloat16* __restrict__ Ah,
                             __nv_bfloat16* __restrict__ Am,
                             float* __restrict__ xsq,
                             const float* __restrict__ wA,
                             __nv_bfloat16* __restrict__ BhA,
                             __nv_bfloat16* __restrict__ BmA,
                             float* __restrict__ ksqa,
                             const float* __restrict__ wP,
                             __nv_bfloat16* __restrict__ BhP,
                             __nv_bfloat16* __restrict__ BmP,
                             float* __restrict__ ksqp) {
    __shared__ float red[8];
    __shared__ float tile[32][33];
    int blk = blockIdx.x, tid = threadIdx.x;
    if (blk < MM) {
        int row = blk;
        size_t i = (size_t)row * 256 + tid;
        float4 v = ((const float4*)x)[i];
        __nv_bfloat16 h0 = __float2bfloat16(v.x);
        __nv_bfloat16 h1 = __float2bfloat16(v.y);
        __nv_bfloat16 h2 = __float2bfloat16(v.z);
        __nv_bfloat16 h3 = __float2bfloat16(v.w);
        __nv_bfloat162* Hp = (__nv_bfloat162*)Ah;
        __nv_bfloat162* Mq = (__nv_bfloat162*)Am;
        Hp[2*i]   = __nv_bfloat162(h0, h1);
        Hp[2*i+1] = __nv_bfloat162(h2, h3);
        Mq[2*i]   = __nv_bfloat162(__float2bfloat16(v.x - __bfloat162float(h0)),
                                   __float2bfloat16(v.y - __bfloat162float(h1)));
        Mq[2*i+1] = __nv_bfloat162(__float2bfloat16(v.z - __bfloat162float(h2)),
                                   __float2bfloat16(v.w - __bfloat162float(h3)));
        float s = v.x*v.x + v.y*v.y + v.z*v.z + v.w*v.w;
        #pragma unroll
        for (int off = 16; off > 0; off >>= 1)
            s += __shfl_xor_sync(0xffffffffu, s, off);
        if ((tid & 31) == 0) red[tid >> 5] = s;
        __syncthreads();
        if (tid == 0) {
            float t = 0.f;
            #pragma unroll
            for (int w = 0; w < 8; ++w) t += red[w];
            xsq[row] = t;
        }
        return;
    }
    const float* W; __nv_bfloat16 *Bh, *Bm; float* ksq; int N, n0, k0;
    if (blk < MM + 3072) {
        int b2 = blk - MM;
        W = wA; Bh = BhA; Bm = BmA; ksq = ksqa; N = N_QKV;
        n0 = (b2 % 96) * 32; k0 = (b2 / 96) * 32;
    } else {
        int b2 = blk - MM - 3072;
        W = wP; Bh = BhP; Bm = BmP; ksq = ksqp; N = CC;
        n0 = (b2 % 32) * 32; k0 = (b2 / 32) * 32;
    }
    int tx = tid & 31, ty = tid >> 5;
    for (int j = ty; j < 32; j += 8)
        tile[j][tx] = W[(size_t)(k0 + j) * N + n0 + tx];
    __syncthreads();
    for (int j = ty; j < 32; j += 8) {
        float v = tile[tx][j];
        __nv_bfloat16 h = __float2bfloat16(v);
        __nv_bfloat16 m = __float2bfloat16(v - __bfloat162float(h));
        size_t o = (size_t)(n0 + j) * KK + k0 + tx;
        Bh[o] = h; Bm[o] = m;
        float sq = v * v;
        #pragma unroll
        for (int off = 16; off > 0; off >>= 1)
            sq += __shfl_xor_sync(0xffffffffu, sq, off);
        if (tx == 0) atomicAdd(&ksq[n0 + j], sq);
    }
}

// ------------------------- mma.sync GEMM + YAT epilogue -------------------
// CTA 128(M)x256(N), 8 warps 2x4 -> warp tile 64x64. 3-stage cp.async.
// MODE 0 (GEMM2): 3 MMA combos, YAT -> fp32 out.
// MODE 1 (GEMM1): Q/K regions 1 combo (hh), V region 2 combos (hh+hm);
//                 YAT -> RoPE -> Qp/Kp (hi) + Vp split planes.
#define SROW 144
#define ATILE (128*SROW)                 // 18432
#define BTILE (256*SROW)                 // 36864
#define GSTAGE (ATILE + BTILE)           // 55296
#define GNKCH (KK/32)                    // 32

template<int MODE>
__global__ __launch_bounds__(256, 1)
void gemm_mma_kernel(const __nv_bfloat16* __restrict__ Ah, const __nv_bfloat16* __restrict__ Am,
                     const __nv_bfloat16* __restrict__ Bh, const __nv_bfloat16* __restrict__ Bm,
                     const float* __restrict__ bias, const float* __restrict__ xsq,
                     const float* __restrict__ ksq, const float* __restrict__ alphap,
                     float* __restrict__ out, int N, float outf,
                     __nv_bfloat16* __restrict__ Qp, __nv_bfloat16* __restrict__ Kp,
                     __nv_bfloat16* __restrict__ Vp, const float2* __restrict__ tbl) {
    extern __shared__ char dsm[];
    uint32_t sbase = smem_u32(dsm);

    const int tid = threadIdx.x;
    const int lane = tid & 31;
    const int wid = tid >> 5;
    const int wm = wid >> 2;
    const int wn = wid & 3;
    const int m0 = blockIdx.y * 128;
    const int n0 = blockIdx.x * 256;
    const int l8 = lane & 7;
    const int lm = lane >> 3;
    const int region = (MODE == 1) ? (n0 >> 10) : 2;
    const bool useBmid = (MODE == 0) || (region == 2);

    const char* pAh = (const char*)Ah + (size_t)m0 * (KK*2);
    const char* pAm = (const char*)Am + (size_t)m0 * (KK*2);
    const char* pBh = (const char*)Bh + (size_t)n0 * (KK*2);
    const char* pBm = (const char*)Bm + (size_t)n0 * (KK*2);

    const int lplane = (tid >> 2) & 1;
    const int lchunk = tid & 3;

    #define LOAD_CHUNK(kc, st) do {                                           \
        size_t kb = (size_t)(kc) * 64 + (size_t)lchunk * 16;                  \
        uint32_t sbs = sbase + (st) * GSTAGE;                                 \
        uint32_t doff0 = (tid >> 3) * SROW + lplane * 64 + lchunk * 16;       \
        if (MODE == 0 || lplane == 0) {                                       \
            _Pragma("unroll")                                                 \
            for (int i = 0; i < 4; ++i) {                                     \
                int row = (tid >> 3) + i * 32;                                \
                const char* sa = (lplane ? pAm : pAh) + (size_t)row * (KK*2) + kb;\
                cp16(sbs + doff0 + i * (32*SROW), sa);                        \
            }                                                                 \
        }                                                                     \
        if (useBmid || lplane == 0) {                                         \
            _Pragma("unroll")                                                 \
            for (int i = 0; i < 8; ++i) {                                     \
                int row = (tid >> 3) + i * 32;                                \
                const char* sbp = (lplane ? pBm : pBh) + (size_t)row * (KK*2) + kb;\
                cp16(sbs + ATILE + doff0 + i * (32*SROW), sbp);               \
            }                                                                 \
        }                                                                     \
        CP_COMMIT();                                                          \
    } while (0)

    float acc[4][8][4];
    #pragma unroll
    for (int i = 0; i < 4; ++i)
        #pragma unroll
        for (int j = 0; j < 8; ++j)
            #pragma unroll
            for (int r = 0; r < 4; ++r) acc[i][j][r] = 0.f;

    const int arow = lane & 15;
    const int akoff = (lane >> 4) * 16;
    constexpr int NPL = (MODE == 0) ? 2 : 1;

    LOAD_CHUNK(0, 0);
    LOAD_CHUNK(1, 1);

    for (int kc = 0; kc < GNKCH; ++kc) {
        int st = kc - (kc / 3) * 3;
        if (kc + 1 < GNKCH) { CP_WAIT(1); } else { CP_WAIT(0); }
        __syncthreads();
        if (kc + 2 < GNKCH) {
            int st2 = (kc + 2) - ((kc + 2) / 3) * 3;
            LOAD_CHUNK(kc + 2, st2);
        }

        uint32_t sA = sbase + st * GSTAGE;
        uint32_t sB = sA + ATILE;

        #pragma unroll
        for (int ks = 0; ks < 2; ++ks) {
            uint32_t a[NPL][4][4];
            #pragma unroll
            for (int pl = 0; pl < NPL; ++pl)
                #pragma unroll
                for (int fm = 0; fm < 4; ++fm) {
                    uint32_t ad = sA + (wm*64 + fm*16 + arow) * SROW
                                + pl*64 + ks*32 + akoff;
                    LDM4(a[pl][fm][0], a[pl][fm][1], a[pl][fm][2], a[pl][fm][3], ad);
                }
            uint32_t b[2][8][2];
            #pragma unroll
            for (int pr = 0; pr < 4; ++pr) {
                uint32_t bd = sB + (wn*64 + (pr*2 + (lm >> 1))*8 + l8) * SROW
                            + ks*32 + (lm & 1)*16;
                LDM4(b[0][pr*2][0], b[0][pr*2][1],
                     b[0][pr*2+1][0], b[0][pr*2+1][1], bd);
            }
            if (useBmid) {
                #pragma unroll
                for (int pr = 0; pr < 4; ++pr) {
                    uint32_t bd = sB + (wn*64 + (pr*2 + (lm >> 1))*8 + l8) * SROW
                                + 64 + ks*32 + (lm & 1)*16;
                    LDM4(b[1][pr*2][0], b[1][pr*2][1],
                         b[1][pr*2+1][0], b[1][pr*2+1][1], bd);
                }
            }
            #pragma unroll
            for (int fm = 0; fm < 4; ++fm)
                #pragma unroll
                for (int fn = 0; fn < 8; ++fn) {
                    MMA16816(acc[fm][fn], a[0][fm], b[0][fn]);
                    if (useBmid) MMA16816(acc[fm][fn], a[0][fm], b[1][fn]);
                    if (MODE == 0) MMA16816(acc[fm][fn], a[NPL-1][fm], b[0][fn]);
                }
        }
        __syncthreads();
    }

    float alpha = *alphap;
    float scl = powf(sqrtf(outf) / logf(1.f + outf), alpha);
    int g = lane >> 2;
    int t2 = (lane & 3) * 2;

    #pragma unroll
    for (int fm = 0; fm < 4; ++fm) {
        int mA = m0 + wm*64 + fm*16 + g;
        float xsA = xsq[mA];
        float xsB = xsq[mA + 8];
        #pragma unroll
        for (int fn = 0; fn < 8; ++fn) {
            int col = n0 + wn*64 + fn*8 + t2;
            float k0v = ksq[col], k1v = ksq[col+1];
            float b0v = bias[col], b1v = bias[col+1];
            float d0 = acc[fm][fn][0], d1 = acc[fm][fn][1];
            float d2 = acc[fm][fn][2], d3 = acc[fm][fn][3];
            acc[fm][fn][0] = d0*d0 / (xsA + k0v - 2.f*d0 + EPSY) * scl + b0v;
            acc[fm][fn][1] = d1*d1 / (xsA + k1v - 2.f*d1 + EPSY) * scl + b1v;
            acc[fm][fn][2] = d2*d2 / (xsB + k0v - 2.f*d2 + EPSY) * scl + b0v;
            acc[fm][fn][3] = d3*d3 / (xsB + k1v - 2.f*d3 + EPSY) * scl + b1v;
        }
        if (MODE == 0) {
            #pragma unroll
            for (int fn = 0; fn < 8; ++fn) {
                int col = n0 + wn*64 + fn*8 + t2;
                *(float2*)(out + (size_t)mA * N + col)
                    = make_float2(acc[fm][fn][0], acc[fm][fn][1]);
                *(float2*)(out + (size_t)(mA+8) * N + col)
                    = make_float2(acc[fm][fn][2], acc[fm][fn][3]);
            }
        } else {
            int hloc = ((n0 & 1023) + wn*64) >> 6;
            float qs = (region == 0) ? 0.125f : 1.f;
            #pragma unroll
            for (int half = 0; half < 2; ++half) {
                int mrow = mA + half*8;
                int t = mrow & (TT-1);
                int b = mrow >> 11;
                if (region < 2) {
                    __nv_bfloat16* P = (region == 0) ? Qp : Kp;
                    size_t rowo = ((size_t)(b*HH + hloc) * TT + t) * 64;
                    #pragma unroll
                    for (int fn = 0; fn < 4; ++fn) {
                        int dd = fn*8 + t2;
                        float4 sc = *(const float4*)(tbl + (t*32 + dd));
                        float x1a = acc[fm][fn][half*2]     * qs;
                        float x1b = acc[fm][fn][half*2+1]   * qs;
                        float x2a = acc[fm][fn+4][half*2]   * qs;
                        float x2b = acc[fm][fn+4][half*2+1] * qs;
                        float r0a = x1a*sc.y - x2a*sc.x, r0b = x1b*sc.w - x2b*sc.z;
                        float r1a = x2a*sc.y + x1a*sc.x, r1b = x2b*sc.w + x1b*sc.z;
                        *(uint32_t*)((char*)P + (rowo + dd) * 2)      = pack_bf16x2(r0b, r0a);
                        *(uint32_t*)((char*)P + (rowo + dd + 32) * 2) = pack_bf16x2(r1b, r1a);
                    }
                } else {
                    size_t rowo = ((size_t)(b*HH + hloc) * TT + t) * 128;
                    #pragma unroll
                    for (int fn = 0; fn < 8; ++fn)
                        store_pair(Vp, rowo, fn*8 + t2,
                                   acc[fm][fn][half*2], acc[fm][fn][half*2+1]);
                }
            }
        }
    }
    #undef LOAD_CHUNK
}

// ------------------------- flash attention (persistent, mma.sync) ----------
// BQ=128, BK=128. Q/K hi-only rows 128B (+16 pad = 144). V rows [hi|mid] 272B.
// QK: 1 MMA combo. PV: 2 combos (p_hi*v_hi + p_hi*v_mid); l is computed from
// the SAME bf16-rounded p values the MMA sees -> exact weighted mean under
// perturbed weights. Fixed m=0 (logits provably bounded for this problem).
#define FQ 128
#define QROWK 144
#define VROW 272
#define SQ_SZ (128*QROWK)                // 18432
#define SK_OFF SQ_SZ
#define SK_SZ (128*QROWK)                // 18432
#define SV_OFF (SK_OFF + 2*SK_SZ)        // 55296
#define SV_SZ (128*VROW)                 // 34816
#define FSMEM (SV_OFF + 2*SV_SZ)         // 124928
#define NPERS 148

__global__ __launch_bounds__(256, 1)
void flash_mma_kernel(const __nv_bfloat16* __restrict__ Qp,
                      const __nv_bfloat16* __restrict__ Kp,
                      const __nv_bfloat16* __restrict__ Vp,
                      __nv_bfloat16* __restrict__ OH,
                      __nv_bfloat16* __restrict__ OM,
                      float* __restrict__ xsq2,
                      int* __restrict__ fctr) {
    extern __shared__ char smf[];
    __shared__ int s_task;
    uint32_t sb = smem_u32(smf);
    int tid = threadIdx.x;
    int lane = tid & 31, wq = tid >> 5;
    const int l8 = lane & 7, lm = lane >> 3;
    const int g = lane >> 2, cq = lane & 3;

    for (;;) {
        if (tid == 0) s_task = atomicAdd(fctr, 1);
        __syncthreads();
        int task = s_task;
        if (task >= NTASK) return;
        int qi = (TT/FQ) - 1 - (task >> 5);   // descending work (LPT)
        int bh = task & 31;
        int q0 = qi * FQ;
        const char* Qg = (const char*)(Qp + ((size_t)bh * TT + q0) * 64);
        const char* Kg = (const char*)(Kp + (size_t)bh * TT * 64);
        const char* Vg = (const char*)(Vp + (size_t)bh * TT * 128);

        // Q tile (hi only) + K0 + V0 -> stage 0
        #pragma unroll
        for (int i = 0; i < 4; ++i) {
            int idx = tid + i * 256; int r = idx >> 3, ch = idx & 7;
            cp16(sb + r * QROWK + ch * 16, Qg + (size_t)r * 128 + ch * 16);
        }
        #pragma unroll
        for (int i = 0; i < 4; ++i) {
            int idx = tid + i * 256; int r = idx >> 3, ch = idx & 7;
            cp16(sb + SK_OFF + r * QROWK + ch * 16, Kg + (size_t)r * 128 + ch * 16);
        }
        #pragma unroll
        for (int i = 0; i < 8; ++i) {
            int idx = tid + i * 256; int r = idx >> 4, ch = idx & 15;
            cp16(sb + SV_OFF + r * VROW + ch * 16, Vg + (size_t)r * 256 + ch * 16);
        }
        CP_COMMIT();

        float oacc[8][4];
        #pragma unroll
        for (int fo = 0; fo < 8; ++fo)
            #pragma unroll
            for (int r = 0; r < 4; ++r) oacc[fo][r] = 0.f;
        uint32_t qa[4][4];
        float l0 = 0.f, l1 = 0.f;
        const int nkt = qi + 1;

        for (int kt = 0; kt < nkt; ++kt) {
            int st = kt & 1;
            CP_WAIT(0);
            __syncthreads();
            if (kt + 1 < nkt) {
                int sn = st ^ 1, k0n = (kt + 1) * FQ;
                #pragma unroll
                for (int i = 0; i < 4; ++i) {
                    int idx = tid + i * 256; int r = idx >> 3, ch = idx & 7;
                    cp16(sb + SK_OFF + sn * SK_SZ + r * QROWK + ch * 16,
                         Kg + (size_t)(k0n + r) * 128 + ch * 16);
                }
                #pragma unroll
                for (int i = 0; i < 8; ++i) {
                    int idx = tid + i * 256; int r = idx >> 4, ch = idx & 15;
                    cp16(sb + SV_OFF + sn * SV_SZ + r * VROW + ch * 16,
                         Vg + (size_t)(k0n + r) * 256 + ch * 16);
                }
                CP_COMMIT();
            }

            if (kt == 0) {
                #pragma unroll
                for (int ks = 0; ks < 4; ++ks) {
                    uint32_t ad = sb + (wq * 16 + (lane & 15)) * QROWK
                                + ks * 32 + (lane >> 4) * 16;
                    LDM4(qa[ks][0], qa[ks][1], qa[ks][2], qa[ks][3], ad);
                }
            }

            uint32_t sKb = sb + SK_OFF + st * SK_SZ;
            uint32_t sVb = sb + SV_OFF + st * SV_SZ;
            bool diag = (kt == nkt - 1);
            const int fnmax = diag ? (2*wq + 2) : 16;
            const int k2max = diag ? (wq + 1) : 8;

            // ---- S = Q K^T, single combo ------------------------------------
            float sacc[16][4];
            #pragma unroll
            for (int fn = 0; fn < 16; ++fn)
                #pragma unroll
                for (int r = 0; r < 4; ++r) sacc[fn][r] = 0.f;

            #pragma unroll
            for (int ks = 0; ks < 4; ++ks) {
                #pragma unroll
                for (int half = 0; half < 2; ++half) {
                    if (half*8 >= fnmax) break;
                    uint32_t kh[8][2];
                    #pragma unroll
                    for (int pr = 0; pr < 4; ++pr) {
                        if (half*8 + pr*2 >= fnmax) break;
                        uint32_t base = sKb
                            + (half*64 + (pr*2 + (lm >> 1))*8 + l8) * QROWK
                            + ks*32 + (lm & 1)*16;
                        LDM4(kh[pr*2][0], kh[pr*2][1], kh[pr*2+1][0], kh[pr*2+1][1], base);
                    }
                    #pragma unroll
                    for (int f = 0; f < 8; ++f) {
                        if (half*8 + f >= fnmax) break;
                        MMA16816(sacc[half*8 + f], qa[ks], kh[f]);
                    }
                }
            }

            // ---- mask + softmax (fixed m=0) ----------------------------------
            int k0 = kt * FQ;
            int r0q = q0 + wq * 16 + g;
            if (diag) {
                #pragma unroll
                for (int fn = 0; fn < 16; ++fn) {
                    int col = k0 + fn * 8 + 2 * cq;
                    if (col     > r0q)     sacc[fn][0] = -1e30f;
                    if (col + 1 > r0q)     sacc[fn][1] = -1e30f;
                    if (col     > r0q + 8) sacc[fn][2] = -1e30f;
                    if (col + 1 > r0q + 8) sacc[fn][3] = -1e30f;
                }
            }

            // pack bf16 p; l sums the ROUNDED values -> exact weighted mean
            float rs0 = 0.f, rs1 = 0.f;
            uint32_t pah[8][4];
            #pragma unroll
            for (int k2 = 0; k2 < 8; ++k2) {
                #pragma unroll
                for (int half = 0; half < 2; ++half) {
                    int fn = k2 * 2 + half;
                    float p0 = __expf(sacc[fn][0]);
                    float p1 = __expf(sacc[fn][1]);
                    float p2 = __expf(sacc[fn][2]);
                    float p3 = __expf(sacc[fn][3]);
                    uint32_t r01 = pack_bf16x2(p1, p0);
                    uint32_t r23 = pack_bf16x2(p3, p2);
                    pah[k2][half*2+0] = r01;
                    pah[k2][half*2+1] = r23;
                    rs0 += sum_bf16x2(r01);
                    rs1 += sum_bf16x2(r23);
                }
            }
            rs0 += __shfl_xor_sync(0xffffffffu, rs0, 1);
            rs0 += __shfl_xor_sync(0xffffffffu, rs0, 2);
            rs1 += __shfl_xor_sync(0xffffffffu, rs1, 1);
            rs1 += __shfl_xor_sync(0xffffffffu, rs1, 2);
            l0 += rs0;
            l1 += rs1;

            // ---- O += P V (2 combos, ldmatrix.trans) -------------------------
            #pragma unroll
            for (int k2 = 0; k2 < 8; ++k2) {
                if (k2 >= k2max) break;
                uint32_t vh[8][2], vm[8][2];
                #pragma unroll
                for (int pr = 0; pr < 4; ++pr) {
                    uint32_t base = sVb + (k2*16 + (lm & 1)*8 + l8) * VROW
                                  + (pr*2 + (lm >> 1)) * 16;
                    LDM4T(vh[pr*2][0], vh[pr*2][1], vh[pr*2+1][0], vh[pr*2+1][1], base);
                    LDM4T(vm[pr*2][0], vm[pr*2][1], vm[pr*2+1][0], vm[pr*2+1][1],
                          base + 128);
                }
                #pragma unroll
                for (int fo = 0; fo < 8; ++fo) {
                    MMA16816(oacc[fo], pah[k2], vh[fo]);
                    MMA16816(oacc[fo], pah[k2], vm[fo]);
                }
            }
        }

        // ---- fused epilogue: bf16 split planes + atomic row-sumsq -----------
        float inv0 = 1.f / l0, inv1 = 1.f / l1;
        int b = bh >> 4, h = bh & 15;
        int r0q = q0 + wq * 16 + g;
        size_t row0 = (size_t)(b * TT + r0q);
        float s0 = 0.f, s1 = 0.f;
        #pragma unroll
        for (int fo = 0; fo < 8; ++fo) {
            int col = h * 64 + fo * 8 + 2 * cq;
            float w00 = oacc[fo][0] * inv0, w01 = oacc[fo][1] * inv0;
            float w10 = oacc[fo][2] * inv1, w11 = oacc[fo][3] * inv1;
            s0 += w00*w00 + w01*w01;
            s1 += w10*w10 + w11*w11;
            float h00 = __bfloat162float(__float2bfloat16(w00));
            float h01 = __bfloat162float(__float2bfloat16(w01));
            float h10 = __bfloat162float(__float2bfloat16(w10));
            float h11 = __bfloat162float(__float2bfloat16(w11));
            *(uint32_t*)((char*)OH + (row0 * KK + col) * 2) = pack_bf16x2(w01, w00);
            *(uint32_t*)((char*)OM + (row0 * KK + col) * 2) = pack_bf16x2(w01 - h01, w00 - h00);
            *(uint32_t*)((char*)OH + ((row0 + 8) * KK + col) * 2) = pack_bf16x2(w11, w10);
            *(uint32_t*)((char*)OM + ((row0 + 8) * KK + col) * 2) = pack_bf16x2(w11 - h11, w10 - h10);
        }
        s0 += __shfl_xor_sync(0xffffffffu, s0, 1);
        s0 += __shfl_xor_sync(0xffffffffu, s0, 2);
        s1 += __shfl_xor_sync(0xffffffffu, s1, 1);
        s1 += __shfl_xor_sync(0xffffffffu, s1, 2);
        if (cq == 0) {
            atomicAdd(&xsq2[row0], s0);
            atomicAdd(&xsq2[row0 + 8], s1);
        }
    }
}

// ------------------------- host launch --------------------------------------
extern "C" void kernel_launch(void* const* d_in, const int* in_sizes, int n_in,
                              void* d_out, int out_size) {
    const float* x      = (const float*)d_in[0];
    const float* w_attn = (const float*)d_in[2];
    const float* b_attn = (const float*)d_in[3];
    const float* a_attn = (const float*)d_in[4];
    const float* w_proj = (const float*)d_in[5];
    const float* b_proj = (const float*)d_in[6];
    const float* a_proj = (const float*)d_in[7];
    float* out = (float*)d_out;

    void *xsq_, *xsq2_, *ksqa_, *ksqp_, *tbl_, *fctr_;
    void *ah_, *am_, *bha_, *bma_, *bhp_, *bmp_, *qp_, *kp_, *vp_;
    cudaGetSymbolAddress(&xsq_,  g_xsq);
    cudaGetSymbolAddress(&xsq2_, g_xsq2);
    cudaGetSymbolAddress(&ksqa_, g_ksqA);
    cudaGetSymbolAddress(&ksqp_, g_ksqP);
    cudaGetSymbolAddress(&tbl_,  g_tbl);
    cudaGetSymbolAddress(&fctr_, g_fctr);
    cudaGetSymbolAddress(&ah_,   g_Ah);
    cudaGetSymbolAddress(&am_,   g_Am);
    cudaGetSymbolAddress(&bha_,  g_BhA);
    cudaGetSymbolAddress(&bma_,  g_BmA);
    cudaGetSymbolAddress(&bhp_,  g_BhP);
    cudaGetSymbolAddress(&bmp_,  g_BmP);
    cudaGetSymbolAddress(&qp_,   g_Qp);
    cudaGetSymbolAddress(&kp_,   g_Kp);
    cudaGetSymbolAddress(&vp_,   g_Vp);
    float* xsq  = (float*)xsq_;
    float* xsq2 = (float*)xsq2_;
    float* ksqa = (float*)ksqa_;
    float* ksqp = (float*)ksqp_;
    float2* tbl = (float2*)tbl_;
    int* fctr   = (int*)fctr_;
    __nv_bfloat16* Ah  = (__nv_bfloat16*)ah_;
    __nv_bfloat16* Am  = (__nv_bfloat16*)am_;
    __nv_bfloat16* BhA = (__nv_bfloat16*)bha_;
    __nv_bfloat16* BmA = (__nv_bfloat16*)bma_;
    __nv_bfloat16* BhP = (__nv_bfloat16*)bhp_;
    __nv_bfloat16* BmP = (__nv_bfloat16*)bmp_;
    __nv_bfloat16* Qp  = (__nv_bfloat16*)qp_;
    __nv_bfloat16* Kp  = (__nv_bfloat16*)kp_;
    __nv_bfloat16* Vp  = (__nv_bfloat16*)vp_;

    const int gemm_smem = 3 * GSTAGE;                        // 165888
    cudaFuncSetAttribute(gemm_mma_kernel<0>,
                         cudaFuncAttributeMaxDynamicSharedMemorySize, gemm_smem);
    cudaFuncSetAttribute(gemm_mma_kernel<1>,
                         cudaFuncAttributeMaxDynamicSharedMemorySize, gemm_smem);
    cudaFuncSetAttribute(flash_mma_kernel,
                         cudaFuncAttributeMaxDynamicSharedMemorySize, FSMEM);

    // zero accumulators + task counter + rope table
    prep_kernel<<<256, 256>>>(ksqa, ksqp, xsq2, tbl, fctr);

    // merged: x split+rowsq, w_attn transpose+colsq, w_proj transpose+colsq
    prep2_kernel<<<MM + 3072 + 1024, 256>>>(x, Ah, Am, xsq,
                                            w_attn, BhA, BmA, ksqa,
                                            w_proj, BhP, BmP, ksqp);

    // GEMM1 (Q/K 1 combo, V 2 combos) + YAT + RoPE + split -> Qp/Kp/Vp
    {
        dim3 grid(N_QKV / 256, MM / 128);
        gemm_mma_kernel<1><<<grid, 256, gemm_smem>>>(Ah, Am, BhA, BmA, b_attn, xsq,
                                                     ksqa, a_attn, nullptr, N_QKV,
                                                     (float)N_QKV, Qp, Kp, Vp, tbl);
    }

    // persistent flash attention (QK 1 combo, PV 2 combos, m=0) -> Ah/Am + xsq2
    flash_mma_kernel<<<NPERS, 256, FSMEM>>>(Qp, Kp, Vp, Ah, Am, xsq2, fctr);

    // GEMM2 (3 combos) + YAT -> out
    {
        dim3 grid(CC / 256, MM / 128);
        gemm_mma_kernel<0><<<grid, 256, gemm_smem>>>(Ah, Am, BhP, BmP, b_proj, xsq2,
                                                     ksqp, a_proj, out, CC,
                                                     (float)CC, nullptr, nullptr,
                                                     nullptr, nullptr);
    }
}

// round 13
// speedup vs baseline: 1.1763x; 1.0393x over previous
#include <cuda_runtime.h>
#include <cuda_bf16.h>
#include <math.h>
#include <stdint.h>

// Problem constants
#define BB 2
#define TT 2048
#define CC 1024
#define HH 16
#define DD 64
#define MM (BB*TT)          // 4096
#define N_QKV (3*CC)        // 3072
#define KK CC               // GEMM K = 1024
#define BH (BB*HH)          // 32
#define EPSY 1e-6f
#define NTASK (BH * (TT/128))   // 512 flash tasks

// ------------------------- scratch (device globals) -----------------------
__device__ float g_xsq[MM];
__device__ float g_xsq2[MM];
__device__ float g_ksqA[N_QKV];
__device__ float g_ksqP[CC];
__device__ float2 g_tbl[TT * 32];
__device__ int g_fctr;
__device__ __nv_bfloat16 g_Ah[(size_t)MM * KK];
__device__ __nv_bfloat16 g_Am[(size_t)MM * KK];
__device__ __nv_bfloat16 g_BhA[(size_t)N_QKV * KK];
__device__ __nv_bfloat16 g_BmA[(size_t)N_QKV * KK];
__device__ __nv_bfloat16 g_BhP[(size_t)CC * KK];
__device__ __nv_bfloat16 g_BmP[(size_t)CC * KK];
// flash operands: Qp/Kp hi-only [bh][t][64] bf16; Vp [bh][t][hi64|mid64]
__device__ __nv_bfloat16 g_Qp[(size_t)BH * TT * 64];
__device__ __nv_bfloat16 g_Kp[(size_t)BH * TT * 64];
__device__ __nv_bfloat16 g_Vp[(size_t)BH * TT * 128];

// ------------------------- PTX helpers ------------------------------------
__device__ __forceinline__ uint32_t smem_u32(const void* p) {
    uint32_t a;
    asm("{ .reg .u64 t; cvta.to.shared.u64 t, %1; cvt.u32.u64 %0, t; }"
        : "=r"(a) : "l"(p));
    return a;
}
__device__ __forceinline__ void cp16(uint32_t dst, const void* src) {
    asm volatile("cp.async.cg.shared.global [%0], [%1], 16;" :: "r"(dst), "l"(src) : "memory");
}
#define CP_COMMIT() asm volatile("cp.async.commit_group;" ::: "memory")
#define CP_WAIT(n)  asm volatile("cp.async.wait_group %0;" :: "n"(n) : "memory")

#define LDM4(r0, r1, r2, r3, addr) \
    asm volatile("ldmatrix.sync.aligned.m8n8.x4.shared.b16 {%0,%1,%2,%3}, [%4];" \
        : "=r"(r0), "=r"(r1), "=r"(r2), "=r"(r3) : "r"(addr))

#define LDM4T(r0, r1, r2, r3, addr) \
    asm volatile("ldmatrix.sync.aligned.m8n8.x4.trans.shared.b16 {%0,%1,%2,%3}, [%4];" \
        : "=r"(r0), "=r"(r1), "=r"(r2), "=r"(r3) : "r"(addr))

#define MMA16816(d, a, b) \
    asm volatile("mma.sync.aligned.m16n8k16.row.col.f32.bf16.bf16.f32 " \
        "{%0,%1,%2,%3}, {%4,%5,%6,%7}, {%8,%9}, {%0,%1,%2,%3};" \
        : "+f"((d)[0]), "+f"((d)[1]), "+f"((d)[2]), "+f"((d)[3]) \
        : "r"((a)[0]), "r"((a)[1]), "r"((a)[2]), "r"((a)[3]), \
          "r"((b)[0]), "r"((b)[1]))

// packs {hi, lo} fp32 -> bf16x2 (first source is upper half)
__device__ __forceinline__ uint32_t pack_bf16x2(float hi, float lo) {
    uint32_t r;
    asm("cvt.rn.bf16x2.f32 %0, %1, %2;" : "=r"(r) : "f"(hi), "f"(lo));
    return r;
}
// split-store a pair of adjacent cols (d even) into hi/mid planes of one row
__device__ __forceinline__ void store_pair(__nv_bfloat16* P, size_t rowo, int d,
                                           float a, float b) {
    float ha = __bfloat162float(__float2bfloat16(a));
    float hb = __bfloat162float(__float2bfloat16(b));
    *(uint32_t*)((char*)P + (rowo + d) * 2)      = pack_bf16x2(b, a);
    *(uint32_t*)((char*)P + (rowo + 64 + d) * 2) = pack_bf16x2(b - hb, a - ha);
}

// ------------------------- prep: zero accumulators + rope table ------------
__global__ void prep_kernel(float* __restrict__ ksqa, float* __restrict__ ksqp,
                            float* __restrict__ xsq2, float2* __restrict__ tbl,
                            int* __restrict__ fctr) {
    int i = blockIdx.x * 256 + threadIdx.x;        // grid 256 -> 65536 threads
    if (i == 0) *fctr = 0;
    if (i < N_QKV) ksqa[i] = 0.f;
    if (i < CC)    ksqp[i] = 0.f;
    if (i < MM)    xsq2[i] = 0.f;
    int t = i >> 5, dd = i & 31;
    float freq = expf(-9.2103403719761836f * ((float)(2*dd) / 64.f));
    float sn, cs;
    sincosf((float)t * freq, &sn, &cs);
    tbl[i] = make_float2(sn, cs);
}

// ------------------------- merged prep2: x split + both W transposes -------
__global__ void prep2_kernel(const float* __restrict__ x,
                             __nv_bfloat16* __restrict__ Ah,
                             __nv_bfloat16* __restrict__ Am,
                             float* __restrict__ xsq,
                             const float* __restrict__ wA,
                             __nv_bfloat16* __restrict__ BhA,
                             __nv_bfloat16* __restrict__ BmA,
                             float* __restrict__ ksqa,
                             const float* __restrict__ wP,
                             __nv_bfloat16* __restrict__ BhP,
                             __nv_bfloat16* __restrict__ BmP,
                             float* __restrict__ ksqp) {
    __shared__ float red[8];
    __shared__ float tile[32][33];
    int blk = blockIdx.x, tid = threadIdx.x;
    if (blk < MM) {
        int row = blk;
        size_t i = (size_t)row * 256 + tid;
        float4 v = ((const float4*)x)[i];
        __nv_bfloat16 h0 = __float2bfloat16(v.x);
        __nv_bfloat16 h1 = __float2bfloat16(v.y);
        __nv_bfloat16 h2 = __float2bfloat16(v.z);
        __nv_bfloat16 h3 = __float2bfloat16(v.w);
        __nv_bfloat162* Hp = (__nv_bfloat162*)Ah;
        __nv_bfloat162* Mq = (__nv_bfloat162*)Am;
        Hp[2*i]   = __nv_bfloat162(h0, h1);
        Hp[2*i+1] = __nv_bfloat162(h2, h3);
        Mq[2*i]   = __nv_bfloat162(__float2bfloat16(v.x - __bfloat162float(h0)),
                                   __float2bfloat16(v.y - __bfloat162float(h1)));
        Mq[2*i+1] = __nv_bfloat162(__float2bfloat16(v.z - __bfloat162float(h2)),
                                   __float2bfloat16(v.w - __bfloat162float(h3)));
        float s = v.x*v.x + v.y*v.y + v.z*v.z + v.w*v.w;
        #pragma unroll
        for (int off = 16; off > 0; off >>= 1)
            s += __shfl_xor_sync(0xffffffffu, s, off);
        if ((tid & 31) == 0) red[tid >> 5] = s;
        __syncthreads();
        if (tid == 0) {
            float t = 0.f;
            #pragma unroll
            for (int w = 0; w < 8; ++w) t += red[w];
            xsq[row] = t;
        }
        return;
    }
    const float* W; __nv_bfloat16 *Bh, *Bm; float* ksq; int N, n0, k0;
    if (blk < MM + 3072) {
        int b2 = blk - MM;
        W = wA; Bh = BhA; Bm = BmA; ksq = ksqa; N = N_QKV;
        n0 = (b2 % 96) * 32; k0 = (b2 / 96) * 32;
    } else {
        int b2 = blk - MM - 3072;
        W = wP; Bh = BhP; Bm = BmP; ksq = ksqp; N = CC;
        n0 = (b2 % 32) * 32; k0 = (b2 / 32) * 32;
    }
    int tx = tid & 31, ty = tid >> 5;
    for (int j = ty; j < 32; j += 8)
        tile[j][tx] = W[(size_t)(k0 + j) * N + n0 + tx];
    __syncthreads();
    for (int j = ty; j < 32; j += 8) {
        float v = tile[tx][j];
        __nv_bfloat16 h = __float2bfloat16(v);
        __nv_bfloat16 m = __float2bfloat16(v - __bfloat162float(h));
        size_t o = (size_t)(n0 + j) * KK + k0 + tx;
        Bh[o] = h; Bm[o] = m;
        float sq = v * v;
        #pragma unroll
        for (int off = 16; off > 0; off >>= 1)
            sq += __shfl_xor_sync(0xffffffffu, sq, off);
        if (tx == 0) atomicAdd(&ksq[n0 + j], sq);
    }
}

// ------------------------- mma.sync GEMM + YAT epilogue -------------------
// CTA 128(M)x256(N), 8 warps 2x4 -> warp tile 64x64. 3-stage cp.async.
// MODE 0 (GEMM2): 3 MMA combos, YAT -> fp32 out.
// MODE 1 (GEMM1): Q/K regions 1 combo (hh), V region 2 combos (hh+hm);
//                 YAT -> RoPE -> Qp/Kp (hi) + Vp split planes.
//                 1D grid with HEAVY-FIRST decode (V CTAs get ids 0..127).
#define SROW 144
#define ATILE (128*SROW)                 // 18432
#define BTILE (256*SROW)                 // 36864
#define GSTAGE (ATILE + BTILE)           // 55296
#define GNKCH (KK/32)                    // 32

template<int MODE>
__global__ __launch_bounds__(256, 1)
void gemm_mma_kernel(const __nv_bfloat16* __restrict__ Ah, const __nv_bfloat16* __restrict__ Am,
                     const __nv_bfloat16* __restrict__ Bh, const __nv_bfloat16* __restrict__ Bm,
                     const float* __restrict__ bias, const float* __restrict__ xsq,
                     const float* __restrict__ ksq, const float* __restrict__ alphap,
                     float* __restrict__ out, int N, float outf,
                     __nv_bfloat16* __restrict__ Qp, __nv_bfloat16* __restrict__ Kp,
                     __nv_bfloat16* __restrict__ Vp, const float2* __restrict__ tbl) {
    extern __shared__ char dsm[];
    uint32_t sbase = smem_u32(dsm);

    const int tid = threadIdx.x;
    const int lane = tid & 31;
    const int wid = tid >> 5;
    const int wm = wid >> 2;
    const int wn = wid & 3;
    int m0, n0;
    if (MODE == 1) {
        // heavy-first: V-region CTAs (2 combos) occupy block ids [0,128)
        int id = blockIdx.x;
        if (id < 128) { n0 = (8 + (id & 3)) * 256; m0 = (id >> 2) * 128; }
        else { int id2 = id - 128; n0 = (id2 & 7) * 256; m0 = (id2 >> 3) * 128; }
    } else {
        m0 = blockIdx.y * 128;
        n0 = blockIdx.x * 256;
    }
    const int l8 = lane & 7;
    const int lm = lane >> 3;
    const int region = (MODE == 1) ? (n0 >> 10) : 2;
    const bool useBmid = (MODE == 0) || (region == 2);

    const char* pAh = (const char*)Ah + (size_t)m0 * (KK*2);
    const char* pAm = (const char*)Am + (size_t)m0 * (KK*2);
    const char* pBh = (const char*)Bh + (size_t)n0 * (KK*2);
    const char* pBm = (const char*)Bm + (size_t)n0 * (KK*2);

    const int lplane = (tid >> 2) & 1;
    const int lchunk = tid & 3;

    #define LOAD_CHUNK(kc, st) do {                                           \
        size_t kb = (size_t)(kc) * 64 + (size_t)lchunk * 16;                  \
        uint32_t sbs = sbase + (st) * GSTAGE;                                 \
        uint32_t doff0 = (tid >> 3) * SROW + lplane * 64 + lchunk * 16;       \
        if (MODE == 0 || lplane == 0) {                                       \
            _Pragma("unroll")                                                 \
            for (int i = 0; i < 4; ++i) {                                     \
                int row = (tid >> 3) + i * 32;                                \
                const char* sa = (lplane ? pAm : pAh) + (size_t)row * (KK*2) + kb;\
                cp16(sbs + doff0 + i * (32*SROW), sa);                        \
            }                                                                 \
        }                                                                     \
        if (useBmid || lplane == 0) {                                         \
            _Pragma("unroll")                                                 \
            for (int i = 0; i < 8; ++i) {                                     \
                int row = (tid >> 3) + i * 32;                                \
                const char* sbp = (lplane ? pBm : pBh) + (size_t)row * (KK*2) + kb;\
                cp16(sbs + ATILE + doff0 + i * (32*SROW), sbp);               \
            }                                                                 \
        }                                                                     \
        CP_COMMIT();                                                          \
    } while (0)

    float acc[4][8][4];
    #pragma unroll
    for (int i = 0; i < 4; ++i)
        #pragma unroll
        for (int j = 0; j < 8; ++j)
            #pragma unroll
            for (int r = 0; r < 4; ++r) acc[i][j][r] = 0.f;

    const int arow = lane & 15;
    const int akoff = (lane >> 4) * 16;
    constexpr int NPL = (MODE == 0) ? 2 : 1;

    LOAD_CHUNK(0, 0);
    LOAD_CHUNK(1, 1);

    for (int kc = 0; kc < GNKCH; ++kc) {
        int st = kc - (kc / 3) * 3;
        if (kc + 1 < GNKCH) { CP_WAIT(1); } else { CP_WAIT(0); }
        __syncthreads();
        if (kc + 2 < GNKCH) {
            int st2 = (kc + 2) - ((kc + 2) / 3) * 3;
            LOAD_CHUNK(kc + 2, st2);
        }

        uint32_t sA = sbase + st * GSTAGE;
        uint32_t sB = sA + ATILE;

        #pragma unroll
        for (int ks = 0; ks < 2; ++ks) {
            uint32_t a[NPL][4][4];
            #pragma unroll
            for (int pl = 0; pl < NPL; ++pl)
                #pragma unroll
                for (int fm = 0; fm < 4; ++fm) {
                    uint32_t ad = sA + (wm*64 + fm*16 + arow) * SROW
                                + pl*64 + ks*32 + akoff;
                    LDM4(a[pl][fm][0], a[pl][fm][1], a[pl][fm][2], a[pl][fm][3], ad);
                }
            uint32_t b[2][8][2];
            #pragma unroll
            for (int pr = 0; pr < 4; ++pr) {
                uint32_t bd = sB + (wn*64 + (pr*2 + (lm >> 1))*8 + l8) * SROW
                            + ks*32 + (lm & 1)*16;
                LDM4(b[0][pr*2][0], b[0][pr*2][1],
                     b[0][pr*2+1][0], b[0][pr*2+1][1], bd);
            }
            if (useBmid) {
                #pragma unroll
                for (int pr = 0; pr < 4; ++pr) {
                    uint32_t bd = sB + (wn*64 + (pr*2 + (lm >> 1))*8 + l8) * SROW
                                + 64 + ks*32 + (lm & 1)*16;
                    LDM4(b[1][pr*2][0], b[1][pr*2][1],
                         b[1][pr*2+1][0], b[1][pr*2+1][1], bd);
                }
            }
            #pragma unroll
            for (int fm = 0; fm < 4; ++fm)
                #pragma unroll
                for (int fn = 0; fn < 8; ++fn) {
                    MMA16816(acc[fm][fn], a[0][fm], b[0][fn]);
                    if (useBmid) MMA16816(acc[fm][fn], a[0][fm], b[1][fn]);
                    if (MODE == 0) MMA16816(acc[fm][fn], a[NPL-1][fm], b[0][fn]);
                }
        }
        __syncthreads();
    }

    float alpha = *alphap;
    float scl = powf(sqrtf(outf) / logf(1.f + outf), alpha);
    int g = lane >> 2;
    int t2 = (lane & 3) * 2;

    #pragma unroll
    for (int fm = 0; fm < 4; ++fm) {
        int mA = m0 + wm*64 + fm*16 + g;
        float xsA = xsq[mA];
        float xsB = xsq[mA + 8];
        #pragma unroll
        for (int fn = 0; fn < 8; ++fn) {
            int col = n0 + wn*64 + fn*8 + t2;
            float k0v = ksq[col], k1v = ksq[col+1];
            float b0v = bias[col], b1v = bias[col+1];
            float d0 = acc[fm][fn][0], d1 = acc[fm][fn][1];
            float d2 = acc[fm][fn][2], d3 = acc[fm][fn][3];
            acc[fm][fn][0] = d0*d0 / (xsA + k0v - 2.f*d0 + EPSY) * scl + b0v;
            acc[fm][fn][1] = d1*d1 / (xsA + k1v - 2.f*d1 + EPSY) * scl + b1v;
            acc[fm][fn][2] = d2*d2 / (xsB + k0v - 2.f*d2 + EPSY) * scl + b0v;
            acc[fm][fn][3] = d3*d3 / (xsB + k1v - 2.f*d3 + EPSY) * scl + b1v;
        }
        if (MODE == 0) {
            #pragma unroll
            for (int fn = 0; fn < 8; ++fn) {
                int col = n0 + wn*64 + fn*8 + t2;
                *(float2*)(out + (size_t)mA * N + col)
                    = make_float2(acc[fm][fn][0], acc[fm][fn][1]);
                *(float2*)(out + (size_t)(mA+8) * N + col)
                    = make_float2(acc[fm][fn][2], acc[fm][fn][3]);
            }
        } else {
            int hloc = ((n0 & 1023) + wn*64) >> 6;
            float qs = (region == 0) ? 0.125f : 1.f;
            #pragma unroll
            for (int half = 0; half < 2; ++half) {
                int mrow = mA + half*8;
                int t = mrow & (TT-1);
                int b = mrow >> 11;
                if (region < 2) {
                    __nv_bfloat16* P = (region == 0) ? Qp : Kp;
                    size_t rowo = ((size_t)(b*HH + hloc) * TT + t) * 64;
                    #pragma unroll
                    for (int fn = 0; fn < 4; ++fn) {
                        int dd = fn*8 + t2;
                        float4 sc = *(const float4*)(tbl + (t*32 + dd));
                        float x1a = acc[fm][fn][half*2]     * qs;
                        float x1b = acc[fm][fn][half*2+1]   * qs;
                        float x2a = acc[fm][fn+4][half*2]   * qs;
                        float x2b = acc[fm][fn+4][half*2+1] * qs;
                        float r0a = x1a*sc.y - x2a*sc.x, r0b = x1b*sc.w - x2b*sc.z;
                        float r1a = x2a*sc.y + x1a*sc.x, r1b = x2b*sc.w + x1b*sc.z;
                        *(uint32_t*)((char*)P + (rowo + dd) * 2)      = pack_bf16x2(r0b, r0a);
                        *(uint32_t*)((char*)P + (rowo + dd + 32) * 2) = pack_bf16x2(r1b, r1a);
                    }
                } else {
                    size_t rowo = ((size_t)(b*HH + hloc) * TT + t) * 128;
                    #pragma unroll
                    for (int fn = 0; fn < 8; ++fn)
                        store_pair(Vp, rowo, fn*8 + t2,
                                   acc[fm][fn][half*2], acc[fm][fn][half*2+1]);
                }
            }
        }
    }
    #undef LOAD_CHUNK
}

// ------------------------- flash attention (persistent, mma.sync) ----------
// BQ=128, BK=128. Q/K hi-only rows 128B (+16 pad = 144). V rows [hi|mid] 272B.
// QK: 1 MMA combo. PV: 2 combos. Softmax denominator l computed ON the tensor
// core: one MMA per k2 against a constant all-ones b-frag sums the SAME
// bf16-rounded p values the PV MMA consumes (exact weighted mean; no shfl).
// Fixed m=0 (logits provably bounded for this problem).
#define FQ 128
#define QROWK 144
#define VROW 272
#define SQ_SZ (128*QROWK)                // 18432
#define SK_OFF SQ_SZ
#define SK_SZ (128*QROWK)                // 18432
#define SV_OFF (SK_OFF + 2*SK_SZ)        // 55296
#define SV_SZ (128*VROW)                 // 34816
#define FSMEM (SV_OFF + 2*SV_SZ)         // 124928
#define NPERS 148

__global__ __launch_bounds__(256, 1)
void flash_mma_kernel(const __nv_bfloat16* __restrict__ Qp,
                      const __nv_bfloat16* __restrict__ Kp,
                      const __nv_bfloat16* __restrict__ Vp,
                      __nv_bfloat16* __restrict__ OH,
                      __nv_bfloat16* __restrict__ OM,
                      float* __restrict__ xsq2,
                      int* __restrict__ fctr) {
    extern __shared__ char smf[];
    __shared__ int s_task;
    uint32_t sb = smem_u32(smf);
    int tid = threadIdx.x;
    int lane = tid & 31, wq = tid >> 5;
    const int l8 = lane & 7, lm = lane >> 3;
    const int g = lane >> 2, cq = lane & 3;
    const uint32_t onesf[2] = {0x3F803F80u, 0x3F803F80u};   // bf16 1.0 x4

    for (;;) {
        if (tid == 0) s_task = atomicAdd(fctr, 1);
        __syncthreads();
        int task = s_task;
        if (task >= NTASK) return;
        int qi = (TT/FQ) - 1 - (task >> 5);   // descending work (LPT)
        int bh = task & 31;
        int q0 = qi * FQ;
        const char* Qg = (const char*)(Qp + ((size_t)bh * TT + q0) * 64);
        const char* Kg = (const char*)(Kp + (size_t)bh * TT * 64);
        const char* Vg = (const char*)(Vp + (size_t)bh * TT * 128);

        // Q tile (hi only) + K0 + V0 -> stage 0
        #pragma unroll
        for (int i = 0; i < 4; ++i) {
            int idx = tid + i * 256; int r = idx >> 3, ch = idx & 7;
            cp16(sb + r * QROWK + ch * 16, Qg + (size_t)r * 128 + ch * 16);
        }
        #pragma unroll
        for (int i = 0; i < 4; ++i) {
            int idx = tid + i * 256; int r = idx >> 3, ch = idx & 7;
            cp16(sb + SK_OFF + r * QROWK + ch * 16, Kg + (size_t)r * 128 + ch * 16);
        }
        #pragma unroll
        for (int i = 0; i < 8; ++i) {
            int idx = tid + i * 256; int r = idx >> 4, ch = idx & 15;
            cp16(sb + SV_OFF + r * VROW + ch * 16, Vg + (size_t)r * 256 + ch * 16);
        }
        CP_COMMIT();

        float oacc[8][4];
        #pragma unroll
        for (int fo = 0; fo < 8; ++fo)
            #pragma unroll
            for (int r = 0; r < 4; ++r) oacc[fo][r] = 0.f;
        float lacc[4] = {0.f, 0.f, 0.f, 0.f};
        uint32_t qa[4][4];
        const int nkt = qi + 1;

        for (int kt = 0; kt < nkt; ++kt) {
            int st = kt & 1;
            CP_WAIT(0);
            __syncthreads();
            if (kt + 1 < nkt) {
                int sn = st ^ 1, k0n = (kt + 1) * FQ;
                #pragma unroll
                for (int i = 0; i < 4; ++i) {
                    int idx = tid + i * 256; int r = idx >> 3, ch = idx & 7;
                    cp16(sb + SK_OFF + sn * SK_SZ + r * QROWK + ch * 16,
                         Kg + (size_t)(k0n + r) * 128 + ch * 16);
                }
                #pragma unroll
                for (int i = 0; i < 8; ++i) {
                    int idx = tid + i * 256; int r = idx >> 4, ch = idx & 15;
                    cp16(sb + SV_OFF + sn * SV_SZ + r * VROW + ch * 16,
                         Vg + (size_t)(k0n + r) * 256 + ch * 16);
                }
                CP_COMMIT();
            }

            if (kt == 0) {
                #pragma unroll
                for (int ks = 0; ks < 4; ++ks) {
                    uint32_t ad = sb + (wq * 16 + (lane & 15)) * QROWK
                                + ks * 32 + (lane >> 4) * 16;
                    LDM4(qa[ks][0], qa[ks][1], qa[ks][2], qa[ks][3], ad);
                }
            }

            uint32_t sKb = sb + SK_OFF + st * SK_SZ;
            uint32_t sVb = sb + SV_OFF + st * SV_SZ;
            bool diag = (kt == nkt - 1);
            const int fnmax = diag ? (2*wq + 2) : 16;
            const int k2max = diag ? (wq + 1) : 8;

            // ---- S = Q K^T, single combo ------------------------------------
            float sacc[16][4];
            #pragma unroll
            for (int fn = 0; fn < 16; ++fn)
                #pragma unroll
                for (int r = 0; r < 4; ++r) sacc[fn][r] = 0.f;

            #pragma unroll
            for (int ks = 0; ks < 4; ++ks) {
                #pragma unroll
                for (int half = 0; half < 2; ++half) {
                    if (half*8 >= fnmax) break;
                    uint32_t kh[8][2];
                    #pragma unroll
                    for (int pr = 0; pr < 4; ++pr) {
                        if (half*8 + pr*2 >= fnmax) break;
                        uint32_t base = sKb
                            + (half*64 + (pr*2 + (lm >> 1))*8 + l8) * QROWK
                            + ks*32 + (lm & 1)*16;
                        LDM4(kh[pr*2][0], kh[pr*2][1], kh[pr*2+1][0], kh[pr*2+1][1], base);
                    }
                    #pragma unroll
                    for (int f = 0; f < 8; ++f) {
                        if (half*8 + f >= fnmax) break;
                        MMA16816(sacc[half*8 + f], qa[ks], kh[f]);
                    }
                }
            }

            // ---- mask + softmax (fixed m=0) ----------------------------------
            int k0 = kt * FQ;
            int r0q = q0 + wq * 16 + g;
            if (diag) {
                #pragma unroll
                for (int fn = 0; fn < 16; ++fn) {
                    int col = k0 + fn * 8 + 2 * cq;
                    if (col     > r0q)     sacc[fn][0] = -1e30f;
                    if (col + 1 > r0q)     sacc[fn][1] = -1e30f;
                    if (col     > r0q + 8) sacc[fn][2] = -1e30f;
                    if (col + 1 > r0q + 8) sacc[fn][3] = -1e30f;
                }
            }

            uint32_t pah[8][4];
            #pragma unroll
            for (int k2 = 0; k2 < 8; ++k2) {
                #pragma unroll
                for (int half = 0; half < 2; ++half) {
                    int fn = k2 * 2 + half;
                    float p0 = __expf(sacc[fn][0]);
                    float p1 = __expf(sacc[fn][1]);
                    float p2 = __expf(sacc[fn][2]);
                    float p3 = __expf(sacc[fn][3]);
                    pah[k2][half*2+0] = pack_bf16x2(p1, p0);
                    pah[k2][half*2+1] = pack_bf16x2(p3, p2);
                }
            }

            // ---- O += P V; l += P @ ones (tensor-core row-sum) ---------------
            #pragma unroll
            for (int k2 = 0; k2 < 8; ++k2) {
                if (k2 >= k2max) break;
                MMA16816(lacc, pah[k2], onesf);
                uint32_t vh[8][2], vm[8][2];
                #pragma unroll
                for (int pr = 0; pr < 4; ++pr) {
                    uint32_t base = sVb + (k2*16 + (lm & 1)*8 + l8) * VROW
                                  + (pr*2 + (lm >> 1)) * 16;
                    LDM4T(vh[pr*2][0], vh[pr*2][1], vh[pr*2+1][0], vh[pr*2+1][1], base);
                    LDM4T(vm[pr*2][0], vm[pr*2][1], vm[pr*2+1][0], vm[pr*2+1][1],
                          base + 128);
                }
                #pragma unroll
                for (int fo = 0; fo < 8; ++fo) {
                    MMA16816(oacc[fo], pah[k2], vh[fo]);
                    MMA16816(oacc[fo], pah[k2], vm[fo]);
                }
            }
        }

        // ---- fused epilogue: bf16 split planes + atomic row-sumsq -----------
        float inv0 = 1.f / lacc[0], inv1 = 1.f / lacc[2];
        int b = bh >> 4, h = bh & 15;
        int r0q = q0 + wq * 16 + g;
        size_t row0 = (size_t)(b * TT + r0q);
        float s0 = 0.f, s1 = 0.f;
        #pragma unroll
        for (int fo = 0; fo < 8; ++fo) {
            int col = h * 64 + fo * 8 + 2 * cq;
            float w00 = oacc[fo][0] * inv0, w01 = oacc[fo][1] * inv0;
            float w10 = oacc[fo][2] * inv1, w11 = oacc[fo][3] * inv1;
            s0 += w00*w00 + w01*w01;
            s1 += w10*w10 + w11*w11;
            float h00 = __bfloat162float(__float2bfloat16(w00));
            float h01 = __bfloat162float(__float2bfloat16(w01));
            float h10 = __bfloat162float(__float2bfloat16(w10));
            float h11 = __bfloat162float(__float2bfloat16(w11));
            *(uint32_t*)((char*)OH + (row0 * KK + col) * 2) = pack_bf16x2(w01, w00);
            *(uint32_t*)((char*)OM + (row0 * KK + col) * 2) = pack_bf16x2(w01 - h01, w00 - h00);
            *(uint32_t*)((char*)OH + ((row0 + 8) * KK + col) * 2) = pack_bf16x2(w11, w10);
            *(uint32_t*)((char*)OM + ((row0 + 8) * KK + col) * 2) = pack_bf16x2(w11 - h11, w10 - h10);
        }
        s0 += __shfl_xor_sync(0xffffffffu, s0, 1);
        s0 += __shfl_xor_sync(0xffffffffu, s0, 2);
        s1 += __shfl_xor_sync(0xffffffffu, s1, 1);
        s1 += __shfl_xor_sync(0xffffffffu, s1, 2);
        if (cq == 0) {
            atomicAdd(&xsq2[row0], s0);
            atomicAdd(&xsq2[row0 + 8], s1);
        }
        // reset l accumulators for next task
        lacc[0] = 0.f; lacc[1] = 0.f; lacc[2] = 0.f; lacc[3] = 0.f;
    }
}

// ------------------------- host launch --------------------------------------
extern "C" void kernel_launch(void* const* d_in, const int* in_sizes, int n_in,
                              void* d_out, int out_size) {
    const float* x      = (const float*)d_in[0];
    const float* w_attn = (const float*)d_in[2];
    const float* b_attn = (const float*)d_in[3];
    const float* a_attn = (const float*)d_in[4];
    const float* w_proj = (const float*)d_in[5];
    const float* b_proj = (const float*)d_in[6];
    const float* a_proj = (const float*)d_in[7];
    float* out = (float*)d_out;

    void *xsq_, *xsq2_, *ksqa_, *ksqp_, *tbl_, *fctr_;
    void *ah_, *am_, *bha_, *bma_, *bhp_, *bmp_, *qp_, *kp_, *vp_;
    cudaGetSymbolAddress(&xsq_,  g_xsq);
    cudaGetSymbolAddress(&xsq2_, g_xsq2);
    cudaGetSymbolAddress(&ksqa_, g_ksqA);
    cudaGetSymbolAddress(&ksqp_, g_ksqP);
    cudaGetSymbolAddress(&tbl_,  g_tbl);
    cudaGetSymbolAddress(&fctr_, g_fctr);
    cudaGetSymbolAddress(&ah_,   g_Ah);
    cudaGetSymbolAddress(&am_,   g_Am);
    cudaGetSymbolAddress(&bha_,  g_BhA);
    cudaGetSymbolAddress(&bma_,  g_BmA);
    cudaGetSymbolAddress(&bhp_,  g_BhP);
    cudaGetSymbolAddress(&bmp_,  g_BmP);
    cudaGetSymbolAddress(&qp_,   g_Qp);
    cudaGetSymbolAddress(&kp_,   g_Kp);
    cudaGetSymbolAddress(&vp_,   g_Vp);
    float* xsq  = (float*)xsq_;
    float* xsq2 = (float*)xsq2_;
    float* ksqa = (float*)ksqa_;
    float* ksqp = (float*)ksqp_;
    float2* tbl = (float2*)tbl_;
    int* fctr   = (int*)fctr_;
    __nv_bfloat16* Ah  = (__nv_bfloat16*)ah_;
    __nv_bfloat16* Am  = (__nv_bfloat16*)am_;
    __nv_bfloat16* BhA = (__nv_bfloat16*)bha_;
    __nv_bfloat16* BmA = (__nv_bfloat16*)bma_;
    __nv_bfloat16* BhP = (__nv_bfloat16*)bhp_;
    __nv_bfloat16* BmP = (__nv_bfloat16*)bmp_;
    __nv_bfloat16* Qp  = (__nv_bfloat16*)qp_;
    __nv_bfloat16* Kp  = (__nv_bfloat16*)kp_;
    __nv_bfloat16* Vp  = (__nv_bfloat16*)vp_;

    const int gemm_smem = 3 * GSTAGE;                        // 165888
    cudaFuncSetAttribute(gemm_mma_kernel<0>,
                         cudaFuncAttributeMaxDynamicSharedMemorySize, gemm_smem);
    cudaFuncSetAttribute(gemm_mma_kernel<1>,
                         cudaFuncAttributeMaxDynamicSharedMemorySize, gemm_smem);
    cudaFuncSetAttribute(flash_mma_kernel,
                         cudaFuncAttributeMaxDynamicSharedMemorySize, FSMEM);

    // zero accumulators + task counter + rope table
    prep_kernel<<<256, 256>>>(ksqa, ksqp, xsq2, tbl, fctr);

    // merged: x split+rowsq, w_attn transpose+colsq, w_proj transpose+colsq
    prep2_kernel<<<MM + 3072 + 1024, 256>>>(x, Ah, Am, xsq,
                                            w_attn, BhA, BmA, ksqa,
                                            w_proj, BhP, BmP, ksqp);

    // GEMM1 (Q/K 1 combo, V 2 combos; heavy-first 1D grid) -> Qp/Kp/Vp
    gemm_mma_kernel<1><<<384, 256, gemm_smem>>>(Ah, Am, BhA, BmA, b_attn, xsq,
                                                ksqa, a_attn, nullptr, N_QKV,
                                                (float)N_QKV, Qp, Kp, Vp, tbl);

    // persistent flash attention (QK 1 combo, PV 2 combos, l via MMA) -> Ah/Am
    flash_mma_kernel<<<NPERS, 256, FSMEM>>>(Qp, Kp, Vp, Ah, Am, xsq2, fctr);

    // GEMM2 (3 combos) + YAT -> out
    {
        dim3 grid(CC / 256, MM / 128);
        gemm_mma_kernel<0><<<grid, 256, gemm_smem>>>(Ah, Am, BhP, BmP, b_proj, xsq2,
                                                     ksqp, a_proj, out, CC,
                                                     (float)CC, nullptr, nullptr,
                                                     nullptr, nullptr);
    }
}

// round 14
// speedup vs baseline: 1.3797x; 1.1730x over previous
#include <cuda_runtime.h>
#include <cuda_bf16.h>
#include <math.h>
#include <stdint.h>

// Problem constants
#define BB 2
#define TT 2048
#define CC 1024
#define HH 16
#define DD 64
#define MM (BB*TT)          // 4096
#define N_QKV (3*CC)        // 3072
#define KK CC               // GEMM K = 1024
#define BH (BB*HH)          // 32
#define EPSY 1e-6f
#define NTASK (BH * (TT/128))   // 512 flash tasks

// ------------------------- scratch (device globals) -----------------------
__device__ float g_xsq[MM];
__device__ float g_xsq2[MM];
__device__ float g_ksqA[N_QKV];
__device__ float g_ksqP[CC];
__device__ float2 g_tbl[TT * 32];
__device__ int g_fctr;
__device__ __nv_bfloat16 g_Ah[(size_t)MM * KK];
__device__ __nv_bfloat16 g_Am[(size_t)MM * KK];
__device__ __nv_bfloat16 g_BhA[(size_t)N_QKV * KK];
__device__ __nv_bfloat16 g_BhP[(size_t)CC * KK];
__device__ __nv_bfloat16 g_BmP[(size_t)CC * KK];
// flash operands: Qp/Kp hi-only [bh][t][64] bf16; Vp [bh][t][hi64|mid64]
__device__ __nv_bfloat16 g_Qp[(size_t)BH * TT * 64];
__device__ __nv_bfloat16 g_Kp[(size_t)BH * TT * 64];
__device__ __nv_bfloat16 g_Vp[(size_t)BH * TT * 128];

// ------------------------- PTX helpers ------------------------------------
__device__ __forceinline__ uint32_t smem_u32(const void* p) {
    uint32_t a;
    asm("{ .reg .u64 t; cvta.to.shared.u64 t, %1; cvt.u32.u64 %0, t; }"
        : "=r"(a) : "l"(p));
    return a;
}
__device__ __forceinline__ void cp16(uint32_t dst, const void* src) {
    asm volatile("cp.async.cg.shared.global [%0], [%1], 16;" :: "r"(dst), "l"(src) : "memory");
}
#define CP_COMMIT() asm volatile("cp.async.commit_group;" ::: "memory")
#define CP_WAIT(n)  asm volatile("cp.async.wait_group %0;" :: "n"(n) : "memory")

#define LDM4(r0, r1, r2, r3, addr) \
    asm volatile("ldmatrix.sync.aligned.m8n8.x4.shared.b16 {%0,%1,%2,%3}, [%4];" \
        : "=r"(r0), "=r"(r1), "=r"(r2), "=r"(r3) : "r"(addr))

#define LDM4T(r0, r1, r2, r3, addr) \
    asm volatile("ldmatrix.sync.aligned.m8n8.x4.trans.shared.b16 {%0,%1,%2,%3}, [%4];" \
        : "=r"(r0), "=r"(r1), "=r"(r2), "=r"(r3) : "r"(addr))

#define MMA16816(d, a, b) \
    asm volatile("mma.sync.aligned.m16n8k16.row.col.f32.bf16.bf16.f32 " \
        "{%0,%1,%2,%3}, {%4,%5,%6,%7}, {%8,%9}, {%0,%1,%2,%3};" \
        : "+f"((d)[0]), "+f"((d)[1]), "+f"((d)[2]), "+f"((d)[3]) \
        : "r"((a)[0]), "r"((a)[1]), "r"((a)[2]), "r"((a)[3]), \
          "r"((b)[0]), "r"((b)[1]))

// packs {hi, lo} fp32 -> bf16x2 (first source is upper half)
__device__ __forceinline__ uint32_t pack_bf16x2(float hi, float lo) {
    uint32_t r;
    asm("cvt.rn.bf16x2.f32 %0, %1, %2;" : "=r"(r) : "f"(hi), "f"(lo));
    return r;
}
// split-store a pair of adjacent cols (d even) into hi/mid planes of one row
__device__ __forceinline__ void store_pair(__nv_bfloat16* P, size_t rowo, int d,
                                           float a, float b) {
    float ha = __bfloat162float(__float2bfloat16(a));
    float hb = __bfloat162float(__float2bfloat16(b));
    *(uint32_t*)((char*)P + (rowo + d) * 2)      = pack_bf16x2(b, a);
    *(uint32_t*)((char*)P + (rowo + 64 + d) * 2) = pack_bf16x2(b - hb, a - ha);
}

// ------------------------- prep: zero accumulators + rope table ------------
__global__ void prep_kernel(float* __restrict__ ksqa, float* __restrict__ ksqp,
                            float* __restrict__ xsq2, float2* __restrict__ tbl,
                            int* __restrict__ fctr) {
    int i = blockIdx.x * 256 + threadIdx.x;        // grid 256 -> 65536 threads
    if (i == 0) *fctr = 0;
    if (i < N_QKV) ksqa[i] = 0.f;
    if (i < CC)    ksqp[i] = 0.f;
    if (i < MM)    xsq2[i] = 0.f;
    int t = i >> 5, dd = i & 31;
    float freq = expf(-9.2103403719761836f * ((float)(2*dd) / 64.f));
    float sn, cs;
    sincosf((float)t * freq, &sn, &cs);
    tbl[i] = make_float2(sn, cs);
}

// ------------------------- merged prep2: x split + both W transposes -------
__global__ void prep2_kernel(const float* __restrict__ x,
                             __nv_bfloat16* __restrict__ Ah,
                             __nv_bfloat16* __restrict__ Am,
                             float* __restrict__ xsq,
                             const float* __restrict__ wA,
                             __nv_bfloat16* __restrict__ BhA,
                             float* __restrict__ ksqa,
                             const float* __restrict__ wP,
                             __nv_bfloat16* __restrict__ BhP,
                             __nv_bfloat16* __restrict__ BmP,
                             float* __restrict__ ksqp) {
    __shared__ float red[8];
    __shared__ float tile[32][33];
    int blk = blockIdx.x, tid = threadIdx.x;
    if (blk < MM) {
        int row = blk;
        size_t i = (size_t)row * 256 + tid;
        float4 v = ((const float4*)x)[i];
        __nv_bfloat16 h0 = __float2bfloat16(v.x);
        __nv_bfloat16 h1 = __float2bfloat16(v.y);
        __nv_bfloat16 h2 = __float2bfloat16(v.z);
        __nv_bfloat16 h3 = __float2bfloat16(v.w);
        __nv_bfloat162* Hp = (__nv_bfloat162*)Ah;
        __nv_bfloat162* Mq = (__nv_bfloat162*)Am;
        Hp[2*i]   = __nv_bfloat162(h0, h1);
        Hp[2*i+1] = __nv_bfloat162(h2, h3);
        Mq[2*i]   = __nv_bfloat162(__float2bfloat16(v.x - __bfloat162float(h0)),
                                   __float2bfloat16(v.y - __bfloat162float(h1)));
        Mq[2*i+1] = __nv_bfloat162(__float2bfloat16(v.z - __bfloat162float(h2)),
                                   __float2bfloat16(v.w - __bfloat162float(h3)));
        float s = v.x*v.x + v.y*v.y + v.z*v.z + v.w*v.w;
        #pragma unroll
        for (int off = 16; off > 0; off >>= 1)
            s += __shfl_xor_sync(0xffffffffu, s, off);
        if ((tid & 31) == 0) red[tid >> 5] = s;
        __syncthreads();
        if (tid == 0) {
            float t = 0.f;
            #pragma unroll
            for (int w = 0; w < 8; ++w) t += red[w];
            xsq[row] = t;
        }
        return;
    }
    const float* W; __nv_bfloat16 *Bh, *Bm; float* ksq; int N, n0, k0;
    if (blk < MM + 3072) {
        int b2 = blk - MM;
        W = wA; Bh = BhA; Bm = nullptr; ksq = ksqa; N = N_QKV;
        n0 = (b2 % 96) * 32; k0 = (b2 / 96) * 32;
    } else {
        int b2 = blk - MM - 3072;
        W = wP; Bh = BhP; Bm = BmP; ksq = ksqp; N = CC;
        n0 = (b2 % 32) * 32; k0 = (b2 / 32) * 32;
    }
    int tx = tid & 31, ty = tid >> 5;
    for (int j = ty; j < 32; j += 8)
        tile[j][tx] = W[(size_t)(k0 + j) * N + n0 + tx];
    __syncthreads();
    for (int j = ty; j < 32; j += 8) {
        float v = tile[tx][j];
        __nv_bfloat16 h = __float2bfloat16(v);
        size_t o = (size_t)(n0 + j) * KK + k0 + tx;
        Bh[o] = h;
        if (Bm) Bm[o] = __float2bfloat16(v - __bfloat162float(h));
        float sq = v * v;
        #pragma unroll
        for (int off = 16; off > 0; off >>= 1)
            sq += __shfl_xor_sync(0xffffffffu, sq, off);
        if (tx == 0) atomicAdd(&ksq[n0 + j], sq);
    }
}

// ------------------------- mma.sync GEMM + YAT epilogue -------------------
// CTA 128(M)x256(N), 8 warps 2x4 -> warp tile 64x64. 3-stage cp.async.
// MODE 0 (GEMM2): 3 MMA combos, YAT -> fp32 out.
// MODE 1 (GEMM1): 1 combo (hh) everywhere (uniform CTAs);
//                 YAT -> RoPE -> Qp/Kp (hi) + Vp split planes.
#define SROW 144
#define ATILE (128*SROW)                 // 18432
#define BTILE (256*SROW)                 // 36864
#define GSTAGE (ATILE + BTILE)           // 55296
#define GNKCH (KK/32)                    // 32

template<int MODE>
__global__ __launch_bounds__(256, 1)
void gemm_mma_kernel(const __nv_bfloat16* __restrict__ Ah, const __nv_bfloat16* __restrict__ Am,
                     const __nv_bfloat16* __restrict__ Bh, const __nv_bfloat16* __restrict__ Bm,
                     const float* __restrict__ bias, const float* __restrict__ xsq,
                     const float* __restrict__ ksq, const float* __restrict__ alphap,
                     float* __restrict__ out, int N, float outf,
                     __nv_bfloat16* __restrict__ Qp, __nv_bfloat16* __restrict__ Kp,
                     __nv_bfloat16* __restrict__ Vp, const float2* __restrict__ tbl) {
    extern __shared__ char dsm[];
    uint32_t sbase = smem_u32(dsm);

    const int tid = threadIdx.x;
    const int lane = tid & 31;
    const int wid = tid >> 5;
    const int wm = wid >> 2;
    const int wn = wid & 3;
    int m0, n0;
    if (MODE == 1) {
        int id = blockIdx.x;
        n0 = (id % 12) * 256;
        m0 = (id / 12) * 128;
    } else {
        m0 = blockIdx.y * 128;
        n0 = blockIdx.x * 256;
    }
    const int l8 = lane & 7;
    const int lm = lane >> 3;
    const int region = (MODE == 1) ? (n0 >> 10) : 2;

    const char* pAh = (const char*)Ah + (size_t)m0 * (KK*2);
    const char* pAm = (const char*)Am + (size_t)m0 * (KK*2);
    const char* pBh = (const char*)Bh + (size_t)n0 * (KK*2);
    const char* pBm = (MODE == 0) ? ((const char*)Bm + (size_t)n0 * (KK*2)) : pBh;

    const int lplane = (tid >> 2) & 1;
    const int lchunk = tid & 3;

    #define LOAD_CHUNK(kc, st) do {                                           \
        size_t kb = (size_t)(kc) * 64 + (size_t)lchunk * 16;                  \
        uint32_t sbs = sbase + (st) * GSTAGE;                                 \
        uint32_t doff0 = (tid >> 3) * SROW + lplane * 64 + lchunk * 16;       \
        if (MODE == 0 || lplane == 0) {                                       \
            _Pragma("unroll")                                                 \
            for (int i = 0; i < 4; ++i) {                                     \
                int row = (tid >> 3) + i * 32;                                \
                const char* sa = (lplane ? pAm : pAh) + (size_t)row * (KK*2) + kb;\
                cp16(sbs + doff0 + i * (32*SROW), sa);                        \
            }                                                                 \
            _Pragma("unroll")                                                 \
            for (int i = 0; i < 8; ++i) {                                     \
                int row = (tid >> 3) + i * 32;                                \
                const char* sbp = (lplane ? pBm : pBh) + (size_t)row * (KK*2) + kb;\
                cp16(sbs + ATILE + doff0 + i * (32*SROW), sbp);               \
            }                                                                 \
        }                                                                     \
        CP_COMMIT();                                                          \
    } while (0)

    float acc[4][8][4];
    #pragma unroll
    for (int i = 0; i < 4; ++i)
        #pragma unroll
        for (int j = 0; j < 8; ++j)
            #pragma unroll
            for (int r = 0; r < 4; ++r) acc[i][j][r] = 0.f;

    const int arow = lane & 15;
    const int akoff = (lane >> 4) * 16;
    constexpr int NPL = (MODE == 0) ? 2 : 1;

    LOAD_CHUNK(0, 0);
    LOAD_CHUNK(1, 1);

    for (int kc = 0; kc < GNKCH; ++kc) {
        int st = kc - (kc / 3) * 3;
        if (kc + 1 < GNKCH) { CP_WAIT(1); } else { CP_WAIT(0); }
        __syncthreads();
        if (kc + 2 < GNKCH) {
            int st2 = (kc + 2) - ((kc + 2) / 3) * 3;
            LOAD_CHUNK(kc + 2, st2);
        }

        uint32_t sA = sbase + st * GSTAGE;
        uint32_t sB = sA + ATILE;

        #pragma unroll
        for (int ks = 0; ks < 2; ++ks) {
            uint32_t a[NPL][4][4];
            #pragma unroll
            for (int pl = 0; pl < NPL; ++pl)
                #pragma unroll
                for (int fm = 0; fm < 4; ++fm) {
                    uint32_t ad = sA + (wm*64 + fm*16 + arow) * SROW
                                + pl*64 + ks*32 + akoff;
                    LDM4(a[pl][fm][0], a[pl][fm][1], a[pl][fm][2], a[pl][fm][3], ad);
                }
            uint32_t b[2][8][2];
            #pragma unroll
            for (int pr = 0; pr < 4; ++pr) {
                uint32_t bd = sB + (wn*64 + (pr*2 + (lm >> 1))*8 + l8) * SROW
                            + ks*32 + (lm & 1)*16;
                LDM4(b[0][pr*2][0], b[0][pr*2][1],
                     b[0][pr*2+1][0], b[0][pr*2+1][1], bd);
            }
            if (MODE == 0) {
                #pragma unroll
                for (int pr = 0; pr < 4; ++pr) {
                    uint32_t bd = sB + (wn*64 + (pr*2 + (lm >> 1))*8 + l8) * SROW
                                + 64 + ks*32 + (lm & 1)*16;
                    LDM4(b[1][pr*2][0], b[1][pr*2][1],
                         b[1][pr*2+1][0], b[1][pr*2+1][1], bd);
                }
            }
            #pragma unroll
            for (int fm = 0; fm < 4; ++fm)
                #pragma unroll
                for (int fn = 0; fn < 8; ++fn) {
                    MMA16816(acc[fm][fn], a[0][fm], b[0][fn]);
                    if (MODE == 0) {
                        MMA16816(acc[fm][fn], a[0][fm], b[1][fn]);
                        MMA16816(acc[fm][fn], a[NPL-1][fm], b[0][fn]);
                    }
                }
        }
        __syncthreads();
    }

    float alpha = *alphap;
    float scl = powf(sqrtf(outf) / logf(1.f + outf), alpha);
    int g = lane >> 2;
    int t2 = (lane & 3) * 2;

    #pragma unroll
    for (int fm = 0; fm < 4; ++fm) {
        int mA = m0 + wm*64 + fm*16 + g;
        float xsA = xsq[mA];
        float xsB = xsq[mA + 8];
        #pragma unroll
        for (int fn = 0; fn < 8; ++fn) {
            int col = n0 + wn*64 + fn*8 + t2;
            float k0v = ksq[col], k1v = ksq[col+1];
            float b0v = bias[col], b1v = bias[col+1];
            float d0 = acc[fm][fn][0], d1 = acc[fm][fn][1];
            float d2 = acc[fm][fn][2], d3 = acc[fm][fn][3];
            acc[fm][fn][0] = d0*d0 / (xsA + k0v - 2.f*d0 + EPSY) * scl + b0v;
            acc[fm][fn][1] = d1*d1 / (xsA + k1v - 2.f*d1 + EPSY) * scl + b1v;
            acc[fm][fn][2] = d2*d2 / (xsB + k0v - 2.f*d2 + EPSY) * scl + b0v;
            acc[fm][fn][3] = d3*d3 / (xsB + k1v - 2.f*d3 + EPSY) * scl + b1v;
        }
        if (MODE == 0) {
            #pragma unroll
            for (int fn = 0; fn < 8; ++fn) {
                int col = n0 + wn*64 + fn*8 + t2;
                *(float2*)(out + (size_t)mA * N + col)
                    = make_float2(acc[fm][fn][0], acc[fm][fn][1]);
                *(float2*)(out + (size_t)(mA+8) * N + col)
                    = make_float2(acc[fm][fn][2], acc[fm][fn][3]);
            }
        } else {
            int hloc = ((n0 & 1023) + wn*64) >> 6;
            float qs = (region == 0) ? 0.125f : 1.f;
            #pragma unroll
            for (int half = 0; half < 2; ++half) {
                int mrow = mA + half*8;
                int t = mrow & (TT-1);
                int b = mrow >> 11;
                if (region < 2) {
                    __nv_bfloat16* P = (region == 0) ? Qp : Kp;
                    size_t rowo = ((size_t)(b*HH + hloc) * TT + t) * 64;
                    #pragma unroll
                    for (int fn = 0; fn < 4; ++fn) {
                        int dd = fn*8 + t2;
                        float4 sc = *(const float4*)(tbl + (t*32 + dd));
                        float x1a = acc[fm][fn][half*2]     * qs;
                        float x1b = acc[fm][fn][half*2+1]   * qs;
                        float x2a = acc[fm][fn+4][half*2]   * qs;
                        float x2b = acc[fm][fn+4][half*2+1] * qs;
                        float r0a = x1a*sc.y - x2a*sc.x, r0b = x1b*sc.w - x2b*sc.z;
                        float r1a = x2a*sc.y + x1a*sc.x, r1b = x2b*sc.w + x1b*sc.z;
                        *(uint32_t*)((char*)P + (rowo + dd) * 2)      = pack_bf16x2(r0b, r0a);
                        *(uint32_t*)((char*)P + (rowo + dd + 32) * 2) = pack_bf16x2(r1b, r1a);
                    }
                } else {
                    size_t rowo = ((size_t)(b*HH + hloc) * TT + t) * 128;
                    #pragma unroll
                    for (int fn = 0; fn < 8; ++fn)
                        store_pair(Vp, rowo, fn*8 + t2,
                                   acc[fm][fn][half*2], acc[fm][fn][half*2+1]);
                }
            }
        }
    }
    #undef LOAD_CHUNK
}

// ------------------------- flash attention (persistent, mma.sync) ----------
// BQ=128, BK=128. Q/K hi-only rows 128B (+16 pad = 144). V rows [hi|mid] 272B.
// QK: 1 MMA combo. PV: 2 combos. l computed ON the tensor core (P @ ones).
// Fixed m=0 (logits provably bounded for this problem).
#define FQ 128
#define QROWK 144
#define VROW 272
#define SQ_SZ (128*QROWK)                // 18432
#define SK_OFF SQ_SZ
#define SK_SZ (128*QROWK)                // 18432
#define SV_OFF (SK_OFF + 2*SK_SZ)        // 55296
#define SV_SZ (128*VROW)                 // 34816
#define FSMEM (SV_OFF + 2*SV_SZ)         // 124928
#define NPERS 148

__global__ __launch_bounds__(256, 1)
void flash_mma_kernel(const __nv_bfloat16* __restrict__ Qp,
                      const __nv_bfloat16* __restrict__ Kp,
                      const __nv_bfloat16* __restrict__ Vp,
                      __nv_bfloat16* __restrict__ OH,
                      __nv_bfloat16* __restrict__ OM,
                      float* __restrict__ xsq2,
                      int* __restrict__ fctr) {
    extern __shared__ char smf[];
    __shared__ int s_task;
    uint32_t sb = smem_u32(smf);
    int tid = threadIdx.x;
    int lane = tid & 31, wq = tid >> 5;
    const int l8 = lane & 7, lm = lane >> 3;
    const int g = lane >> 2, cq = lane & 3;
    const uint32_t onesf[2] = {0x3F803F80u, 0x3F803F80u};   // bf16 1.0 x4

    for (;;) {
        if (tid == 0) s_task = atomicAdd(fctr, 1);
        __syncthreads();
        int task = s_task;
        if (task >= NTASK) return;
        int qi = (TT/FQ) - 1 - (task >> 5);   // descending work (LPT)
        int bh = task & 31;
        int q0 = qi * FQ;
        const char* Qg = (const char*)(Qp + ((size_t)bh * TT + q0) * 64);
        const char* Kg = (const char*)(Kp + (size_t)bh * TT * 64);
        const char* Vg = (const char*)(Vp + (size_t)bh * TT * 128);

        // Q tile (hi only) + K0 + V0 -> stage 0
        #pragma unroll
        for (int i = 0; i < 4; ++i) {
            int idx = tid + i * 256; int r = idx >> 3, ch = idx & 7;
            cp16(sb + r * QROWK + ch * 16, Qg + (size_t)r * 128 + ch * 16);
        }
        #pragma unroll
        for (int i = 0; i < 4; ++i) {
            int idx = tid + i * 256; int r = idx >> 3, ch = idx & 7;
            cp16(sb + SK_OFF + r * QROWK + ch * 16, Kg + (size_t)r * 128 + ch * 16);
        }
        #pragma unroll
        for (int i = 0; i < 8; ++i) {
            int idx = tid + i * 256; int r = idx >> 4, ch = idx & 15;
            cp16(sb + SV_OFF + r * VROW + ch * 16, Vg + (size_t)r * 256 + ch * 16);
        }
        CP_COMMIT();

        float oacc[8][4];
        #pragma unroll
        for (int fo = 0; fo < 8; ++fo)
            #pragma unroll
            for (int r = 0; r < 4; ++r) oacc[fo][r] = 0.f;
        float lacc[4] = {0.f, 0.f, 0.f, 0.f};
        uint32_t qa[4][4];
        const int nkt = qi + 1;

        for (int kt = 0; kt < nkt; ++kt) {
            int st = kt & 1;
            CP_WAIT(0);
            __syncthreads();
            if (kt + 1 < nkt) {
                int sn = st ^ 1, k0n = (kt + 1) * FQ;
                #pragma unroll
                for (int i = 0; i < 4; ++i) {
                    int idx = tid + i * 256; int r = idx >> 3, ch = idx & 7;
                    cp16(sb + SK_OFF + sn * SK_SZ + r * QROWK + ch * 16,
                         Kg + (size_t)(k0n + r) * 128 + ch * 16);
                }
                #pragma unroll
                for (int i = 0; i < 8; ++i) {
                    int idx = tid + i * 256; int r = idx >> 4, ch = idx & 15;
                    cp16(sb + SV_OFF + sn * SV_SZ + r * VROW + ch * 16,
                         Vg + (size_t)(k0n + r) * 256 + ch * 16);
                }
                CP_COMMIT();
            }

            if (kt == 0) {
                #pragma unroll
                for (int ks = 0; ks < 4; ++ks) {
                    uint32_t ad = sb + (wq * 16 + (lane & 15)) * QROWK
                                + ks * 32 + (lane >> 4) * 16;
                    LDM4(qa[ks][0], qa[ks][1], qa[ks][2], qa[ks][3], ad);
                }
            }

            uint32_t sKb = sb + SK_OFF + st * SK_SZ;
            uint32_t sVb = sb + SV_OFF + st * SV_SZ;
            bool diag = (kt == nkt - 1);
            const int fnmax = diag ? (2*wq + 2) : 16;
            const int k2max = diag ? (wq + 1) : 8;

            // ---- S = Q K^T, single combo ------------------------------------
            float sacc[16][4];
            #pragma unroll
            for (int fn = 0; fn < 16; ++fn)
                #pragma unroll
                for (int r = 0; r < 4; ++r) sacc[fn][r] = 0.f;

            #pragma unroll
            for (int ks = 0; ks < 4; ++ks) {
                #pragma unroll
                for (int half = 0; half < 2; ++half) {
                    if (half*8 >= fnmax) break;
                    uint32_t kh[8][2];
                    #pragma unroll
                    for (int pr = 0; pr < 4; ++pr) {
                        if (half*8 + pr*2 >= fnmax) break;
                        uint32_t base = sKb
                            + (half*64 + (pr*2 + (lm >> 1))*8 + l8) * QROWK
                            + ks*32 + (lm & 1)*16;
                        LDM4(kh[pr*2][0], kh[pr*2][1], kh[pr*2+1][0], kh[pr*2+1][1], base);
                    }
                    #pragma unroll
                    for (int f = 0; f < 8; ++f) {
                        if (half*8 + f >= fnmax) break;
                        MMA16816(sacc[half*8 + f], qa[ks], kh[f]);
                    }
                }
            }

            // ---- mask + softmax (fixed m=0) ----------------------------------
            int k0 = kt * FQ;
            int r0q = q0 + wq * 16 + g;
            if (diag) {
                #pragma unroll
                for (int fn = 0; fn < 16; ++fn) {
                    int col = k0 + fn * 8 + 2 * cq;
                    if (col     > r0q)     sacc[fn][0] = -1e30f;
                    if (col + 1 > r0q)     sacc[fn][1] = -1e30f;
                    if (col     > r0q + 8) sacc[fn][2] = -1e30f;
                    if (col + 1 > r0q + 8) sacc[fn][3] = -1e30f;
                }
            }

            uint32_t pah[8][4];
            #pragma unroll
            for (int k2 = 0; k2 < 8; ++k2) {
                #pragma unroll
                for (int half = 0; half < 2; ++half) {
                    int fn = k2 * 2 + half;
                    float p0 = __expf(sacc[fn][0]);
                    float p1 = __expf(sacc[fn][1]);
                    float p2 = __expf(sacc[fn][2]);
                    float p3 = __expf(sacc[fn][3]);
                    pah[k2][half*2+0] = pack_bf16x2(p1, p0);
                    pah[k2][half*2+1] = pack_bf16x2(p3, p2);
                }
            }

            // ---- O += P V; l += P @ ones (tensor-core row-sum) ---------------
            #pragma unroll
            for (int k2 = 0; k2 < 8; ++k2) {
                if (k2 >= k2max) break;
                MMA16816(lacc, pah[k2], onesf);
                uint32_t vh[8][2], vm[8][2];
                #pragma unroll
                for (int pr = 0; pr < 4; ++pr) {
                    uint32_t base = sVb + (k2*16 + (lm & 1)*8 + l8) * VROW
                                  + (pr*2 + (lm >> 1)) * 16;
                    LDM4T(vh[pr*2][0], vh[pr*2][1], vh[pr*2+1][0], vh[pr*2+1][1], base);
                    LDM4T(vm[pr*2][0], vm[pr*2][1], vm[pr*2+1][0], vm[pr*2+1][1],
                          base + 128);
                }
                #pragma unroll
                for (int fo = 0; fo < 8; ++fo) {
                    MMA16816(oacc[fo], pah[k2], vh[fo]);
                    MMA16816(oacc[fo], pah[k2], vm[fo]);
                }
            }
        }

        // ---- fused epilogue: bf16 split planes + atomic row-sumsq -----------
        float inv0 = 1.f / lacc[0], inv1 = 1.f / lacc[2];
        int b = bh >> 4, h = bh & 15;
        int r0q = q0 + wq * 16 + g;
        size_t row0 = (size_t)(b * TT + r0q);
        float s0 = 0.f, s1 = 0.f;
        #pragma unroll
        for (int fo = 0; fo < 8; ++fo) {
            int col = h * 64 + fo * 8 + 2 * cq;
            float w00 = oacc[fo][0] * inv0, w01 = oacc[fo][1] * inv0;
            float w10 = oacc[fo][2] * inv1, w11 = oacc[fo][3] * inv1;
            s0 += w00*w00 + w01*w01;
            s1 += w10*w10 + w11*w11;
            float h00 = __bfloat162float(__float2bfloat16(w00));
            float h01 = __bfloat162float(__float2bfloat16(w01));
            float h10 = __bfloat162float(__float2bfloat16(w10));
            float h11 = __bfloat162float(__float2bfloat16(w11));
            *(uint32_t*)((char*)OH + (row0 * KK + col) * 2) = pack_bf16x2(w01, w00);
            *(uint32_t*)((char*)OM + (row0 * KK + col) * 2) = pack_bf16x2(w01 - h01, w00 - h00);
            *(uint32_t*)((char*)OH + ((row0 + 8) * KK + col) * 2) = pack_bf16x2(w11, w10);
            *(uint32_t*)((char*)OM + ((row0 + 8) * KK + col) * 2) = pack_bf16x2(w11 - h11, w10 - h10);
        }
        s0 += __shfl_xor_sync(0xffffffffu, s0, 1);
        s0 += __shfl_xor_sync(0xffffffffu, s0, 2);
        s1 += __shfl_xor_sync(0xffffffffu, s1, 1);
        s1 += __shfl_xor_sync(0xffffffffu, s1, 2);
        if (cq == 0) {
            atomicAdd(&xsq2[row0], s0);
            atomicAdd(&xsq2[row0 + 8], s1);
        }
        lacc[0] = 0.f; lacc[1] = 0.f; lacc[2] = 0.f; lacc[3] = 0.f;
    }
}

// ------------------------- host launch --------------------------------------
extern "C" void kernel_launch(void* const* d_in, const int* in_sizes, int n_in,
                              void* d_out, int out_size) {
    const float* x      = (const float*)d_in[0];
    const float* w_attn = (const float*)d_in[2];
    const float* b_attn = (const float*)d_in[3];
    const float* a_attn = (const float*)d_in[4];
    const float* w_proj = (const float*)d_in[5];
    const float* b_proj = (const float*)d_in[6];
    const float* a_proj = (const float*)d_in[7];
    float* out = (float*)d_out;

    void *xsq_, *xsq2_, *ksqa_, *ksqp_, *tbl_, *fctr_;
    void *ah_, *am_, *bha_, *bhp_, *bmp_, *qp_, *kp_, *vp_;
    cudaGetSymbolAddress(&xsq_,  g_xsq);
    cudaGetSymbolAddress(&xsq2_, g_xsq2);
    cudaGetSymbolAddress(&ksqa_, g_ksqA);
    cudaGetSymbolAddress(&ksqp_, g_ksqP);
    cudaGetSymbolAddress(&tbl_,  g_tbl);
    cudaGetSymbolAddress(&fctr_, g_fctr);
    cudaGetSymbolAddress(&ah_,   g_Ah);
    cudaGetSymbolAddress(&am_,   g_Am);
    cudaGetSymbolAddress(&bha_,  g_BhA);
    cudaGetSymbolAddress(&bhp_,  g_BhP);
    cudaGetSymbolAddress(&bmp_,  g_BmP);
    cudaGetSymbolAddress(&qp_,   g_Qp);
    cudaGetSymbolAddress(&kp_,   g_Kp);
    cudaGetSymbolAddress(&vp_,   g_Vp);
    float* xsq  = (float*)xsq_;
    float* xsq2 = (float*)xsq2_;
    float* ksqa = (float*)ksqa_;
    float* ksqp = (float*)ksqp_;
    float2* tbl = (float2*)tbl_;
    int* fctr   = (int*)fctr_;
    __nv_bfloat16* Ah  = (__nv_bfloat16*)ah_;
    __nv_bfloat16* Am  = (__nv_bfloat16*)am_;
    __nv_bfloat16* BhA = (__nv_bfloat16*)bha_;
    __nv_bfloat16* BhP = (__nv_bfloat16*)bhp_;
    __nv_bfloat16* BmP = (__nv_bfloat16*)bmp_;
    __nv_bfloat16* Qp  = (__nv_bfloat16*)qp_;
    __nv_bfloat16* Kp  = (__nv_bfloat16*)kp_;
    __nv_bfloat16* Vp  = (__nv_bfloat16*)vp_;

    const int gemm_smem = 3 * GSTAGE;                        // 165888
    cudaFuncSetAttribute(gemm_mma_kernel<0>,
                         cudaFuncAttributeMaxDynamicSharedMemorySize, gemm_smem);
    cudaFuncSetAttribute(gemm_mma_kernel<1>,
                         cudaFuncAttributeMaxDynamicSharedMemorySize, gemm_smem);
    cudaFuncSetAttribute(flash_mma_kernel,
                         cudaFuncAttributeMaxDynamicSharedMemorySize, FSMEM);

    // zero accumulators + task counter + rope table
    prep_kernel<<<256, 256>>>(ksqa, ksqp, xsq2, tbl, fctr);

    // merged: x split+rowsq, w_attn transpose (hi only)+colsq, w_proj full
    prep2_kernel<<<MM + 3072 + 1024, 256>>>(x, Ah, Am, xsq,
                                            w_attn, BhA, ksqa,
                                            w_proj, BhP, BmP, ksqp);

    // GEMM1 (1 combo everywhere, uniform CTAs) -> Qp/Kp/Vp
    gemm_mma_kernel<1><<<384, 256, gemm_smem>>>(Ah, Am, BhA, nullptr, b_attn, xsq,
                                                ksqa, a_attn, nullptr, N_QKV,
                                                (float)N_QKV, Qp, Kp, Vp, tbl);

    // persistent flash attention (QK 1 combo, PV 2 combos, l via MMA) -> Ah/Am
    flash_mma_kernel<<<NPERS, 256, FSMEM>>>(Qp, Kp, Vp, Ah, Am, xsq2, fctr);

    // GEMM2 (3 combos) + YAT -> out
    {
        dim3 grid(CC / 256, MM / 128);
        gemm_mma_kernel<0><<<grid, 256, gemm_smem>>>(Ah, Am, BhP, BmP, b_proj, xsq2,
                                                     ksqp, a_proj, out, CC,
                                                     (float)CC, nullptr, nullptr,
                                                     nullptr, nullptr);
    }
}

// round 15
// speedup vs baseline: 1.3861x; 1.0046x over previous
#include <cuda_runtime.h>
#include <cuda_bf16.h>
#include <math.h>
#include <stdint.h>

// Problem constants
#define BB 2
#define TT 2048
#define CC 1024
#define HH 16
#define DD 64
#define MM (BB*TT)          // 4096
#define N_QKV (3*CC)        // 3072
#define KK CC               // GEMM K = 1024
#define BH (BB*HH)          // 32
#define EPSY 1e-6f
#define NTASK 512           // flash tasks
#define NTASK2 (NTASK + 128) // + GEMM2 tasks

// ------------------------- scratch (device globals) -----------------------
__device__ float g_xsq[MM];
__device__ float g_xsq2[MM];
__device__ float g_ksqA[N_QKV];
__device__ float g_ksqP[CC];
__device__ float2 g_tbl[TT * 32];
__device__ int g_fctr;
__device__ int g_mcnt[32];
__device__ __nv_bfloat16 g_Ah[(size_t)MM * KK];
__device__ __nv_bfloat16 g_Am[(size_t)MM * KK];
__device__ __nv_bfloat16 g_BhA[(size_t)N_QKV * KK];
__device__ __nv_bfloat16 g_BhP[(size_t)CC * KK];
__device__ __nv_bfloat16 g_BmP[(size_t)CC * KK];
// flash operands: Qp/Kp hi-only [bh][t][64] bf16; Vp [bh][t][hi64|mid64]
__device__ __nv_bfloat16 g_Qp[(size_t)BH * TT * 64];
__device__ __nv_bfloat16 g_Kp[(size_t)BH * TT * 64];
__device__ __nv_bfloat16 g_Vp[(size_t)BH * TT * 128];

// ------------------------- PTX helpers ------------------------------------
__device__ __forceinline__ uint32_t smem_u32(const void* p) {
    uint32_t a;
    asm("{ .reg .u64 t; cvta.to.shared.u64 t, %1; cvt.u32.u64 %0, t; }"
        : "=r"(a) : "l"(p));
    return a;
}
__device__ __forceinline__ void cp16(uint32_t dst, const void* src) {
    asm volatile("cp.async.cg.shared.global [%0], [%1], 16;" :: "r"(dst), "l"(src) : "memory");
}
#define CP_COMMIT() asm volatile("cp.async.commit_group;" ::: "memory")
#define CP_WAIT(n)  asm volatile("cp.async.wait_group %0;" :: "n"(n) : "memory")

#define LDM4(r0, r1, r2, r3, addr) \
    asm volatile("ldmatrix.sync.aligned.m8n8.x4.shared.b16 {%0,%1,%2,%3}, [%4];" \
        : "=r"(r0), "=r"(r1), "=r"(r2), "=r"(r3) : "r"(addr))

#define LDM4T(r0, r1, r2, r3, addr) \
    asm volatile("ldmatrix.sync.aligned.m8n8.x4.trans.shared.b16 {%0,%1,%2,%3}, [%4];" \
        : "=r"(r0), "=r"(r1), "=r"(r2), "=r"(r3) : "r"(addr))

#define MMA16816(d, a, b) \
    asm volatile("mma.sync.aligned.m16n8k16.row.col.f32.bf16.bf16.f32 " \
        "{%0,%1,%2,%3}, {%4,%5,%6,%7}, {%8,%9}, {%0,%1,%2,%3};" \
        : "+f"((d)[0]), "+f"((d)[1]), "+f"((d)[2]), "+f"((d)[3]) \
        : "r"((a)[0]), "r"((a)[1]), "r"((a)[2]), "r"((a)[3]), \
          "r"((b)[0]), "r"((b)[1]))

// packs {hi, lo} fp32 -> bf16x2 (first source is upper half)
__device__ __forceinline__ uint32_t pack_bf16x2(float hi, float lo) {
    uint32_t r;
    asm("cvt.rn.bf16x2.f32 %0, %1, %2;" : "=r"(r) : "f"(hi), "f"(lo));
    return r;
}
// split-store a pair of adjacent cols (d even) into hi/mid planes of one row
__device__ __forceinline__ void store_pair(__nv_bfloat16* P, size_t rowo, int d,
                                           float a, float b) {
    float ha = __bfloat162float(__float2bfloat16(a));
    float hb = __bfloat162float(__float2bfloat16(b));
    *(uint32_t*)((char*)P + (rowo + d) * 2)      = pack_bf16x2(b, a);
    *(uint32_t*)((char*)P + (rowo + 64 + d) * 2) = pack_bf16x2(b - hb, a - ha);
}

// ------------------------- prep: zero accumulators + rope table ------------
__global__ void prep_kernel(float* __restrict__ ksqa, float* __restrict__ ksqp,
                            float* __restrict__ xsq2, float2* __restrict__ tbl,
                            int* __restrict__ fctr, int* __restrict__ mcnt) {
    int i = blockIdx.x * 256 + threadIdx.x;        // grid 256 -> 65536 threads
    if (i == 0) *fctr = 0;
    if (i < 32) mcnt[i] = 0;
    if (i < N_QKV) ksqa[i] = 0.f;
    if (i < CC)    ksqp[i] = 0.f;
    if (i < MM)    xsq2[i] = 0.f;
    int t = i >> 5, dd = i & 31;
    float freq = expf(-9.2103403719761836f * ((float)(2*dd) / 64.f));
    float sn, cs;
    sincosf((float)t * freq, &sn, &cs);
    tbl[i] = make_float2(sn, cs);
}

// ------------------------- merged prep2: x split + both W transposes -------
__global__ void prep2_kernel(const float* __restrict__ x,
                             __nv_bfloat16* __restrict__ Ah,
                             float* __restrict__ xsq,
                             const float* __restrict__ wA,
                             __nv_bfloat16* __restrict__ BhA,
                             float* __restrict__ ksqa,
                             const float* __restrict__ wP,
                             __nv_bfloat16* __restrict__ BhP,
                             __nv_bfloat16* __restrict__ BmP,
                             float* __restrict__ ksqp) {
    __shared__ float red[8];
    __shared__ float tile[32][33];
    int blk = blockIdx.x, tid = threadIdx.x;
    if (blk < MM) {
        int row = blk;
        size_t i = (size_t)row * 256 + tid;
        float4 v = ((const float4*)x)[i];
        __nv_bfloat162* Hp = (__nv_bfloat162*)Ah;
        Hp[2*i]   = __nv_bfloat162(__float2bfloat16(v.x), __float2bfloat16(v.y));
        Hp[2*i+1] = __nv_bfloat162(__float2bfloat16(v.z), __float2bfloat16(v.w));
        float s = v.x*v.x + v.y*v.y + v.z*v.z + v.w*v.w;
        #pragma unroll
        for (int off = 16; off > 0; off >>= 1)
            s += __shfl_xor_sync(0xffffffffu, s, off);
        if ((tid & 31) == 0) red[tid >> 5] = s;
        __syncthreads();
        if (tid == 0) {
            float t = 0.f;
            #pragma unroll
            for (int w = 0; w < 8; ++w) t += red[w];
            xsq[row] = t;
        }
        return;
    }
    const float* W; __nv_bfloat16 *Bh, *Bm; float* ksq; int N, n0, k0;
    if (blk < MM + 3072) {
        int b2 = blk - MM;
        W = wA; Bh = BhA; Bm = nullptr; ksq = ksqa; N = N_QKV;
        n0 = (b2 % 96) * 32; k0 = (b2 / 96) * 32;
    } else {
        int b2 = blk - MM - 3072;
        W = wP; Bh = BhP; Bm = BmP; ksq = ksqp; N = CC;
        n0 = (b2 % 32) * 32; k0 = (b2 / 32) * 32;
    }
    int tx = tid & 31, ty = tid >> 5;
    for (int j = ty; j < 32; j += 8)
        tile[j][tx] = W[(size_t)(k0 + j) * N + n0 + tx];
    __syncthreads();
    for (int j = ty; j < 32; j += 8) {
        float v = tile[tx][j];
        __nv_bfloat16 h = __float2bfloat16(v);
        size_t o = (size_t)(n0 + j) * KK + k0 + tx;
        Bh[o] = h;
        if (Bm) Bm[o] = __float2bfloat16(v - __bfloat162float(h));
        float sq = v * v;
        #pragma unroll
        for (int off = 16; off > 0; off >>= 1)
            sq += __shfl_xor_sync(0xffffffffu, sq, off);
        if (tx == 0) atomicAdd(&ksq[n0 + j], sq);
    }
}

// ------------------------- GEMM1 (mma.sync, 1 combo) + YAT+RoPE epilogue ---
// CTA 128(M)x256(N), 8 warps 2x4. 3-stage cp.async. hi planes only.
#define SROW 144
#define ATILE (128*SROW)                 // 18432
#define BTILE (256*SROW)                 // 36864
#define GSTAGE (ATILE + BTILE)           // 55296
#define GNKCH (KK/32)                    // 32

__global__ __launch_bounds__(256, 1)
void gemm1_kernel(const __nv_bfloat16* __restrict__ Ah,
                  const __nv_bfloat16* __restrict__ Bh,
                  const float* __restrict__ bias, const float* __restrict__ xsq,
                  const float* __restrict__ ksq, const float* __restrict__ alphap,
                  __nv_bfloat16* __restrict__ Qp, __nv_bfloat16* __restrict__ Kp,
                  __nv_bfloat16* __restrict__ Vp, const float2* __restrict__ tbl) {
    extern __shared__ char dsm[];
    uint32_t sbase = smem_u32(dsm);

    const int tid = threadIdx.x;
    const int lane = tid & 31;
    const int wid = tid >> 5;
    const int wm = wid >> 2;
    const int wn = wid & 3;
    int id = blockIdx.x;
    int n0 = (id % 12) * 256;
    int m0 = (id / 12) * 128;
    const int l8 = lane & 7;
    const int lm = lane >> 3;
    const int region = n0 >> 10;

    const char* pAh = (const char*)Ah + (size_t)m0 * (KK*2);
    const char* pBh = (const char*)Bh + (size_t)n0 * (KK*2);
    const int lch = tid & 3, lrw = tid >> 2;     // 256-thread loader

    #define LOAD1(kc, st) do {                                                \
        uint32_t sbs = sbase + (st) * GSTAGE;                                 \
        size_t kb = (size_t)(kc) * 64 + (size_t)lch * 16;                     \
        _Pragma("unroll")                                                     \
        for (int i = 0; i < 2; ++i) {                                         \
            int row = lrw + i * 64;                                           \
            cp16(sbs + row * SROW + lch * 16, pAh + (size_t)row * (KK*2) + kb);\
        }                                                                     \
        _Pragma("unroll")                                                     \
        for (int i = 0; i < 4; ++i) {                                         \
            int row = lrw + i * 64;                                           \
            cp16(sbs + ATILE + row * SROW + lch * 16,                         \
                 pBh + (size_t)row * (KK*2) + kb);                            \
        }                                                                     \
        CP_COMMIT();                                                          \
    } while (0)

    float acc[4][8][4];
    #pragma unroll
    for (int i = 0; i < 4; ++i)
        #pragma unroll
        for (int j = 0; j < 8; ++j)
            #pragma unroll
            for (int r = 0; r < 4; ++r) acc[i][j][r] = 0.f;

    const int arow = lane & 15;
    const int akoff = (lane >> 4) * 16;

    LOAD1(0, 0);
    LOAD1(1, 1);

    for (int kc = 0; kc < GNKCH; ++kc) {
        int st = kc - (kc / 3) * 3;
        if (kc + 1 < GNKCH) { CP_WAIT(1); } else { CP_WAIT(0); }
        __syncthreads();
        if (kc + 2 < GNKCH) {
            int st2 = (kc + 2) - ((kc + 2) / 3) * 3;
            LOAD1(kc + 2, st2);
        }

        uint32_t sA = sbase + st * GSTAGE;
        uint32_t sB = sA + ATILE;

        #pragma unroll
        for (int ks = 0; ks < 2; ++ks) {
            uint32_t a[4][4];
            #pragma unroll
            for (int fm = 0; fm < 4; ++fm) {
                uint32_t ad = sA + (wm*64 + fm*16 + arow) * SROW
                            + ks*32 + akoff;
                LDM4(a[fm][0], a[fm][1], a[fm][2], a[fm][3], ad);
            }
            uint32_t b[8][2];
            #pragma unroll
            for (int pr = 0; pr < 4; ++pr) {
                uint32_t bd = sB + (wn*64 + (pr*2 + (lm >> 1))*8 + l8) * SROW
                            + ks*32 + (lm & 1)*16;
                LDM4(b[pr*2][0], b[pr*2][1], b[pr*2+1][0], b[pr*2+1][1], bd);
            }
            #pragma unroll
            for (int fm = 0; fm < 4; ++fm)
                #pragma unroll
                for (int fn = 0; fn < 8; ++fn)
                    MMA16816(acc[fm][fn], a[fm], b[fn]);
        }
        __syncthreads();
    }

    float alpha = *alphap;
    float scl = powf(sqrtf((float)N_QKV) / logf(1.f + (float)N_QKV), alpha);
    int g = lane >> 2;
    int t2 = (lane & 3) * 2;

    #pragma unroll
    for (int fm = 0; fm < 4; ++fm) {
        int mA = m0 + wm*64 + fm*16 + g;
        float xsA = xsq[mA];
        float xsB = xsq[mA + 8];
        #pragma unroll
        for (int fn = 0; fn < 8; ++fn) {
            int col = n0 + wn*64 + fn*8 + t2;
            float k0v = ksq[col], k1v = ksq[col+1];
            float b0v = bias[col], b1v = bias[col+1];
            float d0 = acc[fm][fn][0], d1 = acc[fm][fn][1];
            float d2 = acc[fm][fn][2], d3 = acc[fm][fn][3];
            acc[fm][fn][0] = d0*d0 / (xsA + k0v - 2.f*d0 + EPSY) * scl + b0v;
            acc[fm][fn][1] = d1*d1 / (xsA + k1v - 2.f*d1 + EPSY) * scl + b1v;
            acc[fm][fn][2] = d2*d2 / (xsB + k0v - 2.f*d2 + EPSY) * scl + b0v;
            acc[fm][fn][3] = d3*d3 / (xsB + k1v - 2.f*d3 + EPSY) * scl + b1v;
        }
        int hloc = ((n0 & 1023) + wn*64) >> 6;
        float qs = (region == 0) ? 0.125f : 1.f;
        #pragma unroll
        for (int half = 0; half < 2; ++half) {
            int mrow = mA + half*8;
            int t = mrow & (TT-1);
            int b = mrow >> 11;
            if (region < 2) {
                __nv_bfloat16* P = (region == 0) ? Qp : Kp;
                size_t rowo = ((size_t)(b*HH + hloc) * TT + t) * 64;
                #pragma unroll
                for (int fn = 0; fn < 4; ++fn) {
                    int dd = fn*8 + t2;
                    float4 sc = *(const float4*)(tbl + (t*32 + dd));
                    float x1a = acc[fm][fn][half*2]     * qs;
                    float x1b = acc[fm][fn][half*2+1]   * qs;
                    float x2a = acc[fm][fn+4][half*2]   * qs;
                    float x2b = acc[fm][fn+4][half*2+1] * qs;
                    float r0a = x1a*sc.y - x2a*sc.x, r0b = x1b*sc.w - x2b*sc.z;
                    float r1a = x2a*sc.y + x1a*sc.x, r1b = x2b*sc.w + x1b*sc.z;
                    *(uint32_t*)((char*)P + (rowo + dd) * 2)      = pack_bf16x2(r0b, r0a);
                    *(uint32_t*)((char*)P + (rowo + dd + 32) * 2) = pack_bf16x2(r1b, r1a);
                }
            } else {
                size_t rowo = ((size_t)(b*HH + hloc) * TT + t) * 128;
                #pragma unroll
                for (int fn = 0; fn < 8; ++fn)
                    store_pair(Vp, rowo, fn*8 + t2,
                               acc[fm][fn][half*2], acc[fm][fn][half*2+1]);
            }
        }
    }
    #undef LOAD1
}

// ------------------------- fused flash + GEMM2 (persistent) ----------------
// Task ids [0,512): flash (LPT by qi desc).  [512,640): GEMM2 m-tiles,
// ordered by earliest-ready (qi desc); each waits for its 16 flash tasks
// via g_mcnt. Single persistent grid of 148 CTAs, shared task counter.
#define FQ 128
#define QROWK 144
#define VROW 272
#define SQ_SZ (128*QROWK)                // 18432
#define SK_OFF SQ_SZ
#define SK_SZ (128*QROWK)                // 18432
#define SV_OFF (SK_OFF + 2*SK_SZ)        // 55296
#define SV_SZ (128*VROW)                 // 34816
#define NPERS 148
#define FUSED_SMEM (3*GSTAGE)            // 165888 (>= flash's 124928)

__global__ __launch_bounds__(256, 1)
void fused_kernel(const __nv_bfloat16* __restrict__ Qp,
                  const __nv_bfloat16* __restrict__ Kp,
                  const __nv_bfloat16* __restrict__ Vp,
                  __nv_bfloat16* __restrict__ OH,
                  __nv_bfloat16* __restrict__ OM,
                  float* __restrict__ xsq2,
                  int* __restrict__ fctr,
                  int* __restrict__ mcnt,
                  const __nv_bfloat16* __restrict__ BhP,
                  const __nv_bfloat16* __restrict__ BmP,
                  const float* __restrict__ b_proj,
                  const float* __restrict__ ksqp,
                  const float* __restrict__ a_proj,
                  float* __restrict__ out) {
    extern __shared__ char smf[];
    __shared__ int s_task;
    uint32_t sb = smem_u32(smf);
    int tid = threadIdx.x;
    int lane = tid & 31, wid = tid >> 5;
    const int l8 = lane & 7, lm = lane >> 3;
    const int g = lane >> 2, cq = lane & 3;
    const uint32_t onesf[2] = {0x3F803F80u, 0x3F803F80u};   // bf16 1.0 x4

    for (;;) {
        if (tid == 0) s_task = atomicAdd(fctr, 1);
        __syncthreads();
        int task = s_task;
        if (task >= NTASK2) return;

        if (task < NTASK) {
            // =============== FLASH TASK =====================================
            int wq = wid;
            int qi = (TT/FQ) - 1 - (task >> 5);   // descending work (LPT)
            int bh = task & 31;
            int q0 = qi * FQ;
            const char* Qg = (const char*)(Qp + ((size_t)bh * TT + q0) * 64);
            const char* Kg = (const char*)(Kp + (size_t)bh * TT * 64);
            const char* Vg = (const char*)(Vp + (size_t)bh * TT * 128);

            #pragma unroll
            for (int i = 0; i < 4; ++i) {
                int idx = tid + i * 256; int r = idx >> 3, ch = idx & 7;
                cp16(sb + r * QROWK + ch * 16, Qg + (size_t)r * 128 + ch * 16);
            }
            #pragma unroll
            for (int i = 0; i < 4; ++i) {
                int idx = tid + i * 256; int r = idx >> 3, ch = idx & 7;
                cp16(sb + SK_OFF + r * QROWK + ch * 16, Kg + (size_t)r * 128 + ch * 16);
            }
            #pragma unroll
            for (int i = 0; i < 8; ++i) {
                int idx = tid + i * 256; int r = idx >> 4, ch = idx & 15;
                cp16(sb + SV_OFF + r * VROW + ch * 16, Vg + (size_t)r * 256 + ch * 16);
            }
            CP_COMMIT();

            float oacc[8][4];
            #pragma unroll
            for (int fo = 0; fo < 8; ++fo)
                #pragma unroll
                for (int r = 0; r < 4; ++r) oacc[fo][r] = 0.f;
            float lacc[4] = {0.f, 0.f, 0.f, 0.f};
            uint32_t qa[4][4];
            const int nkt = qi + 1;

            for (int kt = 0; kt < nkt; ++kt) {
                int st = kt & 1;
                CP_WAIT(0);
                __syncthreads();
                if (kt + 1 < nkt) {
                    int sn = st ^ 1, k0n = (kt + 1) * FQ;
                    #pragma unroll
                    for (int i = 0; i < 4; ++i) {
                        int idx = tid + i * 256; int r = idx >> 3, ch = idx & 7;
                        cp16(sb + SK_OFF + sn * SK_SZ + r * QROWK + ch * 16,
                             Kg + (size_t)(k0n + r) * 128 + ch * 16);
                    }
                    #pragma unroll
                    for (int i = 0; i < 8; ++i) {
                        int idx = tid + i * 256; int r = idx >> 4, ch = idx & 15;
                        cp16(sb + SV_OFF + sn * SV_SZ + r * VROW + ch * 16,
                             Vg + (size_t)(k0n + r) * 256 + ch * 16);
                    }
                    CP_COMMIT();
                }

                if (kt == 0) {
                    #pragma unroll
                    for (int ks = 0; ks < 4; ++ks) {
                        uint32_t ad = sb + (wq * 16 + (lane & 15)) * QROWK
                                    + ks * 32 + (lane >> 4) * 16;
                        LDM4(qa[ks][0], qa[ks][1], qa[ks][2], qa[ks][3], ad);
                    }
                }

                uint32_t sKb = sb + SK_OFF + st * SK_SZ;
                uint32_t sVb = sb + SV_OFF + st * SV_SZ;
                bool diag = (kt == nkt - 1);
                const int fnmax = diag ? (2*wq + 2) : 16;
                const int k2max = diag ? (wq + 1) : 8;

                float sacc[16][4];
                #pragma unroll
                for (int fn = 0; fn < 16; ++fn)
                    #pragma unroll
                    for (int r = 0; r < 4; ++r) sacc[fn][r] = 0.f;

                #pragma unroll
                for (int ks = 0; ks < 4; ++ks) {
                    #pragma unroll
                    for (int half = 0; half < 2; ++half) {
                        if (half*8 >= fnmax) break;
                        uint32_t kh[8][2];
                        #pragma unroll
                        for (int pr = 0; pr < 4; ++pr) {
                            if (half*8 + pr*2 >= fnmax) break;
                            uint32_t base = sKb
                                + (half*64 + (pr*2 + (lm >> 1))*8 + l8) * QROWK
                                + ks*32 + (lm & 1)*16;
                            LDM4(kh[pr*2][0], kh[pr*2][1], kh[pr*2+1][0], kh[pr*2+1][1], base);
                        }
                        #pragma unroll
                        for (int f = 0; f < 8; ++f) {
                            if (half*8 + f >= fnmax) break;
                            MMA16816(sacc[half*8 + f], qa[ks], kh[f]);
                        }
                    }
                }

                int k0 = kt * FQ;
                int r0q = q0 + wq * 16 + g;
                if (diag) {
                    #pragma unroll
                    for (int fn = 0; fn < 16; ++fn) {
                        int col = k0 + fn * 8 + 2 * cq;
                        if (col     > r0q)     sacc[fn][0] = -1e30f;
                        if (col + 1 > r0q)     sacc[fn][1] = -1e30f;
                        if (col     > r0q + 8) sacc[fn][2] = -1e30f;
                        if (col + 1 > r0q + 8) sacc[fn][3] = -1e30f;
                    }
                }

                uint32_t pah[8][4];
                #pragma unroll
                for (int k2 = 0; k2 < 8; ++k2) {
                    #pragma unroll
                    for (int half = 0; half < 2; ++half) {
                        int fn = k2 * 2 + half;
                        float p0 = __expf(sacc[fn][0]);
                        float p1 = __expf(sacc[fn][1]);
                        float p2 = __expf(sacc[fn][2]);
                        float p3 = __expf(sacc[fn][3]);
                        pah[k2][half*2+0] = pack_bf16x2(p1, p0);
                        pah[k2][half*2+1] = pack_bf16x2(p3, p2);
                    }
                }

                #pragma unroll
                for (int k2 = 0; k2 < 8; ++k2) {
                    if (k2 >= k2max) break;
                    MMA16816(lacc, pah[k2], onesf);
                    uint32_t vh[8][2], vm[8][2];
                    #pragma unroll
                    for (int pr = 0; pr < 4; ++pr) {
                        uint32_t base = sVb + (k2*16 + (lm & 1)*8 + l8) * VROW
                                      + (pr*2 + (lm >> 1)) * 16;
                        LDM4T(vh[pr*2][0], vh[pr*2][1], vh[pr*2+1][0], vh[pr*2+1][1], base);
                        LDM4T(vm[pr*2][0], vm[pr*2][1], vm[pr*2+1][0], vm[pr*2+1][1],
                              base + 128);
                    }
                    #pragma unroll
                    for (int fo = 0; fo < 8; ++fo) {
                        MMA16816(oacc[fo], pah[k2], vh[fo]);
                        MMA16816(oacc[fo], pah[k2], vm[fo]);
                    }
                }
            }

            // epilogue
            float inv0 = 1.f / lacc[0], inv1 = 1.f / lacc[2];
            int b = bh >> 4, h = bh & 15;
            int r0q = q0 + wq * 16 + g;
            size_t row0 = (size_t)(b * TT + r0q);
            float s0 = 0.f, s1 = 0.f;
            #pragma unroll
            for (int fo = 0; fo < 8; ++fo) {
                int col = h * 64 + fo * 8 + 2 * cq;
                float w00 = oacc[fo][0] * inv0, w01 = oacc[fo][1] * inv0;
                float w10 = oacc[fo][2] * inv1, w11 = oacc[fo][3] * inv1;
                s0 += w00*w00 + w01*w01;
                s1 += w10*w10 + w11*w11;
                float h00 = __bfloat162float(__float2bfloat16(w00));
                float h01 = __bfloat162float(__float2bfloat16(w01));
                float h10 = __bfloat162float(__float2bfloat16(w10));
                float h11 = __bfloat162float(__float2bfloat16(w11));
                *(uint32_t*)((char*)OH + (row0 * KK + col) * 2) = pack_bf16x2(w01, w00);
                *(uint32_t*)((char*)OM + (row0 * KK + col) * 2) = pack_bf16x2(w01 - h01, w00 - h00);
                *(uint32_t*)((char*)OH + ((row0 + 8) * KK + col) * 2) = pack_bf16x2(w11, w10);
                *(uint32_t*)((char*)OM + ((row0 + 8) * KK + col) * 2) = pack_bf16x2(w11 - h11, w10 - h10);
            }
            s0 += __shfl_xor_sync(0xffffffffu, s0, 1);
            s0 += __shfl_xor_sync(0xffffffffu, s0, 2);
            s1 += __shfl_xor_sync(0xffffffffu, s1, 1);
            s1 += __shfl_xor_sync(0xffffffffu, s1, 2);
            if (cq == 0) {
                atomicAdd(&xsq2[row0], s0);
                atomicAdd(&xsq2[row0 + 8], s1);
            }
            // signal completion for dependency tracking
            __threadfence();
            __syncthreads();
            if (tid == 0) atomicAdd(&mcnt[b * 16 + qi], 1);
        } else {
            // =============== GEMM2 TASK =====================================
            int j = task - NTASK;                 // 0..127
            int qo = 15 - (j >> 3);               // earliest-ready first
            int bb = (j >> 2) & 1;
            int mt = bb * 16 + qo;
            int m0 = mt * 128;
            int n0 = (j & 3) * 256;

            // wait for the 16 flash tasks covering this m-tile
            if (tid == 0) {
                volatile int* p = &mcnt[mt];
                while (*p < 16) __nanosleep(128);
            }
            __syncthreads();
            __threadfence();

            const int wm = wid >> 2;
            const int wn = wid & 3;
            const char* pA0 = (const char*)OH + (size_t)m0 * (KK*2);
            const char* pA1 = (const char*)OM + (size_t)m0 * (KK*2);
            const char* pB0 = (const char*)BhP + (size_t)n0 * (KK*2);
            const char* pB1 = (const char*)BmP + (size_t)n0 * (KK*2);
            const int lplane = (tid >> 2) & 1;
            const int lchunk = tid & 3;

            #define LOAD2(kc, st) do {                                         \
                size_t kb = (size_t)(kc) * 64 + (size_t)lchunk * 16;           \
                uint32_t sbs = sb + (st) * GSTAGE;                             \
                uint32_t doff0 = (tid >> 3) * SROW + lplane * 64 + lchunk * 16;\
                _Pragma("unroll")                                              \
                for (int i = 0; i < 4; ++i) {                                  \
                    int row = (tid >> 3) + i * 32;                             \
                    const char* sa = (lplane ? pA1 : pA0) + (size_t)row * (KK*2) + kb;\
                    cp16(sbs + doff0 + i * (32*SROW), sa);                     \
                }                                                              \
                _Pragma("unroll")                                              \
                for (int i = 0; i < 8; ++i) {                                  \
                    int row = (tid >> 3) + i * 32;                             \
                    const char* sbp = (lplane ? pB1 : pB0) + (size_t)row * (KK*2) + kb;\
                    cp16(sbs + ATILE + doff0 + i * (32*SROW), sbp);            \
                }                                                              \
                CP_COMMIT();                                                   \
            } while (0)

            float acc[4][8][4];
            #pragma unroll
            for (int i = 0; i < 4; ++i)
                #pragma unroll
                for (int jj = 0; jj < 8; ++jj)
                    #pragma unroll
                    for (int r = 0; r < 4; ++r) acc[i][jj][r] = 0.f;

            const int arow = lane & 15;
            const int akoff = (lane >> 4) * 16;

            LOAD2(0, 0);
            LOAD2(1, 1);

            for (int kc = 0; kc < GNKCH; ++kc) {
                int st = kc - (kc / 3) * 3;
                if (kc + 1 < GNKCH) { CP_WAIT(1); } else { CP_WAIT(0); }
                __syncthreads();
                if (kc + 2 < GNKCH) {
                    int st2 = (kc + 2) - ((kc + 2) / 3) * 3;
                    LOAD2(kc + 2, st2);
                }

                uint32_t sA = sb + st * GSTAGE;
                uint32_t sB = sA + ATILE;

                #pragma unroll
                for (int ks = 0; ks < 2; ++ks) {
                    uint32_t a[2][4][4];
                    #pragma unroll
                    for (int pl = 0; pl < 2; ++pl)
                        #pragma unroll
                        for (int fm = 0; fm < 4; ++fm) {
                            uint32_t ad = sA + (wm*64 + fm*16 + arow) * SROW
                                        + pl*64 + ks*32 + akoff;
                            LDM4(a[pl][fm][0], a[pl][fm][1], a[pl][fm][2], a[pl][fm][3], ad);
                        }
                    uint32_t b[2][8][2];
                    #pragma unroll
                    for (int pl = 0; pl < 2; ++pl)
                        #pragma unroll
                        for (int pr = 0; pr < 4; ++pr) {
                            uint32_t bd = sB + (wn*64 + (pr*2 + (lm >> 1))*8 + l8) * SROW
                                        + pl*64 + ks*32 + (lm & 1)*16;
                            LDM4(b[pl][pr*2][0], b[pl][pr*2][1],
                                 b[pl][pr*2+1][0], b[pl][pr*2+1][1], bd);
                        }
                    #pragma unroll
                    for (int fm = 0; fm < 4; ++fm)
                        #pragma unroll
                        for (int fn = 0; fn < 8; ++fn) {
                            MMA16816(acc[fm][fn], a[0][fm], b[0][fn]);
                            MMA16816(acc[fm][fn], a[0][fm], b[1][fn]);
                            MMA16816(acc[fm][fn], a[1][fm], b[0][fn]);
                        }
                }
                __syncthreads();
            }

            float alpha = *a_proj;
            float scl = powf(sqrtf((float)CC) / logf(1.f + (float)CC), alpha);
            int t2 = (lane & 3) * 2;

            #pragma unroll
            for (int fm = 0; fm < 4; ++fm) {
                int mA = m0 + wm*64 + fm*16 + g;
                float xsA = xsq2[mA];
                float xsB = xsq2[mA + 8];
                #pragma unroll
                for (int fn = 0; fn < 8; ++fn) {
                    int col = n0 + wn*64 + fn*8 + t2;
                    float k0v = ksqp[col], k1v = ksqp[col+1];
                    float b0v = b_proj[col], b1v = b_proj[col+1];
                    float d0 = acc[fm][fn][0], d1 = acc[fm][fn][1];
                    float d2 = acc[fm][fn][2], d3 = acc[fm][fn][3];
                    float2 o01, o23;
                    o01.x = d0*d0 / (xsA + k0v - 2.f*d0 + EPSY) * scl + b0v;
                    o01.y = d1*d1 / (xsA + k1v - 2.f*d1 + EPSY) * scl + b1v;
                    o23.x = d2*d2 / (xsB + k0v - 2.f*d2 + EPSY) * scl + b0v;
                    o23.y = d3*d3 / (xsB + k1v - 2.f*d3 + EPSY) * scl + b1v;
                    *(float2*)(out + (size_t)mA * CC + col) = o01;
                    *(float2*)(out + (size_t)(mA + 8) * CC + col) = o23;
                }
            }
            #undef LOAD2
        }
    }
}

// ------------------------- host launch --------------------------------------
extern "C" void kernel_launch(void* const* d_in, const int* in_sizes, int n_in,
                              void* d_out, int out_size) {
    const float* x      = (const float*)d_in[0];
    const float* w_attn = (const float*)d_in[2];
    const float* b_attn = (const float*)d_in[3];
    const float* a_attn = (const float*)d_in[4];
    const float* w_proj = (const float*)d_in[5];
    const float* b_proj = (const float*)d_in[6];
    const float* a_proj = (const float*)d_in[7];
    float* out = (float*)d_out;

    void *xsq_, *xsq2_, *ksqa_, *ksqp_, *tbl_, *fctr_, *mcnt_;
    void *ah_, *am_, *bha_, *bhp_, *bmp_, *qp_, *kp_, *vp_;
    cudaGetSymbolAddress(&xsq_,  g_xsq);
    cudaGetSymbolAddress(&xsq2_, g_xsq2);
    cudaGetSymbolAddress(&ksqa_, g_ksqA);
    cudaGetSymbolAddress(&ksqp_, g_ksqP);
    cudaGetSymbolAddress(&tbl_,  g_tbl);
    cudaGetSymbolAddress(&fctr_, g_fctr);
    cudaGetSymbolAddress(&mcnt_, g_mcnt);
    cudaGetSymbolAddress(&ah_,   g_Ah);
    cudaGetSymbolAddress(&am_,   g_Am);
    cudaGetSymbolAddress(&bha_,  g_BhA);
    cudaGetSymbolAddress(&bhp_,  g_BhP);
    cudaGetSymbolAddress(&bmp_,  g_BmP);
    cudaGetSymbolAddress(&qp_,   g_Qp);
    cudaGetSymbolAddress(&kp_,   g_Kp);
    cudaGetSymbolAddress(&vp_,   g_Vp);
    float* xsq  = (float*)xsq_;
    float* xsq2 = (float*)xsq2_;
    float* ksqa = (float*)ksqa_;
    float* ksqp = (float*)ksqp_;
    float2* tbl = (float2*)tbl_;
    int* fctr   = (int*)fctr_;
    int* mcnt   = (int*)mcnt_;
    __nv_bfloat16* Ah  = (__nv_bfloat16*)ah_;
    __nv_bfloat16* Am  = (__nv_bfloat16*)am_;
    __nv_bfloat16* BhA = (__nv_bfloat16*)bha_;
    __nv_bfloat16* BhP = (__nv_bfloat16*)bhp_;
    __nv_bfloat16* BmP = (__nv_bfloat16*)bmp_;
    __nv_bfloat16* Qp  = (__nv_bfloat16*)qp_;
    __nv_bfloat16* Kp  = (__nv_bfloat16*)kp_;
    __nv_bfloat16* Vp  = (__nv_bfloat16*)vp_;

    const int gemm_smem = 3 * GSTAGE;                        // 165888
    cudaFuncSetAttribute(gemm1_kernel,
                         cudaFuncAttributeMaxDynamicSharedMemorySize, gemm_smem);
    cudaFuncSetAttribute(fused_kernel,
                         cudaFuncAttributeMaxDynamicSharedMemorySize, FUSED_SMEM);

    // zero accumulators + task/dep counters + rope table
    prep_kernel<<<256, 256>>>(ksqa, ksqp, xsq2, tbl, fctr, mcnt);

    // merged: x split(hi)+rowsq, w_attn transpose(hi)+colsq, w_proj full
    prep2_kernel<<<MM + 3072 + 1024, 256>>>(x, Ah, xsq,
                                            w_attn, BhA, ksqa,
                                            w_proj, BhP, BmP, ksqp);

    // GEMM1 (1 combo, uniform CTAs) + YAT + RoPE -> Qp/Kp/Vp
    gemm1_kernel<<<384, 256, gemm_smem>>>(Ah, BhA, b_attn, xsq, ksqa, a_attn,
                                          Qp, Kp, Vp, tbl);

    // fused persistent flash + GEMM2 (dependency-counted overlap) -> out
    fused_kernel<<<NPERS, 256, FUSED_SMEM>>>(Qp, Kp, Vp, Ah, Am, xsq2, fctr, mcnt,
                                             BhP, BmP, b_proj, ksqp, a_proj, out);
}

// round 16
// speedup vs baseline: 1.3946x; 1.0061x over previous
#include <cuda_runtime.h>
#include <cuda_bf16.h>
#include <math.h>
#include <stdint.h>

// Problem constants
#define BB 2
#define TT 2048
#define CC 1024
#define HH 16
#define DD 64
#define MM (BB*TT)          // 4096
#define N_QKV (3*CC)        // 3072
#define KK CC               // GEMM K = 1024
#define BH (BB*HH)          // 32
#define EPSY 1e-6f
#define NT_G1 384
#define NT_FL 512
#define NT_G2 128
#define NTALL (NT_G1 + NT_FL + NT_G2)   // 1024

// ------------------------- scratch (device globals) -----------------------
__device__ float g_xsq[MM];
__device__ float g_xsq2[MM];
__device__ float g_ksqA[N_QKV];
__device__ float g_ksqP[CC];
__device__ float2 g_tbl[TT * 32];
__device__ int g_fctr;
__device__ int g_mcnt[32];
__device__ int g_g1cnt[8];
__device__ __nv_bfloat16 g_Ah[(size_t)MM * KK];
__device__ __nv_bfloat16 g_Am[(size_t)MM * KK];
__device__ __nv_bfloat16 g_BhA[(size_t)N_QKV * KK];
__device__ __nv_bfloat16 g_BhP[(size_t)CC * KK];
__device__ __nv_bfloat16 g_BmP[(size_t)CC * KK];
// flash operands: Qp/Kp hi-only [bh][t][64] bf16; Vp [bh][t][hi64|mid64]
__device__ __nv_bfloat16 g_Qp[(size_t)BH * TT * 64];
__device__ __nv_bfloat16 g_Kp[(size_t)BH * TT * 64];
__device__ __nv_bfloat16 g_Vp[(size_t)BH * TT * 128];

// ------------------------- PTX helpers ------------------------------------
__device__ __forceinline__ uint32_t smem_u32(const void* p) {
    uint32_t a;
    asm("{ .reg .u64 t; cvta.to.shared.u64 t, %1; cvt.u32.u64 %0, t; }"
        : "=r"(a) : "l"(p));
    return a;
}
__device__ __forceinline__ void cp16(uint32_t dst, const void* src) {
    asm volatile("cp.async.cg.shared.global [%0], [%1], 16;" :: "r"(dst), "l"(src) : "memory");
}
#define CP_COMMIT() asm volatile("cp.async.commit_group;" ::: "memory")
#define CP_WAIT(n)  asm volatile("cp.async.wait_group %0;" :: "n"(n) : "memory")

#define LDM4(r0, r1, r2, r3, addr) \
    asm volatile("ldmatrix.sync.aligned.m8n8.x4.shared.b16 {%0,%1,%2,%3}, [%4];" \
        : "=r"(r0), "=r"(r1), "=r"(r2), "=r"(r3) : "r"(addr))

#define LDM4T(r0, r1, r2, r3, addr) \
    asm volatile("ldmatrix.sync.aligned.m8n8.x4.trans.shared.b16 {%0,%1,%2,%3}, [%4];" \
        : "=r"(r0), "=r"(r1), "=r"(r2), "=r"(r3) : "r"(addr))

#define MMA16816(d, a, b) \
    asm volatile("mma.sync.aligned.m16n8k16.row.col.f32.bf16.bf16.f32 " \
        "{%0,%1,%2,%3}, {%4,%5,%6,%7}, {%8,%9}, {%0,%1,%2,%3};" \
        : "+f"((d)[0]), "+f"((d)[1]), "+f"((d)[2]), "+f"((d)[3]) \
        : "r"((a)[0]), "r"((a)[1]), "r"((a)[2]), "r"((a)[3]), \
          "r"((b)[0]), "r"((b)[1]))

// packs {hi, lo} fp32 -> bf16x2 (first source is upper half)
__device__ __forceinline__ uint32_t pack_bf16x2(float hi, float lo) {
    uint32_t r;
    asm("cvt.rn.bf16x2.f32 %0, %1, %2;" : "=r"(r) : "f"(hi), "f"(lo));
    return r;
}
// split-store a pair of adjacent cols (d even) into hi/mid planes of one row
__device__ __forceinline__ void store_pair(__nv_bfloat16* P, size_t rowo, int d,
                                           float a, float b) {
    float ha = __bfloat162float(__float2bfloat16(a));
    float hb = __bfloat162float(__float2bfloat16(b));
    *(uint32_t*)((char*)P + (rowo + d) * 2)      = pack_bf16x2(b, a);
    *(uint32_t*)((char*)P + (rowo + 64 + d) * 2) = pack_bf16x2(b - hb, a - ha);
}

// ------------------------- prep: zero accumulators + rope table ------------
__global__ void prep_kernel(float* __restrict__ ksqa, float* __restrict__ ksqp,
                            float* __restrict__ xsq2, float2* __restrict__ tbl,
                            int* __restrict__ fctr, int* __restrict__ mcnt,
                            int* __restrict__ g1cnt) {
    int i = blockIdx.x * 256 + threadIdx.x;        // grid 256 -> 65536 threads
    if (i == 0) *fctr = 0;
    if (i < 32) mcnt[i] = 0;
    if (i < 8)  g1cnt[i] = 0;
    if (i < N_QKV) ksqa[i] = 0.f;
    if (i < CC)    ksqp[i] = 0.f;
    if (i < MM)    xsq2[i] = 0.f;
    int t = i >> 5, dd = i & 31;
    float freq = expf(-9.2103403719761836f * ((float)(2*dd) / 64.f));
    float sn, cs;
    sincosf((float)t * freq, &sn, &cs);
    tbl[i] = make_float2(sn, cs);
}

// ------------------------- merged prep2: x split + both W transposes -------
__global__ void prep2_kernel(const float* __restrict__ x,
                             __nv_bfloat16* __restrict__ Ah,
                             float* __restrict__ xsq,
                             const float* __restrict__ wA,
                             __nv_bfloat16* __restrict__ BhA,
                             float* __restrict__ ksqa,
                             const float* __restrict__ wP,
                             __nv_bfloat16* __restrict__ BhP,
                             __nv_bfloat16* __restrict__ BmP,
                             float* __restrict__ ksqp) {
    __shared__ float red[8];
    __shared__ float tile[32][33];
    int blk = blockIdx.x, tid = threadIdx.x;
    if (blk < MM) {
        int row = blk;
        size_t i = (size_t)row * 256 + tid;
        float4 v = ((const float4*)x)[i];
        __nv_bfloat162* Hp = (__nv_bfloat162*)Ah;
        Hp[2*i]   = __nv_bfloat162(__float2bfloat16(v.x), __float2bfloat16(v.y));
        Hp[2*i+1] = __nv_bfloat162(__float2bfloat16(v.z), __float2bfloat16(v.w));
        float s = v.x*v.x + v.y*v.y + v.z*v.z + v.w*v.w;
        #pragma unroll
        for (int off = 16; off > 0; off >>= 1)
            s += __shfl_xor_sync(0xffffffffu, s, off);
        if ((tid & 31) == 0) red[tid >> 5] = s;
        __syncthreads();
        if (tid == 0) {
            float t = 0.f;
            #pragma unroll
            for (int w = 0; w < 8; ++w) t += red[w];
            xsq[row] = t;
        }
        return;
    }
    const float* W; __nv_bfloat16 *Bh, *Bm; float* ksq; int N, n0, k0;
    if (blk < MM + 3072) {
        int b2 = blk - MM;
        W = wA; Bh = BhA; Bm = nullptr; ksq = ksqa; N = N_QKV;
        n0 = (b2 % 96) * 32; k0 = (b2 / 96) * 32;
    } else {
        int b2 = blk - MM - 3072;
        W = wP; Bh = BhP; Bm = BmP; ksq = ksqp; N = CC;
        n0 = (b2 % 32) * 32; k0 = (b2 / 32) * 32;
    }
    int tx = tid & 31, ty = tid >> 5;
    for (int j = ty; j < 32; j += 8)
        tile[j][tx] = W[(size_t)(k0 + j) * N + n0 + tx];
    __syncthreads();
    for (int j = ty; j < 32; j += 8) {
        float v = tile[tx][j];
        __nv_bfloat16 h = __float2bfloat16(v);
        size_t o = (size_t)(n0 + j) * KK + k0 + tx;
        Bh[o] = h;
        if (Bm) Bm[o] = __float2bfloat16(v - __bfloat162float(h));
        float sq = v * v;
        #pragma unroll
        for (int off = 16; off > 0; off >>= 1)
            sq += __shfl_xor_sync(0xffffffffu, sq, off);
        if (tx == 0) atomicAdd(&ksq[n0 + j], sq);
    }
}

// ------------------------- unified persistent kernel -----------------------
// ids [0,384): GEMM1 tasks, hg-major; completion -> g1cnt[b*4+hg] (target 48)
// ids [384,896): flash tasks, hg-major, LPT within; wait g1cnt[b*4+hg]==48
// ids [896,1024): GEMM2 m-tiles; wait mcnt[mt]==16
#define SROW 144
#define ATILE (128*SROW)                 // 18432
#define BTILE (256*SROW)                 // 36864
#define GSTAGE (ATILE + BTILE)           // 55296
#define GNKCH (KK/32)                    // 32
#define FQ 128
#define QROWK 144
#define VROW 272
#define SQ_SZ (128*QROWK)                // 18432
#define SK_OFF SQ_SZ
#define SK_SZ (128*QROWK)                // 18432
#define SV_OFF (SK_OFF + 2*SK_SZ)        // 55296
#define SV_SZ (128*VROW)                 // 34816
#define NPERS 148
#define FUSED_SMEM (3*GSTAGE)            // 165888

__global__ __launch_bounds__(256, 1)
void fused_kernel(const __nv_bfloat16* __restrict__ Ah,
                  const __nv_bfloat16* __restrict__ BhA,
                  const float* __restrict__ b_attn, const float* __restrict__ xsq,
                  const float* __restrict__ ksqa, const float* __restrict__ a_attn,
                  __nv_bfloat16* __restrict__ Qp, __nv_bfloat16* __restrict__ Kp,
                  __nv_bfloat16* __restrict__ Vp, const float2* __restrict__ tbl,
                  __nv_bfloat16* __restrict__ OH, __nv_bfloat16* __restrict__ OM,
                  float* __restrict__ xsq2,
                  int* __restrict__ fctr, int* __restrict__ mcnt,
                  int* __restrict__ g1cnt,
                  const __nv_bfloat16* __restrict__ BhP,
                  const __nv_bfloat16* __restrict__ BmP,
                  const float* __restrict__ b_proj, const float* __restrict__ ksqp,
                  const float* __restrict__ a_proj, float* __restrict__ out) {
    extern __shared__ char smf[];
    __shared__ int s_task;
    uint32_t sb = smem_u32(smf);
    int tid = threadIdx.x;
    int lane = tid & 31, wid = tid >> 5;
    const int l8 = lane & 7, lm = lane >> 3;
    const int g = lane >> 2, cq = lane & 3;
    const uint32_t onesf[2] = {0x3F803F80u, 0x3F803F80u};   // bf16 1.0 x4

    for (;;) {
        if (tid == 0) s_task = atomicAdd(fctr, 1);
        __syncthreads();
        int task = s_task;
        if (task >= NTALL) return;

        if (task < NT_G1) {
            // =============== GEMM1 TASK (1 combo) ===========================
            int hg = task / 96;
            int sub = task % 96;
            int breg = sub / 16;              // 0..5
            int b = breg / 3;
            int region = breg % 3;
            int m0 = (b * 16 + (sub % 16)) * 128;
            int n0 = region * 1024 + hg * 256;
            const int wm = wid >> 2;
            const int wn = wid & 3;

            const char* pAh = (const char*)Ah + (size_t)m0 * (KK*2);
            const char* pBh = (const char*)BhA + (size_t)n0 * (KK*2);
            const int lch = tid & 3, lrw = tid >> 2;

            #define LOAD1(kc, st) do {                                         \
                uint32_t sbs = sb + (st) * GSTAGE;                             \
                size_t kb = (size_t)(kc) * 64 + (size_t)lch * 16;              \
                _Pragma("unroll")                                              \
                for (int i = 0; i < 2; ++i) {                                  \
                    int row = lrw + i * 64;                                    \
                    cp16(sbs + row * SROW + lch * 16,                          \
                         pAh + (size_t)row * (KK*2) + kb);                     \
                }                                                              \
                _Pragma("unroll")                                              \
                for (int i = 0; i < 4; ++i) {                                  \
                    int row = lrw + i * 64;                                    \
                    cp16(sbs + ATILE + row * SROW + lch * 16,                  \
                         pBh + (size_t)row * (KK*2) + kb);                     \
                }                                                              \
                CP_COMMIT();                                                   \
            } while (0)

            float acc[4][8][4];
            #pragma unroll
            for (int i = 0; i < 4; ++i)
                #pragma unroll
                for (int j = 0; j < 8; ++j)
                    #pragma unroll
                    for (int r = 0; r < 4; ++r) acc[i][j][r] = 0.f;

            const int arow = lane & 15;
            const int akoff = (lane >> 4) * 16;

            LOAD1(0, 0);
            LOAD1(1, 1);

            for (int kc = 0; kc < GNKCH; ++kc) {
                int st = kc - (kc / 3) * 3;
                if (kc + 1 < GNKCH) { CP_WAIT(1); } else { CP_WAIT(0); }
                __syncthreads();
                if (kc + 2 < GNKCH) {
                    int st2 = (kc + 2) - ((kc + 2) / 3) * 3;
                    LOAD1(kc + 2, st2);
                }
                uint32_t sA = sb + st * GSTAGE;
                uint32_t sB = sA + ATILE;
                #pragma unroll
                for (int ks = 0; ks < 2; ++ks) {
                    uint32_t a[4][4];
                    #pragma unroll
                    for (int fm = 0; fm < 4; ++fm) {
                        uint32_t ad = sA + (wm*64 + fm*16 + arow) * SROW
                                    + ks*32 + akoff;
                        LDM4(a[fm][0], a[fm][1], a[fm][2], a[fm][3], ad);
                    }
                    uint32_t bb[8][2];
                    #pragma unroll
                    for (int pr = 0; pr < 4; ++pr) {
                        uint32_t bd = sB + (wn*64 + (pr*2 + (lm >> 1))*8 + l8) * SROW
                                    + ks*32 + (lm & 1)*16;
                        LDM4(bb[pr*2][0], bb[pr*2][1], bb[pr*2+1][0], bb[pr*2+1][1], bd);
                    }
                    #pragma unroll
                    for (int fm = 0; fm < 4; ++fm)
                        #pragma unroll
                        for (int fn = 0; fn < 8; ++fn)
                            MMA16816(acc[fm][fn], a[fm], bb[fn]);
                }
                __syncthreads();
            }

            float alpha = *a_attn;
            float scl = powf(sqrtf((float)N_QKV) / logf(1.f + (float)N_QKV), alpha);
            int t2 = (lane & 3) * 2;

            #pragma unroll
            for (int fm = 0; fm < 4; ++fm) {
                int mA = m0 + wm*64 + fm*16 + g;
                float xsA = xsq[mA];
                float xsB = xsq[mA + 8];
                #pragma unroll
                for (int fn = 0; fn < 8; ++fn) {
                    int col = n0 + wn*64 + fn*8 + t2;
                    float k0v = ksqa[col], k1v = ksqa[col+1];
                    float b0v = b_attn[col], b1v = b_attn[col+1];
                    float d0 = acc[fm][fn][0], d1 = acc[fm][fn][1];
                    float d2 = acc[fm][fn][2], d3 = acc[fm][fn][3];
                    acc[fm][fn][0] = d0*d0 / (xsA + k0v - 2.f*d0 + EPSY) * scl + b0v;
                    acc[fm][fn][1] = d1*d1 / (xsA + k1v - 2.f*d1 + EPSY) * scl + b1v;
                    acc[fm][fn][2] = d2*d2 / (xsB + k0v - 2.f*d2 + EPSY) * scl + b0v;
                    acc[fm][fn][3] = d3*d3 / (xsB + k1v - 2.f*d3 + EPSY) * scl + b1v;
                }
                int hloc = ((n0 & 1023) + wn*64) >> 6;
                float qs = (region == 0) ? 0.125f : 1.f;
                #pragma unroll
                for (int half = 0; half < 2; ++half) {
                    int mrow = mA + half*8;
                    int t = mrow & (TT-1);
                    int br = mrow >> 11;
                    if (region < 2) {
                        __nv_bfloat16* P = (region == 0) ? Qp : Kp;
                        size_t rowo = ((size_t)(br*HH + hloc) * TT + t) * 64;
                        #pragma unroll
                        for (int fn = 0; fn < 4; ++fn) {
                            int dd = fn*8 + t2;
                            float4 sc = *(const float4*)(tbl + (t*32 + dd));
                            float x1a = acc[fm][fn][half*2]     * qs;
                            float x1b = acc[fm][fn][half*2+1]   * qs;
                            float x2a = acc[fm][fn+4][half*2]   * qs;
                            float x2b = acc[fm][fn+4][half*2+1] * qs;
                            float r0a = x1a*sc.y - x2a*sc.x, r0b = x1b*sc.w - x2b*sc.z;
                            float r1a = x2a*sc.y + x1a*sc.x, r1b = x2b*sc.w + x1b*sc.z;
                            *(uint32_t*)((char*)P + (rowo + dd) * 2)      = pack_bf16x2(r0b, r0a);
                            *(uint32_t*)((char*)P + (rowo + dd + 32) * 2) = pack_bf16x2(r1b, r1a);
                        }
                    } else {
                        size_t rowo = ((size_t)(br*HH + hloc) * TT + t) * 128;
                        #pragma unroll
                        for (int fn = 0; fn < 8; ++fn)
                            store_pair(Vp, rowo, fn*8 + t2,
                                       acc[fm][fn][half*2], acc[fm][fn][half*2+1]);
                    }
                }
            }
            __threadfence();
            __syncthreads();
            if (tid == 0) atomicAdd(&g1cnt[b * 4 + hg], 1);
            #undef LOAD1
        } else if (task < NT_G1 + NT_FL) {
            // =============== FLASH TASK =====================================
            int f = task - NT_G1;
            int hg = f >> 7;
            int fi = f & 127;
            int qi = 15 - (fi >> 3);
            int b = (fi >> 2) & 1;
            int h = hg * 4 + (fi & 3);
            int bh = b * 16 + h;
            int wq = wid;
            int q0 = qi * FQ;

            if (tid == 0) {
                volatile int* p = &g1cnt[b * 4 + hg];
                while (*p < 48) __nanosleep(128);
            }
            __syncthreads();
            __threadfence();

            const char* Qg = (const char*)(Qp + ((size_t)bh * TT + q0) * 64);
            const char* Kg = (const char*)(Kp + (size_t)bh * TT * 64);
            const char* Vg = (const char*)(Vp + (size_t)bh * TT * 128);

            #pragma unroll
            for (int i = 0; i < 4; ++i) {
                int idx = tid + i * 256; int r = idx >> 3, ch = idx & 7;
                cp16(sb + r * QROWK + ch * 16, Qg + (size_t)r * 128 + ch * 16);
            }
            #pragma unroll
            for (int i = 0; i < 4; ++i) {
                int idx = tid + i * 256; int r = idx >> 3, ch = idx & 7;
                cp16(sb + SK_OFF + r * QROWK + ch * 16, Kg + (size_t)r * 128 + ch * 16);
            }
            #pragma unroll
            for (int i = 0; i < 8; ++i) {
                int idx = tid + i * 256; int r = idx >> 4, ch = idx & 15;
                cp16(sb + SV_OFF + r * VROW + ch * 16, Vg + (size_t)r * 256 + ch * 16);
            }
            CP_COMMIT();

            float oacc[8][4];
            #pragma unroll
            for (int fo = 0; fo < 8; ++fo)
                #pragma unroll
                for (int r = 0; r < 4; ++r) oacc[fo][r] = 0.f;
            float lacc[4] = {0.f, 0.f, 0.f, 0.f};
            uint32_t qa[4][4];
            const int nkt = qi + 1;

            for (int kt = 0; kt < nkt; ++kt) {
                int st = kt & 1;
                CP_WAIT(0);
                __syncthreads();
                if (kt + 1 < nkt) {
                    int sn = st ^ 1, k0n = (kt + 1) * FQ;
                    #pragma unroll
                    for (int i = 0; i < 4; ++i) {
                        int idx = tid + i * 256; int r = idx >> 3, ch = idx & 7;
                        cp16(sb + SK_OFF + sn * SK_SZ + r * QROWK + ch * 16,
                             Kg + (size_t)(k0n + r) * 128 + ch * 16);
                    }
                    #pragma unroll
                    for (int i = 0; i < 8; ++i) {
                        int idx = tid + i * 256; int r = idx >> 4, ch = idx & 15;
                        cp16(sb + SV_OFF + sn * SV_SZ + r * VROW + ch * 16,
                             Vg + (size_t)(k0n + r) * 256 + ch * 16);
                    }
                    CP_COMMIT();
                }

                if (kt == 0) {
                    #pragma unroll
                    for (int ks = 0; ks < 4; ++ks) {
                        uint32_t ad = sb + (wq * 16 + (lane & 15)) * QROWK
                                    + ks * 32 + (lane >> 4) * 16;
                        LDM4(qa[ks][0], qa[ks][1], qa[ks][2], qa[ks][3], ad);
                    }
                }

                uint32_t sKb = sb + SK_OFF + st * SK_SZ;
                uint32_t sVb = sb + SV_OFF + st * SV_SZ;
                bool diag = (kt == nkt - 1);
                const int fnmax = diag ? (2*wq + 2) : 16;
                const int k2max = diag ? (wq + 1) : 8;

                float sacc[16][4];
                #pragma unroll
                for (int fn = 0; fn < 16; ++fn)
                    #pragma unroll
                    for (int r = 0; r < 4; ++r) sacc[fn][r] = 0.f;

                #pragma unroll
                for (int ks = 0; ks < 4; ++ks) {
                    #pragma unroll
                    for (int half = 0; half < 2; ++half) {
                        if (half*8 >= fnmax) break;
                        uint32_t kh[8][2];
                        #pragma unroll
                        for (int pr = 0; pr < 4; ++pr) {
                            if (half*8 + pr*2 >= fnmax) break;
                            uint32_t base = sKb
                                + (half*64 + (pr*2 + (lm >> 1))*8 + l8) * QROWK
                                + ks*32 + (lm & 1)*16;
                            LDM4(kh[pr*2][0], kh[pr*2][1], kh[pr*2+1][0], kh[pr*2+1][1], base);
                        }
                        #pragma unroll
                        for (int ff = 0; ff < 8; ++ff) {
                            if (half*8 + ff >= fnmax) break;
                            MMA16816(sacc[half*8 + ff], qa[ks], kh[ff]);
                        }
                    }
                }

                int k0 = kt * FQ;
                int r0q = q0 + wq * 16 + g;
                if (diag) {
                    #pragma unroll
                    for (int fn = 0; fn < 16; ++fn) {
                        int col = k0 + fn * 8 + 2 * cq;
                        if (col     > r0q)     sacc[fn][0] = -1e30f;
                        if (col + 1 > r0q)     sacc[fn][1] = -1e30f;
                        if (col     > r0q + 8) sacc[fn][2] = -1e30f;
                        if (col + 1 > r0q + 8) sacc[fn][3] = -1e30f;
                    }
                }

                uint32_t pah[8][4];
                #pragma unroll
                for (int k2 = 0; k2 < 8; ++k2) {
                    #pragma unroll
                    for (int half = 0; half < 2; ++half) {
                        int fn = k2 * 2 + half;
                        float p0 = __expf(sacc[fn][0]);
                        float p1 = __expf(sacc[fn][1]);
                        float p2 = __expf(sacc[fn][2]);
                        float p3 = __expf(sacc[fn][3]);
                        pah[k2][half*2+0] = pack_bf16x2(p1, p0);
                        pah[k2][half*2+1] = pack_bf16x2(p3, p2);
                    }
                }

                #pragma unroll
                for (int k2 = 0; k2 < 8; ++k2) {
                    if (k2 >= k2max) break;
                    MMA16816(lacc, pah[k2], onesf);
                    uint32_t vh[8][2], vm[8][2];
                    #pragma unroll
                    for (int pr = 0; pr < 4; ++pr) {
                        uint32_t base = sVb + (k2*16 + (lm & 1)*8 + l8) * VROW
                                      + (pr*2 + (lm >> 1)) * 16;
                        LDM4T(vh[pr*2][0], vh[pr*2][1], vh[pr*2+1][0], vh[pr*2+1][1], base);
                        LDM4T(vm[pr*2][0], vm[pr*2][1], vm[pr*2+1][0], vm[pr*2+1][1],
                              base + 128);
                    }
                    #pragma unroll
                    for (int fo = 0; fo < 8; ++fo) {
                        MMA16816(oacc[fo], pah[k2], vh[fo]);
                        MMA16816(oacc[fo], pah[k2], vm[fo]);
                    }
                }
            }

            float inv0 = 1.f / lacc[0], inv1 = 1.f / lacc[2];
            int r0q = q0 + wq * 16 + g;
            size_t row0 = (size_t)(b * TT + r0q);
            float s0 = 0.f, s1 = 0.f;
            #pragma unroll
            for (int fo = 0; fo < 8; ++fo) {
                int col = h * 64 + fo * 8 + 2 * cq;
                float w00 = oacc[fo][0] * inv0, w01 = oacc[fo][1] * inv0;
                float w10 = oacc[fo][2] * inv1, w11 = oacc[fo][3] * inv1;
                s0 += w00*w00 + w01*w01;
                s1 += w10*w10 + w11*w11;
                float h00 = __bfloat162float(__float2bfloat16(w00));
                float h01 = __bfloat162float(__float2bfloat16(w01));
                float h10 = __bfloat162float(__float2bfloat16(w10));
                float h11 = __bfloat162float(__float2bfloat16(w11));
                *(uint32_t*)((char*)OH + (row0 * KK + col) * 2) = pack_bf16x2(w01, w00);
                *(uint32_t*)((char*)OM + (row0 * KK + col) * 2) = pack_bf16x2(w01 - h01, w00 - h00);
                *(uint32_t*)((char*)OH + ((row0 + 8) * KK + col) * 2) = pack_bf16x2(w11, w10);
                *(uint32_t*)((char*)OM + ((row0 + 8) * KK + col) * 2) = pack_bf16x2(w11 - h11, w10 - h10);
            }
            s0 += __shfl_xor_sync(0xffffffffu, s0, 1);
            s0 += __shfl_xor_sync(0xffffffffu, s0, 2);
            s1 += __shfl_xor_sync(0xffffffffu, s1, 1);
            s1 += __shfl_xor_sync(0xffffffffu, s1, 2);
            if (cq == 0) {
                atomicAdd(&xsq2[row0], s0);
                atomicAdd(&xsq2[row0 + 8], s1);
            }
            __threadfence();
            __syncthreads();
            if (tid == 0) atomicAdd(&mcnt[b * 16 + qi], 1);
        } else {
            // =============== GEMM2 TASK =====================================
            int j = task - NT_G1 - NT_FL;         // 0..127
            int qo = 15 - (j >> 3);               // earliest-ready first
            int bb2 = (j >> 2) & 1;
            int mt = bb2 * 16 + qo;
            int m0 = mt * 128;
            int n0 = (j & 3) * 256;

            if (tid == 0) {
                volatile int* p = &mcnt[mt];
                while (*p < 16) __nanosleep(128);
            }
            __syncthreads();
            __threadfence();

            const int wm = wid >> 2;
            const int wn = wid & 3;
            const char* pA0 = (const char*)OH + (size_t)m0 * (KK*2);
            const char* pA1 = (const char*)OM + (size_t)m0 * (KK*2);
            const char* pB0 = (const char*)BhP + (size_t)n0 * (KK*2);
            const char* pB1 = (const char*)BmP + (size_t)n0 * (KK*2);
            const int lplane = (tid >> 2) & 1;
            const int lchunk = tid & 3;

            #define LOAD2(kc, st) do {                                         \
                size_t kb = (size_t)(kc) * 64 + (size_t)lchunk * 16;           \
                uint32_t sbs = sb + (st) * GSTAGE;                             \
                uint32_t doff0 = (tid >> 3) * SROW + lplane * 64 + lchunk * 16;\
                _Pragma("unroll")                                              \
                for (int i = 0; i < 4; ++i) {                                  \
                    int row = (tid >> 3) + i * 32;                             \
                    const char* sa = (lplane ? pA1 : pA0) + (size_t)row * (KK*2) + kb;\
                    cp16(sbs + doff0 + i * (32*SROW), sa);                     \
                }                                                              \
                _Pragma("unroll")                                              \
                for (int i = 0; i < 8; ++i) {                                  \
                    int row = (tid >> 3) + i * 32;                             \
                    const char* sbp = (lplane ? pB1 : pB0) + (size_t)row * (KK*2) + kb;\
                    cp16(sbs + ATILE + doff0 + i * (32*SROW), sbp);            \
                }                                                              \
                CP_COMMIT();                                                   \
            } while (0)

            float acc[4][8][4];
            #pragma unroll
            for (int i = 0; i < 4; ++i)
                #pragma unroll
                for (int jj = 0; jj < 8; ++jj)
                    #pragma unroll
                    for (int r = 0; r < 4; ++r) acc[i][jj][r] = 0.f;

            const int arow = lane & 15;
            const int akoff = (lane >> 4) * 16;

            LOAD2(0, 0);
            LOAD2(1, 1);

            for (int kc = 0; kc < GNKCH; ++kc) {
                int st = kc - (kc / 3) * 3;
                if (kc + 1 < GNKCH) { CP_WAIT(1); } else { CP_WAIT(0); }
                __syncthreads();
                if (kc + 2 < GNKCH) {
                    int st2 = (kc + 2) - ((kc + 2) / 3) * 3;
                    LOAD2(kc + 2, st2);
                }

                uint32_t sA = sb + st * GSTAGE;
                uint32_t sB = sA + ATILE;

                #pragma unroll
                for (int ks = 0; ks < 2; ++ks) {
                    uint32_t a[2][4][4];
                    #pragma unroll
                    for (int pl = 0; pl < 2; ++pl)
                        #pragma unroll
                        for (int fm = 0; fm < 4; ++fm) {
                            uint32_t ad = sA + (wm*64 + fm*16 + arow) * SROW
                                        + pl*64 + ks*32 + akoff;
                            LDM4(a[pl][fm][0], a[pl][fm][1], a[pl][fm][2], a[pl][fm][3], ad);
                        }
                    uint32_t bbf[2][8][2];
                    #pragma unroll
                    for (int pl = 0; pl < 2; ++pl)
                        #pragma unroll
                        for (int pr = 0; pr < 4; ++pr) {
                            uint32_t bd = sB + (wn*64 + (pr*2 + (lm >> 1))*8 + l8) * SROW
                                        + pl*64 + ks*32 + (lm & 1)*16;
                            LDM4(bbf[pl][pr*2][0], bbf[pl][pr*2][1],
                                 bbf[pl][pr*2+1][0], bbf[pl][pr*2+1][1], bd);
                        }
                    #pragma unroll
                    for (int fm = 0; fm < 4; ++fm)
                        #pragma unroll
                        for (int fn = 0; fn < 8; ++fn) {
                            MMA16816(acc[fm][fn], a[0][fm], bbf[0][fn]);
                            MMA16816(acc[fm][fn], a[0][fm], bbf[1][fn]);
                            MMA16816(acc[fm][fn], a[1][fm], bbf[0][fn]);
                        }
                }
                __syncthreads();
            }

            float alpha = *a_proj;
            float scl = powf(sqrtf((float)CC) / logf(1.f + (float)CC), alpha);
            int t2 = (lane & 3) * 2;

            #pragma unroll
            for (int fm = 0; fm < 4; ++fm) {
                int mA = m0 + wm*64 + fm*16 + g;
                float xsA = xsq2[mA];
                float xsB = xsq2[mA + 8];
                #pragma unroll
                for (int fn = 0; fn < 8; ++fn) {
                    int col = n0 + wn*64 + fn*8 + t2;
                    float k0v = ksqp[col], k1v = ksqp[col+1];
                    float b0v = b_proj[col], b1v = b_proj[col+1];
                    float d0 = acc[fm][fn][0], d1 = acc[fm][fn][1];
                    float d2 = acc[fm][fn][2], d3 = acc[fm][fn][3];
                    float2 o01, o23;
                    o01.x = d0*d0 / (xsA + k0v - 2.f*d0 + EPSY) * scl + b0v;
                    o01.y = d1*d1 / (xsA + k1v - 2.f*d1 + EPSY) * scl + b1v;
                    o23.x = d2*d2 / (xsB + k0v - 2.f*d2 + EPSY) * scl + b0v;
                    o23.y = d3*d3 / (xsB + k1v - 2.f*d3 + EPSY) * scl + b1v;
                    *(float2*)(out + (size_t)mA * CC + col) = o01;
                    *(float2*)(out + (size_t)(mA + 8) * CC + col) = o23;
                }
            }
            #undef LOAD2
        }
    }
}

// ------------------------- host launch --------------------------------------
extern "C" void kernel_launch(void* const* d_in, const int* in_sizes, int n_in,
                              void* d_out, int out_size) {
    const float* x      = (const float*)d_in[0];
    const float* w_attn = (const float*)d_in[2];
    const float* b_attn = (const float*)d_in[3];
    const float* a_attn = (const float*)d_in[4];
    const float* w_proj = (const float*)d_in[5];
    const float* b_proj = (const float*)d_in[6];
    const float* a_proj = (const float*)d_in[7];
    float* out = (float*)d_out;

    void *xsq_, *xsq2_, *ksqa_, *ksqp_, *tbl_, *fctr_, *mcnt_, *g1c_;
    void *ah_, *am_, *bha_, *bhp_, *bmp_, *qp_, *kp_, *vp_;
    cudaGetSymbolAddress(&xsq_,  g_xsq);
    cudaGetSymbolAddress(&xsq2_, g_xsq2);
    cudaGetSymbolAddress(&ksqa_, g_ksqA);
    cudaGetSymbolAddress(&ksqp_, g_ksqP);
    cudaGetSymbolAddress(&tbl_,  g_tbl);
    cudaGetSymbolAddress(&fctr_, g_fctr);
    cudaGetSymbolAddress(&mcnt_, g_mcnt);
    cudaGetSymbolAddress(&g1c_,  g_g1cnt);
    cudaGetSymbolAddress(&ah_,   g_Ah);
    cudaGetSymbolAddress(&am_,   g_Am);
    cudaGetSymbolAddress(&bha_,  g_BhA);
    cudaGetSymbolAddress(&bhp_,  g_BhP);
    cudaGetSymbolAddress(&bmp_,  g_BmP);
    cudaGetSymbolAddress(&qp_,   g_Qp);
    cudaGetSymbolAddress(&kp_,   g_Kp);
    cudaGetSymbolAddress(&vp_,   g_Vp);
    float* xsq  = (float*)xsq_;
    float* xsq2 = (float*)xsq2_;
    float* ksqa = (float*)ksqa_;
    float* ksqp = (float*)ksqp_;
    float2* tbl = (float2*)tbl_;
    int* fctr   = (int*)fctr_;
    int* mcnt   = (int*)mcnt_;
    int* g1cnt  = (int*)g1c_;
    __nv_bfloat16* Ah  = (__nv_bfloat16*)ah_;
    __nv_bfloat16* Am  = (__nv_bfloat16*)am_;
    __nv_bfloat16* BhA = (__nv_bfloat16*)bha_;
    __nv_bfloat16* BhP = (__nv_bfloat16*)bhp_;
    __nv_bfloat16* BmP = (__nv_bfloat16*)bmp_;
    __nv_bfloat16* Qp  = (__nv_bfloat16*)qp_;
    __nv_bfloat16* Kp  = (__nv_bfloat16*)kp_;
    __nv_bfloat16* Vp  = (__nv_bfloat16*)vp_;

    cudaFuncSetAttribute(fused_kernel,
                         cudaFuncAttributeMaxDynamicSharedMemorySize, FUSED_SMEM);

    // zero accumulators + task/dep counters + rope table
    prep_kernel<<<256, 256>>>(ksqa, ksqp, xsq2, tbl, fctr, mcnt, g1cnt);

    // merged: x split(hi)+rowsq, w_attn transpose(hi)+colsq, w_proj full
    prep2_kernel<<<MM + 3072 + 1024, 256>>>(x, Ah, xsq,
                                            w_attn, BhA, ksqa,
                                            w_proj, BhP, BmP, ksqp);

    // unified persistent GEMM1 + flash + GEMM2 with dependency counters
    fused_kernel<<<NPERS, 256, FUSED_SMEM>>>(Ah, BhA, b_attn, xsq, ksqa, a_attn,
                                             Qp, Kp, Vp, tbl,
                                             Ah /*OH reuse*/, Am /*OM*/, xsq2,
                                             fctr, mcnt, g1cnt,
                                             BhP, BmP, b_proj, ksqp, a_proj, out);
}